// round 6
// baseline (speedup 1.0000x reference)
#include <cuda_runtime.h>
#include <cstdint>
#include <cstddef>

#define BATCH 2
#define SEQ   1024
#define SEQ2  2048
#define PQ    128
#define HIDD  1024
#define NH    16
#define DH    64
#define H3    3072

// ---------------- scratch ----------------
__device__ float g_qkv[BATCH * SEQ * H3];      // [2048][3072] = q|kc|v
__device__ float g_wpack[HIDD * H3];
__device__ float g_kp[BATCH * SEQ2 * HIDD];
__device__ float g_qg[BATCH * PQ * HIDD];
__device__ float g_qscat[BATCH * SEQ * HIDD];
__device__ float g_qq[BATCH * PQ * HIDD];
__device__ float g_qqcb[BATCH * PQ * HIDD];
__device__ float g_qqpb[BATCH * PQ * HIDD];
__device__ float g_csq[(size_t)BATCH * NH * PQ * SEQ];
__device__ float g_ppq[(size_t)BATCH * NH * PQ * SEQ2];
__device__ float g_catt[BATCH * SEQ * HIDD];
__device__ float g_qatt[BATCH * PQ * HIDD];
__device__ int   g_idx[BATCH * PQ];
__device__ int   g_segmode[1];

// ---------------- probe ----------------
__global__ void probe_segmat(const uint32_t* __restrict__ p) {
    if (threadIdx.x == 0 && blockIdx.x == 0) {
        int mode = 1;
        for (int i = 0; i < 4096; i++) {
            uint32_t w = p[i];
            if (w == 0x3F800000u) { mode = 2; break; }
            if (w > 1u)           { mode = 0; break; }
        }
        g_segmode[0] = mode;
    }
}

__device__ __forceinline__ bool seg_at(const void* p, size_t i, int mode) {
    if (mode == 0) return ((const uint8_t*)p)[i] != 0;
    if (mode == 1) return ((const int*)p)[i] != 0;
    return ((const float*)p)[i] > 0.5f;
}

// ---------------- tf32 helpers ----------------
__device__ __forceinline__ uint32_t f2tf(float f) {
    uint32_t u;
    asm("cvt.rna.tf32.f32 %0, %1;" : "=r"(u) : "f"(f));
    return u;
}

__device__ __forceinline__ void mma_tf32(float* c, const uint32_t* a, const uint32_t* b) {
    asm volatile(
        "mma.sync.aligned.m16n8k8.row.col.f32.tf32.tf32.f32 "
        "{%0,%1,%2,%3}, {%4,%5,%6,%7}, {%8,%9}, {%0,%1,%2,%3};"
        : "+f"(c[0]), "+f"(c[1]), "+f"(c[2]), "+f"(c[3])
        : "r"(a[0]), "r"(a[1]), "r"(a[2]), "r"(a[3]), "r"(b[0]), "r"(b[1]));
}

__device__ __forceinline__ void cp16(uint32_t s, const float* g) {
    asm volatile("cp.async.ca.shared.global [%0], [%1], 16;" :: "r"(s), "l"(g));
}

// ---------------- tf32 GEMM, cp.async 3-stage pipeline ----------------
#define AST  20
#define BSTN 72
#define BSTT 20

template<bool TB>
__global__ __launch_bounds__(256) void gemm_tf32(
    const float* __restrict__ A, const float* __restrict__ B, float* __restrict__ C,
    int M, int N, int K, int lda, int ldb, int ldc,
    long aOut, long aIn, long bOut, long bIn, long cOut, long cIn, int zInner)
{
    __shared__ float As[3][128 * AST];
    __shared__ float Bs[3][1280];

    const int tid = threadIdx.x;
    const int zo = blockIdx.z / zInner, zi = blockIdx.z % zInner;
    const float* Ap = A + zo * aOut + zi * aIn;
    const float* Bp = B + zo * bOut + zi * bIn;
    float*       Cp = C + zo * cOut + zi * cIn;
    const int m0 = blockIdx.y * 128, n0 = blockIdx.x * 64;

    const int wid = tid >> 5, lane = tid & 31;
    const int wm = (wid & 3) * 32, wn = (wid >> 2) * 32;
    const int lr = lane >> 2, lc = lane & 3;

    uint32_t aSm[3], bSm[3];
#pragma unroll
    for (int i = 0; i < 3; i++) {
        aSm[i] = (uint32_t)__cvta_generic_to_shared(&As[i][0]);
        bSm[i] = (uint32_t)__cvta_generic_to_shared(&Bs[i][0]);
    }

    const int ar = tid >> 2, ac = (tid & 3) * 4;

    auto stage = [&](int kt) {
        const int k0 = kt * 16, buf = kt % 3;
        const float* ga = Ap + (size_t)(m0 + ar) * lda + k0 + ac;
        cp16(aSm[buf] + (ar * AST + ac) * 4, ga);
        cp16(aSm[buf] + ((ar + 64) * AST + ac) * 4, ga + (size_t)64 * lda);
        if (TB) {
            cp16(bSm[buf] + (ar * BSTT + ac) * 4,
                 Bp + (size_t)(n0 + ar) * ldb + k0 + ac);
        } else {
            const int br = tid >> 4, bc = (tid & 15) * 4;
            cp16(bSm[buf] + (br * BSTN + bc) * 4,
                 Bp + (size_t)(k0 + br) * ldb + n0 + bc);
        }
    };

    float acc[2][4][4] = {};
    const int KT = K >> 4;

    stage(0);
    asm volatile("cp.async.commit_group;");
    if (KT > 1) { stage(1); asm volatile("cp.async.commit_group;"); }

    for (int kt = 0; kt < KT; kt++) {
        if (kt + 1 < KT) asm volatile("cp.async.wait_group 1;");
        else             asm volatile("cp.async.wait_group 0;");
        __syncthreads();
        if (kt + 2 < KT) { stage(kt + 2); asm volatile("cp.async.commit_group;"); }

        const float* as = As[kt % 3];
        const float* bs = Bs[kt % 3];
#pragma unroll
        for (int kk = 0; kk < 16; kk += 8) {
            uint32_t af[2][4], bf[4][2];
#pragma unroll
            for (int im = 0; im < 2; im++) {
                const int base = (wm + im * 16 + lr) * AST + kk + lc;
                af[im][0] = f2tf(as[base]);
                af[im][1] = f2tf(as[base + 8 * AST]);
                af[im][2] = f2tf(as[base + 4]);
                af[im][3] = f2tf(as[base + 8 * AST + 4]);
            }
#pragma unroll
            for (int jn = 0; jn < 4; jn++) {
                if (TB) {
                    const int bb = (wn + jn * 8 + lr) * BSTT + kk + lc;
                    bf[jn][0] = f2tf(bs[bb]);
                    bf[jn][1] = f2tf(bs[bb + 4]);
                } else {
                    const int bb = (kk + lc) * BSTN + wn + jn * 8 + lr;
                    bf[jn][0] = f2tf(bs[bb]);
                    bf[jn][1] = f2tf(bs[bb + 4 * BSTN]);
                }
            }
#pragma unroll
            for (int im = 0; im < 2; im++)
#pragma unroll
                for (int jn = 0; jn < 4; jn++)
                    mma_tf32(acc[im][jn], af[im], bf[jn]);
        }
    }

#pragma unroll
    for (int im = 0; im < 2; im++) {
#pragma unroll
        for (int jn = 0; jn < 4; jn++) {
            const int row = m0 + wm + im * 16 + lr;
            const int col = n0 + wn + jn * 8 + 2 * lc;
            *(float2*)(Cp + (size_t)row * ldc + col) =
                make_float2(acc[im][jn][0], acc[im][jn][1]);
            *(float2*)(Cp + (size_t)(row + 8) * ldc + col) =
                make_float2(acc[im][jn][2], acc[im][jn][3]);
        }
    }
}

// ---------------- flash-fused content attention (q-tile 64, 128 thr) ----------------
#define FST 68
#define T64 (64 * FST)
// smem floats: KCs | KPs(=Ps) | Vs | ring[2] | s0s[64] | s1s[64]
#define FL_SMEMF (5 * T64 + 128)

__device__ __forceinline__ void stage64f(float* dst, const float* src, long rstride, int tid) {
    uint32_t s = (uint32_t)__cvta_generic_to_shared(dst);
#pragma unroll
    for (int i = 0; i < 8; i++) {
        int id = tid + i * 128;
        int j = id >> 4, d4 = (id & 15) * 4;
        cp16(s + (uint32_t)(j * FST + d4) * 4, src + (size_t)j * rstride + d4);
    }
}

__global__ __launch_bounds__(128, 2) void flash_content(
    const float* __restrict__ qkv, const float* __restrict__ kp,
    const float* __restrict__ cb, const float* __restrict__ pb,
    const float* __restrict__ sb, const float* __restrict__ seg,
    const void* __restrict__ segmat, const float* __restrict__ mask,
    float* __restrict__ out)
{
    extern __shared__ float sm[];
    float* KCs  = sm;
    float* KPs  = sm + T64;          // aliased as Ps after pp_tile
    float* Vs   = sm + 2 * T64;
    float* ring = sm + 3 * T64;      // 2 slots
    float* s0s  = sm + 5 * T64;
    float* s1s  = s0s + 64;
    float* Ps   = KPs;

    const int b = blockIdx.z, h = blockIdx.y, qt = blockIdx.x, q0 = qt * 64;
    const int tid = threadIdx.x, w = tid >> 5, l = tid & 31;
    const int lr = l >> 2, lc = l & 3;
    const int qb = w * 16;
    const int mode = g_segmode[0];

    // Q fragments (+cb, +pb), tf32
    uint32_t aC[8][4], aP[8][4];
    {
        const float* r0 = qkv + ((size_t)(b * SEQ + q0 + qb + lr)) * H3 + h * DH;
        const float* r1 = r0 + (size_t)8 * H3;
#pragma unroll
        for (int s = 0; s < 8; s++) {
            const int d0 = 8 * s + lc, d1 = d0 + 4;
            const float c0v = cb[h * DH + d0], c1v = cb[h * DH + d1];
            const float p0v = pb[h * DH + d0], p1v = pb[h * DH + d1];
            float v00 = r0[d0], v01 = r0[d1], v10 = r1[d0], v11 = r1[d1];
            aC[s][0] = f2tf(v00 + c0v); aC[s][1] = f2tf(v10 + c0v);
            aC[s][2] = f2tf(v01 + c1v); aC[s][3] = f2tf(v11 + c1v);
            aP[s][0] = f2tf(v00 + p0v); aP[s][1] = f2tf(v10 + p0v);
            aP[s][2] = f2tf(v01 + p1v); aP[s][3] = f2tf(v11 + p1v);
        }
    }
    // segment scalars per q row
    if (tid < 64) {
        const float* qr = qkv + ((size_t)(b * SEQ + q0 + tid)) * H3 + h * DH;
        float s0 = 0.f, s1 = 0.f;
        for (int d = 0; d < DH; d++) {
            float qs = qr[d] + sb[h * DH + d];
            s0 += qs * seg[h * DH + d];
            s1 += qs * seg[NH * DH + h * DH + d];
        }
        s0s[tid] = s0; s1s[tid] = s1;
    }

    float O[8][4] = {};
    float m_a = -1e30f, m_b = -1e30f, l_a = 0.f, l_b = 0.f;

    // PP tile: (Q+pb) x KPs^T -> ring[slot], own-warp rows
    auto pp_tile = [&](int slot) {
        float* rg = ring + slot * T64;
#pragma unroll
        for (int jn = 0; jn < 8; jn++) {
            float c[4] = {0.f, 0.f, 0.f, 0.f};
            const float* bp = KPs + (jn * 8 + lr) * FST;
#pragma unroll
            for (int s = 0; s < 8; s++) {
                uint32_t bfr[2];
                bfr[0] = __float_as_uint(bp[8 * s + lc]);
                bfr[1] = __float_as_uint(bp[8 * s + lc + 4]);
                mma_tf32(c, aP[s], bfr);
            }
            float* r0 = rg + (qb + lr) * FST + jn * 8 + 2 * lc;
            *(float2*)r0 = make_float2(c[0], c[1]);
            *(float2*)(r0 + 8 * FST) = make_float2(c[2], c[3]);
        }
        __syncwarp();
    };

    // prologue: tileA for kt=0, index T = 15 - qt (+16 basis), kp rows [S-q0-64, S-q0)
    {
        stage64f(KPs, kp + ((size_t)(b * SEQ2 + SEQ - q0 - 64)) * HIDD + h * DH, HIDD, tid);
        asm volatile("cp.async.commit_group;");
        asm volatile("cp.async.wait_group 0;");
        __syncthreads();
        for (int i = tid; i < T64 / 4; i += 128) {
            float4* p4 = ((float4*)(sm + T64)) + i;
            float4 vv = *p4;
            vv.x = __uint_as_float(f2tf(vv.x)); vv.y = __uint_as_float(f2tf(vv.y));
            vv.z = __uint_as_float(f2tf(vv.z)); vv.w = __uint_as_float(f2tf(vv.w));
            *p4 = vv;
        }
        __syncthreads();
        pp_tile((15 - qt) & 1);
    }

    const int ra = qb + lr, rb = ra + 8;
    const size_t mbase_a = ((size_t)b * SEQ + q0 + ra) * SEQ;
    const size_t mbase_b = mbase_a + (size_t)8 * SEQ;
    const float s0a = s0s[ra], s1a = s1s[ra];   // note: s0s written pre-sync above
    const float s0b = s0s[rb], s1b = s1s[rb];

    for (int kt = 0; kt < 16; kt++) {
        const int k0 = kt * 64;
        const int Tb = 16 + kt - qt;
        __syncthreads();   // Ps/Vs consumed; safe to restage
        stage64f(KCs, qkv + ((size_t)(b * SEQ + k0)) * H3 + 1024 + h * DH, H3, tid);
        stage64f(Vs,  qkv + ((size_t)(b * SEQ + k0)) * H3 + 2048 + h * DH, H3, tid);
        stage64f(KPs, kp + ((size_t)b * SEQ2 + (size_t)64 * Tb) * HIDD + h * DH, HIDD, tid);
        asm volatile("cp.async.commit_group;");
        asm volatile("cp.async.wait_group 0;");
        __syncthreads();
        // convert all three tiles to tf32 in place
        for (int i = tid; i < 3 * T64 / 4; i += 128) {
            float4* p4 = ((float4*)sm) + i;
            float4 vv = *p4;
            vv.x = __uint_as_float(f2tf(vv.x)); vv.y = __uint_as_float(f2tf(vv.y));
            vv.z = __uint_as_float(f2tf(vv.z)); vv.w = __uint_as_float(f2tf(vv.w));
            *p4 = vv;
        }
        __syncthreads();

        pp_tile(Tb & 1);
        const int slotA = (Tb - 1) & 1, slotB = Tb & 1;

        // content scores
        float cs[8][4];
#pragma unroll
        for (int jn = 0; jn < 8; jn++) {
            float c[4] = {0.f, 0.f, 0.f, 0.f};
            const float* bp = KCs + (jn * 8 + lr) * FST;
#pragma unroll
            for (int s = 0; s < 8; s++) {
                uint32_t bfr[2];
                bfr[0] = __float_as_uint(bp[8 * s + lc]);
                bfr[1] = __float_as_uint(bp[8 * s + lc + 4]);
                mma_tf32(c, aC[s], bfr);
            }
            cs[jn][0] = c[0]; cs[jn][1] = c[1]; cs[jn][2] = c[2]; cs[jn][3] = c[3];
        }

        float mxa = -1e30f, mxb = -1e30f;
#pragma unroll
        for (int jn = 0; jn < 8; jn++) {
            const int kkp = jn * 8 + 2 * lc;
            float2 mva = *(const float2*)(mask + mbase_a + k0 + kkp);
            float2 mvb = *(const float2*)(mask + mbase_b + k0 + kkp);
            float sa0 = seg_at(segmat, mbase_a + k0 + kkp, mode)     ? s1a : s0a;
            float sa1 = seg_at(segmat, mbase_a + k0 + kkp + 1, mode) ? s1a : s0a;
            float sb0 = seg_at(segmat, mbase_b + k0 + kkp, mode)     ? s1b : s0b;
            float sb1 = seg_at(segmat, mbase_b + k0 + kkp + 1, mode) ? s1b : s0b;
            const int wa = kkp - ra + 64, wb = kkp - rb + 64;
            float ppa0 = ring[(wa < 64 ? slotA : slotB) * T64 + ra * FST + (wa & 63)];
            float ppa1 = ring[(wa + 1 < 64 ? slotA : slotB) * T64 + ra * FST + ((wa + 1) & 63)];
            float ppb0 = ring[(wb < 64 ? slotA : slotB) * T64 + rb * FST + (wb & 63)];
            float ppb1 = ring[(wb + 1 < 64 ? slotA : slotB) * T64 + rb * FST + ((wb + 1) & 63)];
            cs[jn][0] = (cs[jn][0] + ppa0 + sa0) * 0.125f + mva.x * (-1e9f);
            cs[jn][1] = (cs[jn][1] + ppa1 + sa1) * 0.125f + mva.y * (-1e9f);
            cs[jn][2] = (cs[jn][2] + ppb0 + sb0) * 0.125f + mvb.x * (-1e9f);
            cs[jn][3] = (cs[jn][3] + ppb1 + sb1) * 0.125f + mvb.y * (-1e9f);
            mxa = fmaxf(mxa, fmaxf(cs[jn][0], cs[jn][1]));
            mxb = fmaxf(mxb, fmaxf(cs[jn][2], cs[jn][3]));
        }
        __syncthreads();   // all warps done reading KPs (pp_tile) before Ps overwrite

        mxa = fmaxf(mxa, __shfl_xor_sync(0xffffffffu, mxa, 1));
        mxa = fmaxf(mxa, __shfl_xor_sync(0xffffffffu, mxa, 2));
        mxb = fmaxf(mxb, __shfl_xor_sync(0xffffffffu, mxb, 1));
        mxb = fmaxf(mxb, __shfl_xor_sync(0xffffffffu, mxb, 2));

        const float mna = fmaxf(m_a, mxa), mnb = fmaxf(m_b, mxb);
        const float alA = __expf(m_a - mna), alB = __expf(m_b - mnb);
        m_a = mna; m_b = mnb;

        float sa = 0.f, sbm = 0.f;
#pragma unroll
        for (int jn = 0; jn < 8; jn++) {
            float p0 = __expf(cs[jn][0] - m_a), p1 = __expf(cs[jn][1] - m_a);
            float p2 = __expf(cs[jn][2] - m_b), p3 = __expf(cs[jn][3] - m_b);
            sa += p0 + p1; sbm += p2 + p3;
            // store pre-converted to tf32 bits
            *(float2*)(Ps + ra * FST + jn * 8 + 2 * lc) =
                make_float2(__uint_as_float(f2tf(p0)), __uint_as_float(f2tf(p1)));
            *(float2*)(Ps + rb * FST + jn * 8 + 2 * lc) =
                make_float2(__uint_as_float(f2tf(p2)), __uint_as_float(f2tf(p3)));
            O[jn][0] *= alA; O[jn][1] *= alA; O[jn][2] *= alB; O[jn][3] *= alB;
        }
        sa  += __shfl_xor_sync(0xffffffffu, sa, 1);
        sa  += __shfl_xor_sync(0xffffffffu, sa, 2);
        sbm += __shfl_xor_sync(0xffffffffu, sbm, 1);
        sbm += __shfl_xor_sync(0xffffffffu, sbm, 2);
        l_a = l_a * alA + sa;
        l_b = l_b * alB + sbm;
        __syncwarp();

        // AV (Ps rows are own-warp; Vs pre-converted)
        uint32_t ap[8][4];
#pragma unroll
        for (int s = 0; s < 8; s++) {
            ap[s][0] = __float_as_uint(Ps[ra * FST + 8 * s + lc]);
            ap[s][1] = __float_as_uint(Ps[rb * FST + 8 * s + lc]);
            ap[s][2] = __float_as_uint(Ps[ra * FST + 8 * s + lc + 4]);
            ap[s][3] = __float_as_uint(Ps[rb * FST + 8 * s + lc + 4]);
        }
#pragma unroll
        for (int jn = 0; jn < 8; jn++) {
#pragma unroll
            for (int s = 0; s < 8; s++) {
                uint32_t bfr[2];
                bfr[0] = __float_as_uint(Vs[(8 * s + lc) * FST + jn * 8 + lr]);
                bfr[1] = __float_as_uint(Vs[(8 * s + lc + 4) * FST + jn * 8 + lr]);
                mma_tf32(O[jn], ap[s], bfr);
            }
        }
        __syncwarp();
    }

    const float ia = 1.f / l_a, ib = 1.f / l_b;
    float* o0 = out + ((size_t)(b * SEQ + q0 + ra)) * HIDD + h * DH;
    float* o1 = o0 + (size_t)8 * HIDD;
#pragma unroll
    for (int jn = 0; jn < 8; jn++) {
        *(float2*)(o0 + jn * 8 + 2 * lc) = make_float2(O[jn][0] * ia, O[jn][1] * ia);
        *(float2*)(o1 + jn * 8 + 2 * lc) = make_float2(O[jn][2] * ib, O[jn][3] * ib);
    }
}

// ---------------- small kernels ----------------
__global__ void zero_f(float* __restrict__ p, int n) {
    int i = blockIdx.x * 256 + threadIdx.x;
    if (i < n) p[i] = 0.f;
}

__global__ void pack_w(const float* __restrict__ wq, const float* __restrict__ wkc,
                       const float* __restrict__ wv, float* __restrict__ W)
{
    int i = blockIdx.x * 256 + threadIdx.x;
    int r = i >> 10, c = i & 1023;
    float* dst = W + (size_t)r * H3 + c;
    dst[0]    = wq[i];
    dst[1024] = wkc[i];
    dst[2048] = wv[i];
}

__global__ void add_bias2(const float* __restrict__ src, int ld,
                          const float* __restrict__ cb, const float* __restrict__ pb,
                          float* __restrict__ ocb, float* __restrict__ opb)
{
    const int row = blockIdx.x, t = threadIdx.x;
    const float* s = src + (size_t)row * ld;
    float* o1 = ocb + (size_t)row * HIDD;
    float* o2 = opb + (size_t)row * HIDD;
    for (int i = t; i < HIDD; i += 256) {
        float v = s[i];
        o1[i] = v + cb[i];
        o2[i] = v + pb[i];
    }
}

__global__ void scatter_q(const float* __restrict__ tmap, const float* __restrict__ qg,
                          float* __restrict__ qscat, int* __restrict__ idx)
{
    const int b = blockIdx.y, p = blockIdx.x, t = threadIdx.x;
    __shared__ int sidx;
    const float* row = tmap + ((size_t)b * PQ + p) * SEQ;
    for (int s = t; s < SEQ; s += 128)
        if (row[s] > 0.5f) sidx = s;
    __syncthreads();
    const int si = sidx;
    if (t == 0) idx[b * PQ + p] = si;
    const float* src = qg + ((size_t)b * PQ + p) * HIDD;
    float* dst = qscat + ((size_t)b * SEQ + si) * HIDD;
    for (int i = t; i < HIDD; i += 128) atomicAdd(&dst[i], src[i]);
}

__global__ void gather_q(const float* __restrict__ qscat, const int* __restrict__ idx,
                         float* __restrict__ qq)
{
    const int b = blockIdx.y, p = blockIdx.x, t = threadIdx.x;
    const int si = idx[b * PQ + p];
    const float* src = qscat + ((size_t)b * SEQ + si) * HIDD;
    float* dst = qq + ((size_t)b * PQ + p) * HIDD;
    for (int i = t; i < HIDD; i += 128) dst[i] = src[i];
}

// ---------------- query-stream softmax ----------------
__global__ __launch_bounds__(256) void softmax_kernel(
    float* __restrict__ cs, const float* __restrict__ pp,
    const float* __restrict__ qArr, const float* __restrict__ sb,
    const float* __restrict__ seg, const void* __restrict__ segmat,
    const float* __restrict__ mask, const int* __restrict__ qidx,
    int Mrows, long qBatchStride, int ldq)
{
    const int b = blockIdx.z, h = blockIdx.y, qo = blockIdx.x, t = threadIdx.x;
    const int qrow = qidx ? qidx[b * PQ + qo] : qo;
    const int z = b * NH + h;
    const int mode = g_segmode[0];

    float* csrow = cs + ((size_t)z * Mrows + qo) * SEQ;
    const float* pprow = pp + ((size_t)z * Mrows + qo) * SEQ2 + (SEQ - qrow);
    const float* mrow = mask + ((size_t)b * SEQ + qrow) * SEQ;
    const size_t segbase = ((size_t)b * SEQ + qrow) * SEQ;

    __shared__ float qsv[DH];
    __shared__ float s01[2];
    __shared__ float red[256];

    if (t < DH)
        qsv[t] = qArr[qBatchStride * b + (size_t)qo * ldq + h * DH + t] + sb[h * DH + t];
    __syncthreads();
    if (t < 64) {
        const int which = t >> 5, lx = t & 31;
        const float* sgp = seg + which * NH * DH + h * DH;
        float a = qsv[lx] * sgp[lx] + qsv[lx + 32] * sgp[lx + 32];
#pragma unroll
        for (int o = 16; o; o >>= 1) a += __shfl_xor_sync(0xffffffffu, a, o);
        if (lx == 0) s01[which] = a;
    }
    __syncthreads();
    const float s0 = s01[0], s1 = s01[1];

    float lg[4];
    float mx = -3.4e38f;
#pragma unroll
    for (int j = 0; j < 4; j++) {
        int k = t + j * 256;
        float sgv = seg_at(segmat, segbase + k, mode) ? s1 : s0;
        float v = (csrow[k] + pprow[k] + sgv) * 0.125f + mrow[k] * (-1e9f);
        lg[j] = v;
        mx = fmaxf(mx, v);
    }
    red[t] = mx; __syncthreads();
#pragma unroll
    for (int s2 = 128; s2; s2 >>= 1) {
        if (t < s2) red[t] = fmaxf(red[t], red[t + s2]);
        __syncthreads();
    }
    mx = red[0]; __syncthreads();

    float sum = 0.f;
#pragma unroll
    for (int j = 0; j < 4; j++) {
        float e = __expf(lg[j] - mx);
        lg[j] = e;
        sum += e;
    }
    red[t] = sum; __syncthreads();
#pragma unroll
    for (int s2 = 128; s2; s2 >>= 1) {
        if (t < s2) red[t] += red[t + s2];
        __syncthreads();
    }
    const float invZ = 1.f / red[0];
#pragma unroll
    for (int j = 0; j < 4; j++) csrow[t + j * 256] = lg[j] * invZ;
}

// ---------------- launch ----------------
extern "C" void kernel_launch(void* const* d_in, const int* in_sizes, int n_in,
                              void* d_out, int out_size)
{
    const float* content = (const float*)d_in[0];
    const float* query   = (const float*)d_in[1];
    const float* pe      = (const float*)d_in[2];
    const void*  segmat  = d_in[3];
    const float* segenc  = (const float*)d_in[4];
    const float* segbias = (const float*)d_in[5];
    const float* cmask   = (const float*)d_in[6];
    const float* qmask   = (const float*)d_in[7];
    const float* tmap    = (const float*)d_in[8];
    const float* cbias   = (const float*)d_in[9];
    const float* pbias   = (const float*)d_in[10];
    const float* wq      = (const float*)d_in[11];
    const float* wkc     = (const float*)d_in[12];
    const float* wv      = (const float*)d_in[13];
    const float* wkp     = (const float*)d_in[14];
    const float* wo      = (const float*)d_in[15];
    float* out = (float*)d_out;

    float *qkv, *wpack, *kp, *qg, *qscat, *qq, *qqcb, *qqpb;
    float *csq, *ppq, *catt, *qatt;
    int* idx;
    cudaGetSymbolAddress((void**)&qkv,   g_qkv);
    cudaGetSymbolAddress((void**)&wpack, g_wpack);
    cudaGetSymbolAddress((void**)&kp,    g_kp);
    cudaGetSymbolAddress((void**)&qg,    g_qg);
    cudaGetSymbolAddress((void**)&qscat, g_qscat);
    cudaGetSymbolAddress((void**)&qq,    g_qq);
    cudaGetSymbolAddress((void**)&qqcb,  g_qqcb);
    cudaGetSymbolAddress((void**)&qqpb,  g_qqpb);
    cudaGetSymbolAddress((void**)&csq,   g_csq);
    cudaGetSymbolAddress((void**)&ppq,   g_ppq);
    cudaGetSymbolAddress((void**)&catt,  g_catt);
    cudaGetSymbolAddress((void**)&qatt,  g_qatt);
    cudaGetSymbolAddress((void**)&idx,   g_idx);

    static bool attr_done = false;
    if (!attr_done) {
        cudaFuncSetAttribute(flash_content, cudaFuncAttributeMaxDynamicSharedMemorySize,
                             FL_SMEMF * sizeof(float));
        attr_done = true;
    }

    probe_segmat<<<1, 32>>>((const uint32_t*)segmat);
    zero_f<<<(BATCH * SEQ * HIDD + 255) / 256, 256>>>(qscat, BATCH * SEQ * HIDD);
    pack_w<<<4096, 256>>>(wq, wkc, wv, wpack);

    const long SH = (long)SEQ * HIDD, S2H = (long)SEQ2 * HIDD, PH = (long)PQ * HIDD;
    const long SH3 = (long)SEQ * H3;
    const long PS = (long)PQ * SEQ, PS2 = (long)PQ * SEQ2;

    // projections
    gemm_tf32<false><<<dim3(48, 16, 1), 256>>>(content, wpack, qkv,
        2048, H3, HIDD, HIDD, H3, H3, 0,0,0,0,0,0, 1);
    gemm_tf32<false><<<dim3(16, 32, 1), 256>>>(pe, wkp, kp,
        4096, HIDD, HIDD, HIDD, HIDD, HIDD, 0,0,0,0,0,0, 1);
    gemm_tf32<false><<<dim3(16, 2, 1), 256>>>(query, wq, qg,
        256, HIDD, HIDD, HIDD, HIDD, HIDD, 0,0,0,0,0,0, 1);

    scatter_q<<<dim3(PQ, BATCH), 128>>>(tmap, qg, qscat, idx);
    gather_q<<<dim3(PQ, BATCH), 128>>>(qscat, idx, qq);
    add_bias2<<<BATCH * PQ, 256>>>(qq, HIDD, cbias, pbias, qqcb, qqpb);

    const float* kcp = qkv + 1024;
    const float* vp  = qkv + 2048;

    // content stream: flash-fused (q-tile 64)
    flash_content<<<dim3(SEQ / 64, NH, BATCH), 128, FL_SMEMF * sizeof(float)>>>(
        qkv, kp, cbias, pbias, segbias, segenc, segmat, cmask, catt);

    // query stream
    gemm_tf32<true><<<dim3(16, 1, BATCH * NH), 256>>>(qqcb, kcp, csq,
        PQ, SEQ, DH, HIDD, H3, SEQ,  PH, DH, SH3, DH, (long)NH * PS, PS, NH);
    gemm_tf32<true><<<dim3(32, 1, BATCH * NH), 256>>>(qqpb, kp, ppq,
        PQ, SEQ2, DH, HIDD, HIDD, SEQ2, PH, DH, S2H, DH, (long)NH * PS2, PS2, NH);
    softmax_kernel<<<dim3(PQ, NH, BATCH), 256>>>(
        csq, ppq, qq, segbias, segenc, segmat, qmask, idx, PQ, PH, HIDD);
    gemm_tf32<false><<<dim3(1, 1, BATCH * NH), 256>>>(csq, vp, qatt,
        PQ, DH, SEQ, SEQ, H3, HIDD, (long)NH * PS, PS, SH3, DH, PH, DH, NH);

    // output projections
    gemm_tf32<false><<<dim3(16, 16, 1), 256>>>(catt, wo, out,
        2048, HIDD, HIDD, HIDD, HIDD, HIDD, 0,0,0,0,0,0, 1);
    gemm_tf32<false><<<dim3(16, 2, 1), 256>>>(qatt, wo, out + (size_t)BATCH * SEQ * HIDD,
        256, HIDD, HIDD, HIDD, HIDD, HIDD, 0,0,0,0,0,0, 1);
}

// round 7
// speedup vs baseline: 1.0599x; 1.0599x over previous
#include <cuda_runtime.h>
#include <cstdint>
#include <cstddef>

#define BATCH 2
#define SEQ   1024
#define SEQ2  2048
#define PQ    128
#define HIDD  1024
#define NH    16
#define DH    64
#define H3    3072

// ---------------- scratch ----------------
__device__ float g_qkv[BATCH * SEQ * H3];
__device__ float g_wpack[HIDD * H3];
__device__ float g_kp[BATCH * SEQ2 * HIDD];
__device__ float g_qg[BATCH * PQ * HIDD];
__device__ float g_qscat[BATCH * SEQ * HIDD];
__device__ float g_qq[BATCH * PQ * HIDD];
__device__ float g_qqcb[BATCH * PQ * HIDD];
__device__ float g_qqpb[BATCH * PQ * HIDD];
__device__ float g_csq[(size_t)BATCH * NH * PQ * SEQ];
__device__ float g_ppq[(size_t)BATCH * NH * PQ * SEQ2];
__device__ float g_catt[BATCH * SEQ * HIDD];
__device__ float g_qatt[BATCH * PQ * HIDD];
__device__ int   g_idx[BATCH * PQ];
__device__ int   g_segmode[1];

// ---------------- probe ----------------
__global__ void probe_segmat(const uint32_t* __restrict__ p) {
    if (threadIdx.x == 0 && blockIdx.x == 0) {
        int mode = 1;
        for (int i = 0; i < 4096; i++) {
            uint32_t w = p[i];
            if (w == 0x3F800000u) { mode = 2; break; }
            if (w > 1u)           { mode = 0; break; }
        }
        g_segmode[0] = mode;
    }
}

__device__ __forceinline__ bool seg_at(const void* p, size_t i, int mode) {
    if (mode == 0) return ((const uint8_t*)p)[i] != 0;
    if (mode == 1) return ((const int*)p)[i] != 0;
    return ((const float*)p)[i] > 0.5f;
}

// ---------------- tf32 helpers ----------------
__device__ __forceinline__ uint32_t f2tf(float f) {
    uint32_t u;
    asm("cvt.rna.tf32.f32 %0, %1;" : "=r"(u) : "f"(f));
    return u;
}

__device__ __forceinline__ void mma_tf32(float* c, const uint32_t* a, const uint32_t* b) {
    asm volatile(
        "mma.sync.aligned.m16n8k8.row.col.f32.tf32.tf32.f32 "
        "{%0,%1,%2,%3}, {%4,%5,%6,%7}, {%8,%9}, {%0,%1,%2,%3};"
        : "+f"(c[0]), "+f"(c[1]), "+f"(c[2]), "+f"(c[3])
        : "r"(a[0]), "r"(a[1]), "r"(a[2]), "r"(a[3]), "r"(b[0]), "r"(b[1]));
}

__device__ __forceinline__ void cp16(uint32_t s, const float* g) {
    asm volatile("cp.async.ca.shared.global [%0], [%1], 16;" :: "r"(s), "l"(g));
}

// ---------------- tf32 GEMM 128x64, cp.async 2-stage (R4, measured-best) ----------------
#define AST  20
#define BSTN 72
#define BSTT 20

template<bool TB>
__global__ __launch_bounds__(256) void gemm_tf32(
    const float* __restrict__ A, const float* __restrict__ B, float* __restrict__ C,
    int M, int N, int K, int lda, int ldb, int ldc,
    long aOut, long aIn, long bOut, long bIn, long cOut, long cIn, int zInner)
{
    __shared__ float As[2][128 * AST];
    __shared__ float Bs[2][1280];

    const int tid = threadIdx.x;
    const int zo = blockIdx.z / zInner, zi = blockIdx.z % zInner;
    const float* Ap = A + zo * aOut + zi * aIn;
    const float* Bp = B + zo * bOut + zi * bIn;
    float*       Cp = C + zo * cOut + zi * cIn;
    const int m0 = blockIdx.y * 128, n0 = blockIdx.x * 64;

    const int wid = tid >> 5, lane = tid & 31;
    const int wm = (wid & 3) * 32, wn = (wid >> 2) * 32;
    const int lr = lane >> 2, lc = lane & 3;

    uint32_t aSm[2], bSm[2];
    aSm[0] = (uint32_t)__cvta_generic_to_shared(&As[0][0]);
    aSm[1] = (uint32_t)__cvta_generic_to_shared(&As[1][0]);
    bSm[0] = (uint32_t)__cvta_generic_to_shared(&Bs[0][0]);
    bSm[1] = (uint32_t)__cvta_generic_to_shared(&Bs[1][0]);

    const int ar = tid >> 2, ac = (tid & 3) * 4;

    auto stage = [&](int kt) {
        const int k0 = kt * 16, buf = kt & 1;
        const float* ga = Ap + (size_t)(m0 + ar) * lda + k0 + ac;
        cp16(aSm[buf] + (ar * AST + ac) * 4, ga);
        cp16(aSm[buf] + ((ar + 64) * AST + ac) * 4, ga + (size_t)64 * lda);
        if (TB) {
            cp16(bSm[buf] + (ar * BSTT + ac) * 4,
                 Bp + (size_t)(n0 + ar) * ldb + k0 + ac);
        } else {
            const int br = tid >> 4, bc = (tid & 15) * 4;
            cp16(bSm[buf] + (br * BSTN + bc) * 4,
                 Bp + (size_t)(k0 + br) * ldb + n0 + bc);
        }
    };

    float acc[2][4][4] = {};

    stage(0);
    asm volatile("cp.async.commit_group;");
    const int KT = K >> 4;

    for (int kt = 0; kt < KT; kt++) {
        if (kt + 1 < KT) {
            stage(kt + 1);
            asm volatile("cp.async.commit_group;");
            asm volatile("cp.async.wait_group 1;");
        } else {
            asm volatile("cp.async.wait_group 0;");
        }
        __syncthreads();

        const float* as = As[kt & 1];
        const float* bs = Bs[kt & 1];
#pragma unroll
        for (int kk = 0; kk < 16; kk += 8) {
            uint32_t af[2][4], bf[4][2];
#pragma unroll
            for (int im = 0; im < 2; im++) {
                const int base = (wm + im * 16 + lr) * AST + kk + lc;
                af[im][0] = f2tf(as[base]);
                af[im][1] = f2tf(as[base + 8 * AST]);
                af[im][2] = f2tf(as[base + 4]);
                af[im][3] = f2tf(as[base + 8 * AST + 4]);
            }
#pragma unroll
            for (int jn = 0; jn < 4; jn++) {
                if (TB) {
                    const int bb = (wn + jn * 8 + lr) * BSTT + kk + lc;
                    bf[jn][0] = f2tf(bs[bb]);
                    bf[jn][1] = f2tf(bs[bb + 4]);
                } else {
                    const int bb = (kk + lc) * BSTN + wn + jn * 8 + lr;
                    bf[jn][0] = f2tf(bs[bb]);
                    bf[jn][1] = f2tf(bs[bb + 4 * BSTN]);
                }
            }
#pragma unroll
            for (int im = 0; im < 2; im++)
#pragma unroll
                for (int jn = 0; jn < 4; jn++)
                    mma_tf32(acc[im][jn], af[im], bf[jn]);
        }
        __syncthreads();
    }

#pragma unroll
    for (int im = 0; im < 2; im++) {
#pragma unroll
        for (int jn = 0; jn < 4; jn++) {
            const int row = m0 + wm + im * 16 + lr;
            const int col = n0 + wn + jn * 8 + 2 * lc;
            *(float2*)(Cp + (size_t)row * ldc + col) =
                make_float2(acc[im][jn][0], acc[im][jn][1]);
            *(float2*)(Cp + (size_t)(row + 8) * ldc + col) =
                make_float2(acc[im][jn][2], acc[im][jn][3]);
        }
    }
}

// ---------------- tf32 GEMM 128x128, cp.async 2-stage ----------------
// 8 warps, warp tile 32x128/... wm=(wid&3)*32, wn=(wid>>2)*64 => 32x64 per warp.
#define B128 136   // B smem stride (NN): 8 mod 32 -> conflict-free fragment loads

template<bool TB>
__global__ __launch_bounds__(256) void gemm128(
    const float* __restrict__ A, const float* __restrict__ B, float* __restrict__ C,
    int M, int N, int K, int lda, int ldb, int ldc,
    long aOut, long aIn, long bOut, long bIn, long cOut, long cIn, int zInner)
{
    __shared__ float As[2][128 * AST];          // 128 rows x 16 k
    __shared__ float Bs[2][TB ? 128 * BSTT : 16 * B128];

    const int tid = threadIdx.x;
    const int zo = blockIdx.z / zInner, zi = blockIdx.z % zInner;
    const float* Ap = A + zo * aOut + zi * aIn;
    const float* Bp = B + zo * bOut + zi * bIn;
    float*       Cp = C + zo * cOut + zi * cIn;
    const int m0 = blockIdx.y * 128, n0 = blockIdx.x * 128;

    const int wid = tid >> 5, lane = tid & 31;
    const int wm = (wid & 3) * 32, wn = (wid >> 2) * 64;
    const int lr = lane >> 2, lc = lane & 3;

    uint32_t aSm[2], bSm[2];
    aSm[0] = (uint32_t)__cvta_generic_to_shared(&As[0][0]);
    aSm[1] = (uint32_t)__cvta_generic_to_shared(&As[1][0]);
    bSm[0] = (uint32_t)__cvta_generic_to_shared(&Bs[0][0]);
    bSm[1] = (uint32_t)__cvta_generic_to_shared(&Bs[1][0]);

    const int ar = tid >> 2, ac = (tid & 3) * 4;

    auto stage = [&](int kt) {
        const int k0 = kt * 16, buf = kt & 1;
        const float* ga = Ap + (size_t)(m0 + ar) * lda + k0 + ac;
        cp16(aSm[buf] + (ar * AST + ac) * 4, ga);
        cp16(aSm[buf] + ((ar + 64) * AST + ac) * 4, ga + (size_t)64 * lda);
        if (TB) {
            // B[N,K]: 128 rows x 16 k
            const int r = tid >> 1, c = (tid & 1) * 8;
            const float* gb = Bp + (size_t)(n0 + r) * ldb + k0 + c;
            cp16(bSm[buf] + (r * BSTT + c) * 4, gb);
            cp16(bSm[buf] + (r * BSTT + c + 4) * 4, gb + 4);
        } else {
            // B[K,N]: 16 rows x 128 n
            const int br = tid >> 4, bc = (tid & 15) * 4;
            const float* gb = Bp + (size_t)(k0 + br) * ldb + n0 + bc;
            cp16(bSm[buf] + (br * B128 + bc) * 4, gb);
            cp16(bSm[buf] + (br * B128 + bc + 64) * 4, gb + 64);
        }
    };

    float acc[2][8][4] = {};

    stage(0);
    asm volatile("cp.async.commit_group;");
    const int KT = K >> 4;

    for (int kt = 0; kt < KT; kt++) {
        if (kt + 1 < KT) {
            stage(kt + 1);
            asm volatile("cp.async.commit_group;");
            asm volatile("cp.async.wait_group 1;");
        } else {
            asm volatile("cp.async.wait_group 0;");
        }
        __syncthreads();

        const float* as = As[kt & 1];
        const float* bs = Bs[kt & 1];
#pragma unroll
        for (int kk = 0; kk < 16; kk += 8) {
            uint32_t af[2][4], bf[8][2];
#pragma unroll
            for (int im = 0; im < 2; im++) {
                const int base = (wm + im * 16 + lr) * AST + kk + lc;
                af[im][0] = f2tf(as[base]);
                af[im][1] = f2tf(as[base + 8 * AST]);
                af[im][2] = f2tf(as[base + 4]);
                af[im][3] = f2tf(as[base + 8 * AST + 4]);
            }
#pragma unroll
            for (int jn = 0; jn < 8; jn++) {
                if (TB) {
                    const int bb = (wn + jn * 8 + lr) * BSTT + kk + lc;
                    bf[jn][0] = f2tf(bs[bb]);
                    bf[jn][1] = f2tf(bs[bb + 4]);
                } else {
                    const int bb = (kk + lc) * B128 + wn + jn * 8 + lr;
                    bf[jn][0] = f2tf(bs[bb]);
                    bf[jn][1] = f2tf(bs[bb + 4 * B128]);
                }
            }
#pragma unroll
            for (int im = 0; im < 2; im++)
#pragma unroll
                for (int jn = 0; jn < 8; jn++)
                    mma_tf32(acc[im][jn], af[im], bf[jn]);
        }
        __syncthreads();
    }

#pragma unroll
    for (int im = 0; im < 2; im++) {
#pragma unroll
        for (int jn = 0; jn < 8; jn++) {
            const int row = m0 + wm + im * 16 + lr;
            const int col = n0 + wn + jn * 8 + 2 * lc;
            *(float2*)(Cp + (size_t)row * ldc + col) =
                make_float2(acc[im][jn][0], acc[im][jn][1]);
            *(float2*)(Cp + (size_t)(row + 8) * ldc + col) =
                make_float2(acc[im][jn][2], acc[im][jn][3]);
        }
    }
}

// ---------------- flash-fused content attention (q-tile 64, 128 thr) ----------------
#define FST 68
#define T64 (64 * FST)
#define FL_SMEMF (5 * T64 + 128)

__device__ __forceinline__ void stage64f(float* dst, const float* src, long rstride, int tid) {
    uint32_t s = (uint32_t)__cvta_generic_to_shared(dst);
#pragma unroll
    for (int i = 0; i < 8; i++) {
        int id = tid + i * 128;
        int j = id >> 4, d4 = (id & 15) * 4;
        cp16(s + (uint32_t)(j * FST + d4) * 4, src + (size_t)j * rstride + d4);
    }
}

__global__ __launch_bounds__(128, 2) void flash_content(
    const float* __restrict__ qkv, const float* __restrict__ kp,
    const float* __restrict__ cb, const float* __restrict__ pb,
    const float* __restrict__ sb, const float* __restrict__ seg,
    const void* __restrict__ segmat, const float* __restrict__ mask,
    float* __restrict__ out)
{
    extern __shared__ float sm[];
    float* KCs  = sm;
    float* KPs  = sm + T64;
    float* Vs   = sm + 2 * T64;
    float* ring = sm + 3 * T64;
    float* s0s  = sm + 5 * T64;
    float* s1s  = s0s + 64;
    float* Ps   = KPs;

    const int b = blockIdx.z, h = blockIdx.y, qt = blockIdx.x, q0 = qt * 64;
    const int tid = threadIdx.x, w = tid >> 5, l = tid & 31;
    const int lr = l >> 2, lc = l & 3;
    const int qb = w * 16;
    const int mode = g_segmode[0];

    uint32_t aC[8][4], aP[8][4];
    {
        const float* r0 = qkv + ((size_t)(b * SEQ + q0 + qb + lr)) * H3 + h * DH;
        const float* r1 = r0 + (size_t)8 * H3;
#pragma unroll
        for (int s = 0; s < 8; s++) {
            const int d0 = 8 * s + lc, d1 = d0 + 4;
            const float c0v = cb[h * DH + d0], c1v = cb[h * DH + d1];
            const float p0v = pb[h * DH + d0], p1v = pb[h * DH + d1];
            float v00 = r0[d0], v01 = r0[d1], v10 = r1[d0], v11 = r1[d1];
            aC[s][0] = f2tf(v00 + c0v); aC[s][1] = f2tf(v10 + c0v);
            aC[s][2] = f2tf(v01 + c1v); aC[s][3] = f2tf(v11 + c1v);
            aP[s][0] = f2tf(v00 + p0v); aP[s][1] = f2tf(v10 + p0v);
            aP[s][2] = f2tf(v01 + p1v); aP[s][3] = f2tf(v11 + p1v);
        }
    }
    if (tid < 64) {
        const float* qr = qkv + ((size_t)(b * SEQ + q0 + tid)) * H3 + h * DH;
        float s0 = 0.f, s1 = 0.f;
        for (int d = 0; d < DH; d++) {
            float qs = qr[d] + sb[h * DH + d];
            s0 += qs * seg[h * DH + d];
            s1 += qs * seg[NH * DH + h * DH + d];
        }
        s0s[tid] = s0; s1s[tid] = s1;
    }

    float O[8][4] = {};
    float m_a = -1e30f, m_b = -1e30f, l_a = 0.f, l_b = 0.f;

    auto pp_tile = [&](int slot) {
        float* rg = ring + slot * T64;
#pragma unroll
        for (int jn = 0; jn < 8; jn++) {
            float c[4] = {0.f, 0.f, 0.f, 0.f};
            const float* bp = KPs + (jn * 8 + lr) * FST;
#pragma unroll
            for (int s = 0; s < 8; s++) {
                uint32_t bfr[2];
                bfr[0] = __float_as_uint(bp[8 * s + lc]);
                bfr[1] = __float_as_uint(bp[8 * s + lc + 4]);
                mma_tf32(c, aP[s], bfr);
            }
            float* r0 = rg + (qb + lr) * FST + jn * 8 + 2 * lc;
            *(float2*)r0 = make_float2(c[0], c[1]);
            *(float2*)(r0 + 8 * FST) = make_float2(c[2], c[3]);
        }
        __syncwarp();
    };

    {
        stage64f(KPs, kp + ((size_t)(b * SEQ2 + SEQ - q0 - 64)) * HIDD + h * DH, HIDD, tid);
        asm volatile("cp.async.commit_group;");
        asm volatile("cp.async.wait_group 0;");
        __syncthreads();
        for (int i = tid; i < T64 / 4; i += 128) {
            float4* p4 = ((float4*)(sm + T64)) + i;
            float4 vv = *p4;
            vv.x = __uint_as_float(f2tf(vv.x)); vv.y = __uint_as_float(f2tf(vv.y));
            vv.z = __uint_as_float(f2tf(vv.z)); vv.w = __uint_as_float(f2tf(vv.w));
            *p4 = vv;
        }
        __syncthreads();
        pp_tile((15 - qt) & 1);
    }

    const int ra = qb + lr, rb = ra + 8;
    const size_t mbase_a = ((size_t)b * SEQ + q0 + ra) * SEQ;
    const size_t mbase_b = mbase_a + (size_t)8 * SEQ;
    const float s0a = s0s[ra], s1a = s1s[ra];
    const float s0b = s0s[rb], s1b = s1s[rb];

    for (int kt = 0; kt < 16; kt++) {
        const int k0 = kt * 64;
        const int Tb = 16 + kt - qt;
        __syncthreads();
        stage64f(KCs, qkv + ((size_t)(b * SEQ + k0)) * H3 + 1024 + h * DH, H3, tid);
        stage64f(Vs,  qkv + ((size_t)(b * SEQ + k0)) * H3 + 2048 + h * DH, H3, tid);
        stage64f(KPs, kp + ((size_t)b * SEQ2 + (size_t)64 * Tb) * HIDD + h * DH, HIDD, tid);
        asm volatile("cp.async.commit_group;");
        asm volatile("cp.async.wait_group 0;");
        __syncthreads();
        for (int i = tid; i < 3 * T64 / 4; i += 128) {
            float4* p4 = ((float4*)sm) + i;
            float4 vv = *p4;
            vv.x = __uint_as_float(f2tf(vv.x)); vv.y = __uint_as_float(f2tf(vv.y));
            vv.z = __uint_as_float(f2tf(vv.z)); vv.w = __uint_as_float(f2tf(vv.w));
            *p4 = vv;
        }
        __syncthreads();

        pp_tile(Tb & 1);
        const int slotA = (Tb - 1) & 1, slotB = Tb & 1;

        float cs[8][4];
#pragma unroll
        for (int jn = 0; jn < 8; jn++) {
            float c[4] = {0.f, 0.f, 0.f, 0.f};
            const float* bp = KCs + (jn * 8 + lr) * FST;
#pragma unroll
            for (int s = 0; s < 8; s++) {
                uint32_t bfr[2];
                bfr[0] = __float_as_uint(bp[8 * s + lc]);
                bfr[1] = __float_as_uint(bp[8 * s + lc + 4]);
                mma_tf32(c, aC[s], bfr);
            }
            cs[jn][0] = c[0]; cs[jn][1] = c[1]; cs[jn][2] = c[2]; cs[jn][3] = c[3];
        }

        float mxa = -1e30f, mxb = -1e30f;
#pragma unroll
        for (int jn = 0; jn < 8; jn++) {
            const int kkp = jn * 8 + 2 * lc;
            float2 mva = *(const float2*)(mask + mbase_a + k0 + kkp);
            float2 mvb = *(const float2*)(mask + mbase_b + k0 + kkp);
            float sa0 = seg_at(segmat, mbase_a + k0 + kkp, mode)     ? s1a : s0a;
            float sa1 = seg_at(segmat, mbase_a + k0 + kkp + 1, mode) ? s1a : s0a;
            float sb0 = seg_at(segmat, mbase_b + k0 + kkp, mode)     ? s1b : s0b;
            float sb1 = seg_at(segmat, mbase_b + k0 + kkp + 1, mode) ? s1b : s0b;
            const int wa = kkp - ra + 64, wb = kkp - rb + 64;
            float ppa0 = ring[(wa < 64 ? slotA : slotB) * T64 + ra * FST + (wa & 63)];
            float ppa1 = ring[(wa + 1 < 64 ? slotA : slotB) * T64 + ra * FST + ((wa + 1) & 63)];
            float ppb0 = ring[(wb < 64 ? slotA : slotB) * T64 + rb * FST + (wb & 63)];
            float ppb1 = ring[(wb + 1 < 64 ? slotA : slotB) * T64 + rb * FST + ((wb + 1) & 63)];
            cs[jn][0] = (cs[jn][0] + ppa0 + sa0) * 0.125f + mva.x * (-1e9f);
            cs[jn][1] = (cs[jn][1] + ppa1 + sa1) * 0.125f + mva.y * (-1e9f);
            cs[jn][2] = (cs[jn][2] + ppb0 + sb0) * 0.125f + mvb.x * (-1e9f);
            cs[jn][3] = (cs[jn][3] + ppb1 + sb1) * 0.125f + mvb.y * (-1e9f);
            mxa = fmaxf(mxa, fmaxf(cs[jn][0], cs[jn][1]));
            mxb = fmaxf(mxb, fmaxf(cs[jn][2], cs[jn][3]));
        }
        __syncthreads();

        mxa = fmaxf(mxa, __shfl_xor_sync(0xffffffffu, mxa, 1));
        mxa = fmaxf(mxa, __shfl_xor_sync(0xffffffffu, mxa, 2));
        mxb = fmaxf(mxb, __shfl_xor_sync(0xffffffffu, mxb, 1));
        mxb = fmaxf(mxb, __shfl_xor_sync(0xffffffffu, mxb, 2));

        const float mna = fmaxf(m_a, mxa), mnb = fmaxf(m_b, mxb);
        const float alA = __expf(m_a - mna), alB = __expf(m_b - mnb);
        m_a = mna; m_b = mnb;

        float sa = 0.f, sbm = 0.f;
#pragma unroll
        for (int jn = 0; jn < 8; jn++) {
            float p0 = __expf(cs[jn][0] - m_a), p1 = __expf(cs[jn][1] - m_a);
            float p2 = __expf(cs[jn][2] - m_b), p3 = __expf(cs[jn][3] - m_b);
            sa += p0 + p1; sbm += p2 + p3;
            *(float2*)(Ps + ra * FST + jn * 8 + 2 * lc) =
                make_float2(__uint_as_float(f2tf(p0)), __uint_as_float(f2tf(p1)));
            *(float2*)(Ps + rb * FST + jn * 8 + 2 * lc) =
                make_float2(__uint_as_float(f2tf(p2)), __uint_as_float(f2tf(p3)));
            O[jn][0] *= alA; O[jn][1] *= alA; O[jn][2] *= alB; O[jn][3] *= alB;
        }
        sa  += __shfl_xor_sync(0xffffffffu, sa, 1);
        sa  += __shfl_xor_sync(0xffffffffu, sa, 2);
        sbm += __shfl_xor_sync(0xffffffffu, sbm, 1);
        sbm += __shfl_xor_sync(0xffffffffu, sbm, 2);
        l_a = l_a * alA + sa;
        l_b = l_b * alB + sbm;
        __syncwarp();

        uint32_t ap[8][4];
#pragma unroll
        for (int s = 0; s < 8; s++) {
            ap[s][0] = __float_as_uint(Ps[ra * FST + 8 * s + lc]);
            ap[s][1] = __float_as_uint(Ps[rb * FST + 8 * s + lc]);
            ap[s][2] = __float_as_uint(Ps[ra * FST + 8 * s + lc + 4]);
            ap[s][3] = __float_as_uint(Ps[rb * FST + 8 * s + lc + 4]);
        }
#pragma unroll
        for (int jn = 0; jn < 8; jn++) {
#pragma unroll
            for (int s = 0; s < 8; s++) {
                uint32_t bfr[2];
                bfr[0] = __float_as_uint(Vs[(8 * s + lc) * FST + jn * 8 + lr]);
                bfr[1] = __float_as_uint(Vs[(8 * s + lc + 4) * FST + jn * 8 + lr]);
                mma_tf32(O[jn], ap[s], bfr);
            }
        }
        __syncwarp();
    }

    const float ia = 1.f / l_a, ib = 1.f / l_b;
    float* o0 = out + ((size_t)(b * SEQ + q0 + ra)) * HIDD + h * DH;
    float* o1 = o0 + (size_t)8 * HIDD;
#pragma unroll
    for (int jn = 0; jn < 8; jn++) {
        *(float2*)(o0 + jn * 8 + 2 * lc) = make_float2(O[jn][0] * ia, O[jn][1] * ia);
        *(float2*)(o1 + jn * 8 + 2 * lc) = make_float2(O[jn][2] * ib, O[jn][3] * ib);
    }
}

// ---------------- small kernels ----------------
__global__ void zero_f(float* __restrict__ p, int n) {
    int i = blockIdx.x * 256 + threadIdx.x;
    if (i < n) p[i] = 0.f;
}

__global__ void pack_w(const float* __restrict__ wq, const float* __restrict__ wkc,
                       const float* __restrict__ wv, float* __restrict__ W)
{
    int i = blockIdx.x * 256 + threadIdx.x;
    int r = i >> 10, c = i & 1023;
    float* dst = W + (size_t)r * H3 + c;
    dst[0]    = wq[i];
    dst[1024] = wkc[i];
    dst[2048] = wv[i];
}

__global__ void add_bias2(const float* __restrict__ src, int ld,
                          const float* __restrict__ cb, const float* __restrict__ pb,
                          float* __restrict__ ocb, float* __restrict__ opb)
{
    const int row = blockIdx.x, t = threadIdx.x;
    const float* s = src + (size_t)row * ld;
    float* o1 = ocb + (size_t)row * HIDD;
    float* o2 = opb + (size_t)row * HIDD;
    for (int i = t; i < HIDD; i += 256) {
        float v = s[i];
        o1[i] = v + cb[i];
        o2[i] = v + pb[i];
    }
}

__global__ void scatter_q(const float* __restrict__ tmap, const float* __restrict__ qg,
                          float* __restrict__ qscat, int* __restrict__ idx)
{
    const int b = blockIdx.y, p = blockIdx.x, t = threadIdx.x;
    __shared__ int sidx;
    const float* row = tmap + ((size_t)b * PQ + p) * SEQ;
    for (int s = t; s < SEQ; s += 128)
        if (row[s] > 0.5f) sidx = s;
    __syncthreads();
    const int si = sidx;
    if (t == 0) idx[b * PQ + p] = si;
    const float* src = qg + ((size_t)b * PQ + p) * HIDD;
    float* dst = qscat + ((size_t)b * SEQ + si) * HIDD;
    for (int i = t; i < HIDD; i += 128) atomicAdd(&dst[i], src[i]);
}

__global__ void gather_q(const float* __restrict__ qscat, const int* __restrict__ idx,
                         float* __restrict__ qq)
{
    const int b = blockIdx.y, p = blockIdx.x, t = threadIdx.x;
    const int si = idx[b * PQ + p];
    const float* src = qscat + ((size_t)b * SEQ + si) * HIDD;
    float* dst = qq + ((size_t)b * PQ + p) * HIDD;
    for (int i = t; i < HIDD; i += 128) dst[i] = src[i];
}

// ---------------- query-stream softmax ----------------
__global__ __launch_bounds__(256) void softmax_kernel(
    float* __restrict__ cs, const float* __restrict__ pp,
    const float* __restrict__ qArr, const float* __restrict__ sb,
    const float* __restrict__ seg, const void* __restrict__ segmat,
    const float* __restrict__ mask, const int* __restrict__ qidx,
    int Mrows, long qBatchStride, int ldq)
{
    const int b = blockIdx.z, h = blockIdx.y, qo = blockIdx.x, t = threadIdx.x;
    const int qrow = qidx ? qidx[b * PQ + qo] : qo;
    const int z = b * NH + h;
    const int mode = g_segmode[0];

    float* csrow = cs + ((size_t)z * Mrows + qo) * SEQ;
    const float* pprow = pp + ((size_t)z * Mrows + qo) * SEQ2 + (SEQ - qrow);
    const float* mrow = mask + ((size_t)b * SEQ + qrow) * SEQ;
    const size_t segbase = ((size_t)b * SEQ + qrow) * SEQ;

    __shared__ float qsv[DH];
    __shared__ float s01[2];
    __shared__ float red[256];

    if (t < DH)
        qsv[t] = qArr[qBatchStride * b + (size_t)qo * ldq + h * DH + t] + sb[h * DH + t];
    __syncthreads();
    if (t < 64) {
        const int which = t >> 5, lx = t & 31;
        const float* sgp = seg + which * NH * DH + h * DH;
        float a = qsv[lx] * sgp[lx] + qsv[lx + 32] * sgp[lx + 32];
#pragma unroll
        for (int o = 16; o; o >>= 1) a += __shfl_xor_sync(0xffffffffu, a, o);
        if (lx == 0) s01[which] = a;
    }
    __syncthreads();
    const float s0 = s01[0], s1 = s01[1];

    float lg[4];
    float mx = -3.4e38f;
#pragma unroll
    for (int j = 0; j < 4; j++) {
        int k = t + j * 256;
        float sgv = seg_at(segmat, segbase + k, mode) ? s1 : s0;
        float v = (csrow[k] + pprow[k] + sgv) * 0.125f + mrow[k] * (-1e9f);
        lg[j] = v;
        mx = fmaxf(mx, v);
    }
    red[t] = mx; __syncthreads();
#pragma unroll
    for (int s2 = 128; s2; s2 >>= 1) {
        if (t < s2) red[t] = fmaxf(red[t], red[t + s2]);
        __syncthreads();
    }
    mx = red[0]; __syncthreads();

    float sum = 0.f;
#pragma unroll
    for (int j = 0; j < 4; j++) {
        float e = __expf(lg[j] - mx);
        lg[j] = e;
        sum += e;
    }
    red[t] = sum; __syncthreads();
#pragma unroll
    for (int s2 = 128; s2; s2 >>= 1) {
        if (t < s2) red[t] += red[t + s2];
        __syncthreads();
    }
    const float invZ = 1.f / red[0];
#pragma unroll
    for (int j = 0; j < 4; j++) csrow[t + j * 256] = lg[j] * invZ;
}

// ---------------- launch ----------------
extern "C" void kernel_launch(void* const* d_in, const int* in_sizes, int n_in,
                              void* d_out, int out_size)
{
    const float* content = (const float*)d_in[0];
    const float* query   = (const float*)d_in[1];
    const float* pe      = (const float*)d_in[2];
    const void*  segmat  = d_in[3];
    const float* segenc  = (const float*)d_in[4];
    const float* segbias = (const float*)d_in[5];
    const float* cmask   = (const float*)d_in[6];
    const float* qmask   = (const float*)d_in[7];
    const float* tmap    = (const float*)d_in[8];
    const float* cbias   = (const float*)d_in[9];
    const float* pbias   = (const float*)d_in[10];
    const float* wq      = (const float*)d_in[11];
    const float* wkc     = (const float*)d_in[12];
    const float* wv      = (const float*)d_in[13];
    const float* wkp     = (const float*)d_in[14];
    const float* wo      = (const float*)d_in[15];
    float* out = (float*)d_out;

    float *qkv, *wpack, *kp, *qg, *qscat, *qq, *qqcb, *qqpb;
    float *csq, *ppq, *catt, *qatt;
    int* idx;
    cudaGetSymbolAddress((void**)&qkv,   g_qkv);
    cudaGetSymbolAddress((void**)&wpack, g_wpack);
    cudaGetSymbolAddress((void**)&kp,    g_kp);
    cudaGetSymbolAddress((void**)&qg,    g_qg);
    cudaGetSymbolAddress((void**)&qscat, g_qscat);
    cudaGetSymbolAddress((void**)&qq,    g_qq);
    cudaGetSymbolAddress((void**)&qqcb,  g_qqcb);
    cudaGetSymbolAddress((void**)&qqpb,  g_qqpb);
    cudaGetSymbolAddress((void**)&csq,   g_csq);
    cudaGetSymbolAddress((void**)&ppq,   g_ppq);
    cudaGetSymbolAddress((void**)&catt,  g_catt);
    cudaGetSymbolAddress((void**)&qatt,  g_qatt);
    cudaGetSymbolAddress((void**)&idx,   g_idx);

    static bool attr_done = false;
    if (!attr_done) {
        cudaFuncSetAttribute(flash_content, cudaFuncAttributeMaxDynamicSharedMemorySize,
                             FL_SMEMF * sizeof(float));
        attr_done = true;
    }

    probe_segmat<<<1, 32>>>((const uint32_t*)segmat);
    zero_f<<<(BATCH * SEQ * HIDD + 255) / 256, 256>>>(qscat, BATCH * SEQ * HIDD);
    pack_w<<<4096, 256>>>(wq, wkc, wv, wpack);

    const long SH = (long)SEQ * HIDD, S2H = (long)SEQ2 * HIDD, PH = (long)PQ * HIDD;
    const long SH3 = (long)SEQ * H3;
    const long PS = (long)PQ * SEQ, PS2 = (long)PQ * SEQ2;

    // projections (128-wide tiles)
    gemm128<false><<<dim3(24, 16, 1), 256>>>(content, wpack, qkv,
        2048, H3, HIDD, HIDD, H3, H3, 0,0,0,0,0,0, 1);
    gemm128<false><<<dim3(8, 32, 1), 256>>>(pe, wkp, kp,
        4096, HIDD, HIDD, HIDD, HIDD, HIDD, 0,0,0,0,0,0, 1);
    gemm128<false><<<dim3(8, 2, 1), 256>>>(query, wq, qg,
        256, HIDD, HIDD, HIDD, HIDD, HIDD, 0,0,0,0,0,0, 1);

    scatter_q<<<dim3(PQ, BATCH), 128>>>(tmap, qg, qscat, idx);
    gather_q<<<dim3(PQ, BATCH), 128>>>(qscat, idx, qq);
    add_bias2<<<BATCH * PQ, 256>>>(qq, HIDD, cbias, pbias, qqcb, qqpb);

    const float* kcp = qkv + 1024;
    const float* vp  = qkv + 2048;

    // content stream: flash-fused (q-tile 64)
    flash_content<<<dim3(SEQ / 64, NH, BATCH), 128, FL_SMEMF * sizeof(float)>>>(
        qkv, kp, cbias, pbias, segbias, segenc, segmat, cmask, catt);

    // query stream (score GEMMs on 128-wide tiles)
    gemm128<true><<<dim3(8, 1, BATCH * NH), 256>>>(qqcb, kcp, csq,
        PQ, SEQ, DH, HIDD, H3, SEQ,  PH, DH, SH3, DH, (long)NH * PS, PS, NH);
    gemm128<true><<<dim3(16, 1, BATCH * NH), 256>>>(qqpb, kp, ppq,
        PQ, SEQ2, DH, HIDD, HIDD, SEQ2, PH, DH, S2H, DH, (long)NH * PS2, PS2, NH);
    softmax_kernel<<<dim3(PQ, NH, BATCH), 256>>>(
        csq, ppq, qq, segbias, segenc, segmat, qmask, idx, PQ, PH, HIDD);
    gemm_tf32<false><<<dim3(1, 1, BATCH * NH), 256>>>(csq, vp, qatt,
        PQ, DH, SEQ, SEQ, H3, HIDD, (long)NH * PS, PS, SH3, DH, PH, DH, NH);

    // output projections (128-wide tiles)
    gemm128<false><<<dim3(8, 16, 1), 256>>>(catt, wo, out,
        2048, HIDD, HIDD, HIDD, HIDD, HIDD, 0,0,0,0,0,0, 1);
    gemm128<false><<<dim3(8, 2, 1), 256>>>(qatt, wo, out + (size_t)BATCH * SEQ * HIDD,
        256, HIDD, HIDD, HIDD, HIDD, HIDD, 0,0,0,0,0,0, 1);
}

// round 8
// speedup vs baseline: 1.0837x; 1.0225x over previous
#include <cuda_runtime.h>
#include <cstdint>
#include <cstddef>

#define BATCH 2
#define SEQ   1024
#define SEQ2  2048
#define PQ    128
#define HIDD  1024
#define NH    16
#define DH    64
#define H3    3072
#define NOCVT (1 << 30)

// ---------------- scratch ----------------
__device__ float g_qkv[BATCH * SEQ * H3];      // q (fp32) | kc (tf32) | v (tf32)
__device__ float g_wpack[HIDD * H3];           // tf32 bits
__device__ float g_kp[BATCH * SEQ2 * HIDD];    // tf32 bits
__device__ float g_qg[BATCH * PQ * HIDD];
__device__ float g_qscat[BATCH * SEQ * HIDD];
__device__ float g_qq[BATCH * PQ * HIDD];
__device__ float g_qqcb[BATCH * PQ * HIDD];    // tf32
__device__ float g_qqpb[BATCH * PQ * HIDD];    // tf32
__device__ float g_csq[(size_t)BATCH * NH * PQ * SEQ];       // tf32 after softmax
__device__ float g_ppq[(size_t)BATCH * NH * PQ * SEQ2];
__device__ float g_catt[BATCH * SEQ * HIDD];   // tf32
__device__ float g_qatt[BATCH * PQ * HIDD];    // tf32
__device__ float g_content_c[BATCH * SEQ * HIDD];   // tf32 copies of inputs
__device__ float g_pe_c[BATCH * SEQ2 * HIDD];
__device__ float g_query_c[BATCH * PQ * HIDD];
__device__ float g_wo_c[HIDD * HIDD];
__device__ float g_wkp_c[HIDD * HIDD];
__device__ int   g_idx[BATCH * PQ];
__device__ int   g_segmode[1];

// ---------------- probe ----------------
__global__ void probe_segmat(const uint32_t* __restrict__ p) {
    if (threadIdx.x == 0 && blockIdx.x == 0) {
        int mode = 1;
        for (int i = 0; i < 4096; i++) {
            uint32_t w = p[i];
            if (w == 0x3F800000u) { mode = 2; break; }
            if (w > 1u)           { mode = 0; break; }
        }
        g_segmode[0] = mode;
    }
}

__device__ __forceinline__ bool seg_at(const void* p, size_t i, int mode) {
    if (mode == 0) return ((const uint8_t*)p)[i] != 0;
    if (mode == 1) return ((const int*)p)[i] != 0;
    return ((const float*)p)[i] > 0.5f;
}

// ---------------- tf32 helpers ----------------
__device__ __forceinline__ uint32_t f2tf(float f) {
    uint32_t u;
    asm("cvt.rna.tf32.f32 %0, %1;" : "=r"(u) : "f"(f));
    return u;
}
__device__ __forceinline__ float f2tff(float f) { return __uint_as_float(f2tf(f)); }

__device__ __forceinline__ void mma_tf32(float* c, const uint32_t* a, const uint32_t* b) {
    asm volatile(
        "mma.sync.aligned.m16n8k8.row.col.f32.tf32.tf32.f32 "
        "{%0,%1,%2,%3}, {%4,%5,%6,%7}, {%8,%9}, {%0,%1,%2,%3};"
        : "+f"(c[0]), "+f"(c[1]), "+f"(c[2]), "+f"(c[3])
        : "r"(a[0]), "r"(a[1]), "r"(a[2]), "r"(a[3]), "r"(b[0]), "r"(b[1]));
}

__device__ __forceinline__ void cp16(uint32_t s, const float* g) {
    asm volatile("cp.async.ca.shared.global [%0], [%1], 16;" :: "r"(s), "l"(g));
}

// ---------------- elementwise tf32 convert (float4) ----------------
__global__ void cvt_f(const float* __restrict__ src, float* __restrict__ dst, int n4) {
    int i = blockIdx.x * 256 + threadIdx.x;
    if (i < n4) {
        float4 v = ((const float4*)src)[i];
        v.x = f2tff(v.x); v.y = f2tff(v.y); v.z = f2tff(v.z); v.w = f2tff(v.w);
        ((float4*)dst)[i] = v;
    }
}

// ---------------- tf32 GEMM 128x64, 2-stage; operands pre-converted ----------------
#define AST  20
#define BSTN 72
#define BSTT 20

template<bool TB>
__global__ __launch_bounds__(256) void gemm_tf32(
    const float* __restrict__ A, const float* __restrict__ B, float* __restrict__ C,
    int M, int N, int K, int lda, int ldb, int ldc,
    long aOut, long aIn, long bOut, long bIn, long cOut, long cIn, int zInner, int cvtCol)
{
    __shared__ float As[2][128 * AST];
    __shared__ float Bs[2][1280];

    const int tid = threadIdx.x;
    const int zo = blockIdx.z / zInner, zi = blockIdx.z % zInner;
    const float* Ap = A + zo * aOut + zi * aIn;
    const float* Bp = B + zo * bOut + zi * bIn;
    float*       Cp = C + zo * cOut + zi * cIn;
    const int m0 = blockIdx.y * 128, n0 = blockIdx.x * 64;

    const int wid = tid >> 5, lane = tid & 31;
    const int wm = (wid & 3) * 32, wn = (wid >> 2) * 32;
    const int lr = lane >> 2, lc = lane & 3;

    uint32_t aSm[2], bSm[2];
    aSm[0] = (uint32_t)__cvta_generic_to_shared(&As[0][0]);
    aSm[1] = (uint32_t)__cvta_generic_to_shared(&As[1][0]);
    bSm[0] = (uint32_t)__cvta_generic_to_shared(&Bs[0][0]);
    bSm[1] = (uint32_t)__cvta_generic_to_shared(&Bs[1][0]);

    const int ar = tid >> 2, ac = (tid & 3) * 4;

    auto stage = [&](int kt) {
        const int k0 = kt * 16, buf = kt & 1;
        const float* ga = Ap + (size_t)(m0 + ar) * lda + k0 + ac;
        cp16(aSm[buf] + (ar * AST + ac) * 4, ga);
        cp16(aSm[buf] + ((ar + 64) * AST + ac) * 4, ga + (size_t)64 * lda);
        if (TB) {
            cp16(bSm[buf] + (ar * BSTT + ac) * 4,
                 Bp + (size_t)(n0 + ar) * ldb + k0 + ac);
        } else {
            const int br = tid >> 4, bc = (tid & 15) * 4;
            cp16(bSm[buf] + (br * BSTN + bc) * 4,
                 Bp + (size_t)(k0 + br) * ldb + n0 + bc);
        }
    };

    float acc[2][4][4] = {};

    stage(0);
    asm volatile("cp.async.commit_group;");
    const int KT = K >> 4;

    for (int kt = 0; kt < KT; kt++) {
        if (kt + 1 < KT) {
            stage(kt + 1);
            asm volatile("cp.async.commit_group;");
            asm volatile("cp.async.wait_group 1;");
        } else {
            asm volatile("cp.async.wait_group 0;");
        }
        __syncthreads();

        const float* as = As[kt & 1];
        const float* bs = Bs[kt & 1];
#pragma unroll
        for (int kk = 0; kk < 16; kk += 8) {
            uint32_t af[2][4], bf[4][2];
#pragma unroll
            for (int im = 0; im < 2; im++) {
                const int base = (wm + im * 16 + lr) * AST + kk + lc;
                af[im][0] = __float_as_uint(as[base]);
                af[im][1] = __float_as_uint(as[base + 8 * AST]);
                af[im][2] = __float_as_uint(as[base + 4]);
                af[im][3] = __float_as_uint(as[base + 8 * AST + 4]);
            }
#pragma unroll
            for (int jn = 0; jn < 4; jn++) {
                if (TB) {
                    const int bb = (wn + jn * 8 + lr) * BSTT + kk + lc;
                    bf[jn][0] = __float_as_uint(bs[bb]);
                    bf[jn][1] = __float_as_uint(bs[bb + 4]);
                } else {
                    const int bb = (kk + lc) * BSTN + wn + jn * 8 + lr;
                    bf[jn][0] = __float_as_uint(bs[bb]);
                    bf[jn][1] = __float_as_uint(bs[bb + 4 * BSTN]);
                }
            }
#pragma unroll
            for (int im = 0; im < 2; im++)
#pragma unroll
                for (int jn = 0; jn < 4; jn++)
                    mma_tf32(acc[im][jn], af[im], bf[jn]);
        }
        __syncthreads();
    }

#pragma unroll
    for (int im = 0; im < 2; im++) {
#pragma unroll
        for (int jn = 0; jn < 4; jn++) {
            const int row = m0 + wm + im * 16 + lr;
            const int col = n0 + wn + jn * 8 + 2 * lc;
            float v0 = acc[im][jn][0], v1 = acc[im][jn][1];
            float v2 = acc[im][jn][2], v3 = acc[im][jn][3];
            if (col >= cvtCol) {
                v0 = f2tff(v0); v1 = f2tff(v1); v2 = f2tff(v2); v3 = f2tff(v3);
            }
            *(float2*)(Cp + (size_t)row * ldc + col) = make_float2(v0, v1);
            *(float2*)(Cp + (size_t)(row + 8) * ldc + col) = make_float2(v2, v3);
        }
    }
}

// ---------------- tf32 GEMM 128x128, 2-stage; operands pre-converted ----------------
#define B128 136

template<bool TB>
__global__ __launch_bounds__(256) void gemm128(
    const float* __restrict__ A, const float* __restrict__ B, float* __restrict__ C,
    int M, int N, int K, int lda, int ldb, int ldc,
    long aOut, long aIn, long bOut, long bIn, long cOut, long cIn, int zInner, int cvtCol)
{
    __shared__ float As[2][128 * AST];
    __shared__ float Bs[2][TB ? 128 * BSTT : 16 * B128];

    const int tid = threadIdx.x;
    const int zo = blockIdx.z / zInner, zi = blockIdx.z % zInner;
    const float* Ap = A + zo * aOut + zi * aIn;
    const float* Bp = B + zo * bOut + zi * bIn;
    float*       Cp = C + zo * cOut + zi * cIn;
    const int m0 = blockIdx.y * 128, n0 = blockIdx.x * 128;

    const int wid = tid >> 5, lane = tid & 31;
    const int wm = (wid & 3) * 32, wn = (wid >> 2) * 64;
    const int lr = lane >> 2, lc = lane & 3;

    uint32_t aSm[2], bSm[2];
    aSm[0] = (uint32_t)__cvta_generic_to_shared(&As[0][0]);
    aSm[1] = (uint32_t)__cvta_generic_to_shared(&As[1][0]);
    bSm[0] = (uint32_t)__cvta_generic_to_shared(&Bs[0][0]);
    bSm[1] = (uint32_t)__cvta_generic_to_shared(&Bs[1][0]);

    const int ar = tid >> 2, ac = (tid & 3) * 4;

    auto stage = [&](int kt) {
        const int k0 = kt * 16, buf = kt & 1;
        const float* ga = Ap + (size_t)(m0 + ar) * lda + k0 + ac;
        cp16(aSm[buf] + (ar * AST + ac) * 4, ga);
        cp16(aSm[buf] + ((ar + 64) * AST + ac) * 4, ga + (size_t)64 * lda);
        if (TB) {
            const int r = tid >> 1, c = (tid & 1) * 8;
            const float* gb = Bp + (size_t)(n0 + r) * ldb + k0 + c;
            cp16(bSm[buf] + (r * BSTT + c) * 4, gb);
            cp16(bSm[buf] + (r * BSTT + c + 4) * 4, gb + 4);
        } else {
            const int br = tid >> 4, bc = (tid & 15) * 4;
            const float* gb = Bp + (size_t)(k0 + br) * ldb + n0 + bc;
            cp16(bSm[buf] + (br * B128 + bc) * 4, gb);
            cp16(bSm[buf] + (br * B128 + bc + 64) * 4, gb + 64);
        }
    };

    float acc[2][8][4] = {};

    stage(0);
    asm volatile("cp.async.commit_group;");
    const int KT = K >> 4;

    for (int kt = 0; kt < KT; kt++) {
        if (kt + 1 < KT) {
            stage(kt + 1);
            asm volatile("cp.async.commit_group;");
            asm volatile("cp.async.wait_group 1;");
        } else {
            asm volatile("cp.async.wait_group 0;");
        }
        __syncthreads();

        const float* as = As[kt & 1];
        const float* bs = Bs[kt & 1];
#pragma unroll
        for (int kk = 0; kk < 16; kk += 8) {
            uint32_t af[2][4], bf[8][2];
#pragma unroll
            for (int im = 0; im < 2; im++) {
                const int base = (wm + im * 16 + lr) * AST + kk + lc;
                af[im][0] = __float_as_uint(as[base]);
                af[im][1] = __float_as_uint(as[base + 8 * AST]);
                af[im][2] = __float_as_uint(as[base + 4]);
                af[im][3] = __float_as_uint(as[base + 8 * AST + 4]);
            }
#pragma unroll
            for (int jn = 0; jn < 8; jn++) {
                if (TB) {
                    const int bb = (wn + jn * 8 + lr) * BSTT + kk + lc;
                    bf[jn][0] = __float_as_uint(bs[bb]);
                    bf[jn][1] = __float_as_uint(bs[bb + 4]);
                } else {
                    const int bb = (kk + lc) * B128 + wn + jn * 8 + lr;
                    bf[jn][0] = __float_as_uint(bs[bb]);
                    bf[jn][1] = __float_as_uint(bs[bb + 4 * B128]);
                }
            }
#pragma unroll
            for (int im = 0; im < 2; im++)
#pragma unroll
                for (int jn = 0; jn < 8; jn++)
                    mma_tf32(acc[im][jn], af[im], bf[jn]);
        }
        __syncthreads();
    }

#pragma unroll
    for (int im = 0; im < 2; im++) {
#pragma unroll
        for (int jn = 0; jn < 8; jn++) {
            const int row = m0 + wm + im * 16 + lr;
            const int col = n0 + wn + jn * 8 + 2 * lc;
            float v0 = acc[im][jn][0], v1 = acc[im][jn][1];
            float v2 = acc[im][jn][2], v3 = acc[im][jn][3];
            if (col >= cvtCol) {
                v0 = f2tff(v0); v1 = f2tff(v1); v2 = f2tff(v2); v3 = f2tff(v3);
            }
            *(float2*)(Cp + (size_t)row * ldc + col) = make_float2(v0, v1);
            *(float2*)(Cp + (size_t)(row + 8) * ldc + col) = make_float2(v2, v3);
        }
    }
}

// ---------------- flash-fused content attention (q64, 128 thr, no cvt sweep) ----------------
#define FST 68
#define T64 (64 * FST)
#define FL_SMEMF (5 * T64 + 128)

__device__ __forceinline__ void stage64f(float* dst, const float* src, long rstride, int tid) {
    uint32_t s = (uint32_t)__cvta_generic_to_shared(dst);
#pragma unroll
    for (int i = 0; i < 8; i++) {
        int id = tid + i * 128;
        int j = id >> 4, d4 = (id & 15) * 4;
        cp16(s + (uint32_t)(j * FST + d4) * 4, src + (size_t)j * rstride + d4);
    }
}

__global__ __launch_bounds__(128, 2) void flash_content(
    const float* __restrict__ qkv, const float* __restrict__ kp,
    const float* __restrict__ cb, const float* __restrict__ pb,
    const float* __restrict__ sb, const float* __restrict__ seg,
    const void* __restrict__ segmat, const float* __restrict__ mask,
    float* __restrict__ out)
{
    extern __shared__ float sm[];
    float* KCs  = sm;
    float* KPs  = sm + T64;
    float* Vs   = sm + 2 * T64;
    float* ring = sm + 3 * T64;
    float* s0s  = sm + 5 * T64;
    float* s1s  = s0s + 64;
    float* Ps   = KPs;

    const int b = blockIdx.z, h = blockIdx.y, qt = blockIdx.x, q0 = qt * 64;
    const int tid = threadIdx.x, w = tid >> 5, l = tid & 31;
    const int lr = l >> 2, lc = l & 3;
    const int qb = w * 16;
    const int mode = g_segmode[0];

    uint32_t aC[8][4], aP[8][4];
    {
        const float* r0 = qkv + ((size_t)(b * SEQ + q0 + qb + lr)) * H3 + h * DH;
        const float* r1 = r0 + (size_t)8 * H3;
#pragma unroll
        for (int s = 0; s < 8; s++) {
            const int d0 = 8 * s + lc, d1 = d0 + 4;
            const float c0v = cb[h * DH + d0], c1v = cb[h * DH + d1];
            const float p0v = pb[h * DH + d0], p1v = pb[h * DH + d1];
            float v00 = r0[d0], v01 = r0[d1], v10 = r1[d0], v11 = r1[d1];
            aC[s][0] = f2tf(v00 + c0v); aC[s][1] = f2tf(v10 + c0v);
            aC[s][2] = f2tf(v01 + c1v); aC[s][3] = f2tf(v11 + c1v);
            aP[s][0] = f2tf(v00 + p0v); aP[s][1] = f2tf(v10 + p0v);
            aP[s][2] = f2tf(v01 + p1v); aP[s][3] = f2tf(v11 + p1v);
        }
    }
    if (tid < 64) {
        const float* qr = qkv + ((size_t)(b * SEQ + q0 + tid)) * H3 + h * DH;
        float s0 = 0.f, s1 = 0.f;
        for (int d = 0; d < DH; d++) {
            float qs = qr[d] + sb[h * DH + d];
            s0 += qs * seg[h * DH + d];
            s1 += qs * seg[NH * DH + h * DH + d];
        }
        s0s[tid] = s0; s1s[tid] = s1;
    }

    float O[8][4] = {};
    float m_a = -1e30f, m_b = -1e30f, l_a = 0.f, l_b = 0.f;

    auto pp_tile = [&](int slot) {
        float* rg = ring + slot * T64;
#pragma unroll
        for (int jn = 0; jn < 8; jn++) {
            float c[4] = {0.f, 0.f, 0.f, 0.f};
            const float* bp = KPs + (jn * 8 + lr) * FST;
#pragma unroll
            for (int s = 0; s < 8; s++) {
                uint32_t bfr[2];
                bfr[0] = __float_as_uint(bp[8 * s + lc]);
                bfr[1] = __float_as_uint(bp[8 * s + lc + 4]);
                mma_tf32(c, aP[s], bfr);
            }
            float* r0 = rg + (qb + lr) * FST + jn * 8 + 2 * lc;
            *(float2*)r0 = make_float2(c[0], c[1]);
            *(float2*)(r0 + 8 * FST) = make_float2(c[2], c[3]);
        }
        __syncwarp();
    };

    {
        stage64f(KPs, kp + ((size_t)(b * SEQ2 + SEQ - q0 - 64)) * HIDD + h * DH, HIDD, tid);
        asm volatile("cp.async.commit_group;");
        asm volatile("cp.async.wait_group 0;");
        __syncthreads();
        pp_tile((15 - qt) & 1);
    }

    const int ra = qb + lr, rb = ra + 8;
    const size_t mbase_a = ((size_t)b * SEQ + q0 + ra) * SEQ;
    const size_t mbase_b = mbase_a + (size_t)8 * SEQ;
    const float s0a = s0s[ra], s1a = s1s[ra];
    const float s0b = s0s[rb], s1b = s1s[rb];

    for (int kt = 0; kt < 16; kt++) {
        const int k0 = kt * 64;
        const int Tb = 16 + kt - qt;
        __syncthreads();
        stage64f(KCs, qkv + ((size_t)(b * SEQ + k0)) * H3 + 1024 + h * DH, H3, tid);
        stage64f(Vs,  qkv + ((size_t)(b * SEQ + k0)) * H3 + 2048 + h * DH, H3, tid);
        stage64f(KPs, kp + ((size_t)b * SEQ2 + (size_t)64 * Tb) * HIDD + h * DH, HIDD, tid);
        asm volatile("cp.async.commit_group;");
        asm volatile("cp.async.wait_group 0;");
        __syncthreads();

        pp_tile(Tb & 1);
        const int slotA = (Tb - 1) & 1, slotB = Tb & 1;

        float cs[8][4];
#pragma unroll
        for (int jn = 0; jn < 8; jn++) {
            float c[4] = {0.f, 0.f, 0.f, 0.f};
            const float* bp = KCs + (jn * 8 + lr) * FST;
#pragma unroll
            for (int s = 0; s < 8; s++) {
                uint32_t bfr[2];
                bfr[0] = __float_as_uint(bp[8 * s + lc]);
                bfr[1] = __float_as_uint(bp[8 * s + lc + 4]);
                mma_tf32(c, aC[s], bfr);
            }
            cs[jn][0] = c[0]; cs[jn][1] = c[1]; cs[jn][2] = c[2]; cs[jn][3] = c[3];
        }

        float mxa = -1e30f, mxb = -1e30f;
#pragma unroll
        for (int jn = 0; jn < 8; jn++) {
            const int kkp = jn * 8 + 2 * lc;
            float2 mva = *(const float2*)(mask + mbase_a + k0 + kkp);
            float2 mvb = *(const float2*)(mask + mbase_b + k0 + kkp);
            float sa0 = seg_at(segmat, mbase_a + k0 + kkp, mode)     ? s1a : s0a;
            float sa1 = seg_at(segmat, mbase_a + k0 + kkp + 1, mode) ? s1a : s0a;
            float sb0 = seg_at(segmat, mbase_b + k0 + kkp, mode)     ? s1b : s0b;
            float sb1 = seg_at(segmat, mbase_b + k0 + kkp + 1, mode) ? s1b : s0b;
            const int wa = kkp - ra + 64, wb = kkp - rb + 64;
            float ppa0 = ring[(wa < 64 ? slotA : slotB) * T64 + ra * FST + (wa & 63)];
            float ppa1 = ring[(wa + 1 < 64 ? slotA : slotB) * T64 + ra * FST + ((wa + 1) & 63)];
            float ppb0 = ring[(wb < 64 ? slotA : slotB) * T64 + rb * FST + (wb & 63)];
            float ppb1 = ring[(wb + 1 < 64 ? slotA : slotB) * T64 + rb * FST + ((wb + 1) & 63)];
            cs[jn][0] = (cs[jn][0] + ppa0 + sa0) * 0.125f + mva.x * (-1e9f);
            cs[jn][1] = (cs[jn][1] + ppa1 + sa1) * 0.125f + mva.y * (-1e9f);
            cs[jn][2] = (cs[jn][2] + ppb0 + sb0) * 0.125f + mvb.x * (-1e9f);
            cs[jn][3] = (cs[jn][3] + ppb1 + sb1) * 0.125f + mvb.y * (-1e9f);
            mxa = fmaxf(mxa, fmaxf(cs[jn][0], cs[jn][1]));
            mxb = fmaxf(mxb, fmaxf(cs[jn][2], cs[jn][3]));
        }
        __syncthreads();

        mxa = fmaxf(mxa, __shfl_xor_sync(0xffffffffu, mxa, 1));
        mxa = fmaxf(mxa, __shfl_xor_sync(0xffffffffu, mxa, 2));
        mxb = fmaxf(mxb, __shfl_xor_sync(0xffffffffu, mxb, 1));
        mxb = fmaxf(mxb, __shfl_xor_sync(0xffffffffu, mxb, 2));

        const float mna = fmaxf(m_a, mxa), mnb = fmaxf(m_b, mxb);
        const float alA = __expf(m_a - mna), alB = __expf(m_b - mnb);
        m_a = mna; m_b = mnb;

        float sa = 0.f, sbm = 0.f;
#pragma unroll
        for (int jn = 0; jn < 8; jn++) {
            float p0 = __expf(cs[jn][0] - m_a), p1 = __expf(cs[jn][1] - m_a);
            float p2 = __expf(cs[jn][2] - m_b), p3 = __expf(cs[jn][3] - m_b);
            sa += p0 + p1; sbm += p2 + p3;
            *(float2*)(Ps + ra * FST + jn * 8 + 2 * lc) =
                make_float2(f2tff(p0), f2tff(p1));
            *(float2*)(Ps + rb * FST + jn * 8 + 2 * lc) =
                make_float2(f2tff(p2), f2tff(p3));
            O[jn][0] *= alA; O[jn][1] *= alA; O[jn][2] *= alB; O[jn][3] *= alB;
        }
        sa  += __shfl_xor_sync(0xffffffffu, sa, 1);
        sa  += __shfl_xor_sync(0xffffffffu, sa, 2);
        sbm += __shfl_xor_sync(0xffffffffu, sbm, 1);
        sbm += __shfl_xor_sync(0xffffffffu, sbm, 2);
        l_a = l_a * alA + sa;
        l_b = l_b * alB + sbm;
        __syncwarp();

        uint32_t ap[8][4];
#pragma unroll
        for (int s = 0; s < 8; s++) {
            ap[s][0] = __float_as_uint(Ps[ra * FST + 8 * s + lc]);
            ap[s][1] = __float_as_uint(Ps[rb * FST + 8 * s + lc]);
            ap[s][2] = __float_as_uint(Ps[ra * FST + 8 * s + lc + 4]);
            ap[s][3] = __float_as_uint(Ps[rb * FST + 8 * s + lc + 4]);
        }
#pragma unroll
        for (int jn = 0; jn < 8; jn++) {
#pragma unroll
            for (int s = 0; s < 8; s++) {
                uint32_t bfr[2];
                bfr[0] = __float_as_uint(Vs[(8 * s + lc) * FST + jn * 8 + lr]);
                bfr[1] = __float_as_uint(Vs[(8 * s + lc + 4) * FST + jn * 8 + lr]);
                mma_tf32(O[jn], ap[s], bfr);
            }
        }
        __syncwarp();
    }

    // store converted (catt consumed only as GEMM A operand)
    const float ia = 1.f / l_a, ib = 1.f / l_b;
    float* o0 = out + ((size_t)(b * SEQ + q0 + ra)) * HIDD + h * DH;
    float* o1 = o0 + (size_t)8 * HIDD;
#pragma unroll
    for (int jn = 0; jn < 8; jn++) {
        *(float2*)(o0 + jn * 8 + 2 * lc) =
            make_float2(f2tff(O[jn][0] * ia), f2tff(O[jn][1] * ia));
        *(float2*)(o1 + jn * 8 + 2 * lc) =
            make_float2(f2tff(O[jn][2] * ib), f2tff(O[jn][3] * ib));
    }
}

// ---------------- small kernels ----------------
__global__ void zero_f(float* __restrict__ p, int n) {
    int i = blockIdx.x * 256 + threadIdx.x;
    if (i < n) p[i] = 0.f;
}

__global__ void pack_w(const float* __restrict__ wq, const float* __restrict__ wkc,
                       const float* __restrict__ wv, float* __restrict__ W)
{
    int i = blockIdx.x * 256 + threadIdx.x;
    int r = i >> 10, c = i & 1023;
    float* dst = W + (size_t)r * H3 + c;
    dst[0]    = f2tff(wq[i]);
    dst[1024] = f2tff(wkc[i]);
    dst[2048] = f2tff(wv[i]);
}

__global__ void add_bias2(const float* __restrict__ src, int ld,
                          const float* __restrict__ cb, const float* __restrict__ pb,
                          float* __restrict__ ocb, float* __restrict__ opb)
{
    const int row = blockIdx.x, t = threadIdx.x;
    const float* s = src + (size_t)row * ld;
    float* o1 = ocb + (size_t)row * HIDD;
    float* o2 = opb + (size_t)row * HIDD;
    for (int i = t; i < HIDD; i += 256) {
        float v = s[i];
        o1[i] = f2tff(v + cb[i]);
        o2[i] = f2tff(v + pb[i]);
    }
}

__global__ void scatter_q(const float* __restrict__ tmap, const float* __restrict__ qg,
                          float* __restrict__ qscat, int* __restrict__ idx)
{
    const int b = blockIdx.y, p = blockIdx.x, t = threadIdx.x;
    __shared__ int sidx;
    const float* row = tmap + ((size_t)b * PQ + p) * SEQ;
    for (int s = t; s < SEQ; s += 128)
        if (row[s] > 0.5f) sidx = s;
    __syncthreads();
    const int si = sidx;
    if (t == 0) idx[b * PQ + p] = si;
    const float* src = qg + ((size_t)b * PQ + p) * HIDD;
    float* dst = qscat + ((size_t)b * SEQ + si) * HIDD;
    for (int i = t; i < HIDD; i += 128) atomicAdd(&dst[i], src[i]);
}

__global__ void gather_q(const float* __restrict__ qscat, const int* __restrict__ idx,
                         float* __restrict__ qq)
{
    const int b = blockIdx.y, p = blockIdx.x, t = threadIdx.x;
    const int si = idx[b * PQ + p];
    const float* src = qscat + ((size_t)b * SEQ + si) * HIDD;
    float* dst = qq + ((size_t)b * PQ + p) * HIDD;
    for (int i = t; i < HIDD; i += 128) dst[i] = src[i];
}

// ---------------- query-stream softmax (stores tf32-converted weights) ----------------
__global__ __launch_bounds__(256) void softmax_kernel(
    float* __restrict__ cs, const float* __restrict__ pp,
    const float* __restrict__ qArr, const float* __restrict__ sb,
    const float* __restrict__ seg, const void* __restrict__ segmat,
    const float* __restrict__ mask, const int* __restrict__ qidx,
    int Mrows, long qBatchStride, int ldq)
{
    const int b = blockIdx.z, h = blockIdx.y, qo = blockIdx.x, t = threadIdx.x;
    const int qrow = qidx ? qidx[b * PQ + qo] : qo;
    const int z = b * NH + h;
    const int mode = g_segmode[0];

    float* csrow = cs + ((size_t)z * Mrows + qo) * SEQ;
    const float* pprow = pp + ((size_t)z * Mrows + qo) * SEQ2 + (SEQ - qrow);
    const float* mrow = mask + ((size_t)b * SEQ + qrow) * SEQ;
    const size_t segbase = ((size_t)b * SEQ + qrow) * SEQ;

    __shared__ float qsv[DH];
    __shared__ float s01[2];
    __shared__ float red[256];

    if (t < DH)
        qsv[t] = qArr[qBatchStride * b + (size_t)qo * ldq + h * DH + t] + sb[h * DH + t];
    __syncthreads();
    if (t < 64) {
        const int which = t >> 5, lx = t & 31;
        const float* sgp = seg + which * NH * DH + h * DH;
        float a = qsv[lx] * sgp[lx] + qsv[lx + 32] * sgp[lx + 32];
#pragma unroll
        for (int o = 16; o; o >>= 1) a += __shfl_xor_sync(0xffffffffu, a, o);
        if (lx == 0) s01[which] = a;
    }
    __syncthreads();
    const float s0 = s01[0], s1 = s01[1];

    float lg[4];
    float mx = -3.4e38f;
#pragma unroll
    for (int j = 0; j < 4; j++) {
        int k = t + j * 256;
        float sgv = seg_at(segmat, segbase + k, mode) ? s1 : s0;
        float v = (csrow[k] + pprow[k] + sgv) * 0.125f + mrow[k] * (-1e9f);
        lg[j] = v;
        mx = fmaxf(mx, v);
    }
    red[t] = mx; __syncthreads();
#pragma unroll
    for (int s2 = 128; s2; s2 >>= 1) {
        if (t < s2) red[t] = fmaxf(red[t], red[t + s2]);
        __syncthreads();
    }
    mx = red[0]; __syncthreads();

    float sum = 0.f;
#pragma unroll
    for (int j = 0; j < 4; j++) {
        float e = __expf(lg[j] - mx);
        lg[j] = e;
        sum += e;
    }
    red[t] = sum; __syncthreads();
#pragma unroll
    for (int s2 = 128; s2; s2 >>= 1) {
        if (t < s2) red[t] += red[t + s2];
        __syncthreads();
    }
    const float invZ = 1.f / red[0];
#pragma unroll
    for (int j = 0; j < 4; j++) csrow[t + j * 256] = f2tff(lg[j] * invZ);
}

// ---------------- launch ----------------
extern "C" void kernel_launch(void* const* d_in, const int* in_sizes, int n_in,
                              void* d_out, int out_size)
{
    const float* content = (const float*)d_in[0];
    const float* query   = (const float*)d_in[1];
    const float* pe      = (const float*)d_in[2];
    const void*  segmat  = d_in[3];
    const float* segenc  = (const float*)d_in[4];
    const float* segbias = (const float*)d_in[5];
    const float* cmask   = (const float*)d_in[6];
    const float* qmask   = (const float*)d_in[7];
    const float* tmap    = (const float*)d_in[8];
    const float* cbias   = (const float*)d_in[9];
    const float* pbias   = (const float*)d_in[10];
    const float* wq      = (const float*)d_in[11];
    const float* wkc     = (const float*)d_in[12];
    const float* wv      = (const float*)d_in[13];
    const float* wkp     = (const float*)d_in[14];
    const float* wo      = (const float*)d_in[15];
    float* out = (float*)d_out;

    float *qkv, *wpack, *kp, *qg, *qscat, *qq, *qqcb, *qqpb;
    float *csq, *ppq, *catt, *qatt;
    float *content_c, *pe_c, *query_c, *wo_c, *wkp_c;
    int* idx;
    cudaGetSymbolAddress((void**)&qkv,   g_qkv);
    cudaGetSymbolAddress((void**)&wpack, g_wpack);
    cudaGetSymbolAddress((void**)&kp,    g_kp);
    cudaGetSymbolAddress((void**)&qg,    g_qg);
    cudaGetSymbolAddress((void**)&qscat, g_qscat);
    cudaGetSymbolAddress((void**)&qq,    g_qq);
    cudaGetSymbolAddress((void**)&qqcb,  g_qqcb);
    cudaGetSymbolAddress((void**)&qqpb,  g_qqpb);
    cudaGetSymbolAddress((void**)&csq,   g_csq);
    cudaGetSymbolAddress((void**)&ppq,   g_ppq);
    cudaGetSymbolAddress((void**)&catt,  g_catt);
    cudaGetSymbolAddress((void**)&qatt,  g_qatt);
    cudaGetSymbolAddress((void**)&content_c, g_content_c);
    cudaGetSymbolAddress((void**)&pe_c,  g_pe_c);
    cudaGetSymbolAddress((void**)&query_c, g_query_c);
    cudaGetSymbolAddress((void**)&wo_c,  g_wo_c);
    cudaGetSymbolAddress((void**)&wkp_c, g_wkp_c);
    cudaGetSymbolAddress((void**)&idx,   g_idx);

    static bool attr_done = false;
    if (!attr_done) {
        cudaFuncSetAttribute(flash_content, cudaFuncAttributeMaxDynamicSharedMemorySize,
                             FL_SMEMF * sizeof(float));
        attr_done = true;
    }

    probe_segmat<<<1, 32>>>((const uint32_t*)segmat);
    zero_f<<<(BATCH * SEQ * HIDD + 255) / 256, 256>>>(qscat, BATCH * SEQ * HIDD);
    pack_w<<<4096, 256>>>(wq, wkc, wv, wpack);

    // input conversions to tf32 bits
    cvt_f<<<2048, 256>>>(content, content_c, BATCH * SEQ * HIDD / 4);
    cvt_f<<<4096, 256>>>(pe, pe_c, BATCH * SEQ2 * HIDD / 4);
    cvt_f<<<256, 256>>>(query, query_c, BATCH * PQ * HIDD / 4);
    cvt_f<<<1024, 256>>>(wo, wo_c, HIDD * HIDD / 4);
    cvt_f<<<1024, 256>>>(wkp, wkp_c, HIDD * HIDD / 4);

    const long SH = (long)SEQ * HIDD, S2H = (long)SEQ2 * HIDD, PH = (long)PQ * HIDD;
    const long SH3 = (long)SEQ * H3;
    const long PS = (long)PQ * SEQ, PS2 = (long)PQ * SEQ2;

    // projections: qkv epilogue converts kc|v columns; kp fully converted
    gemm128<false><<<dim3(24, 16, 1), 256>>>(content_c, wpack, qkv,
        2048, H3, HIDD, HIDD, H3, H3, 0,0,0,0,0,0, 1, 1024);
    gemm128<false><<<dim3(8, 32, 1), 256>>>(pe_c, wkp_c, kp,
        4096, HIDD, HIDD, HIDD, HIDD, HIDD, 0,0,0,0,0,0, 1, 0);
    gemm128<false><<<dim3(8, 2, 1), 256>>>(query_c, wpack, qg,
        256, HIDD, HIDD, HIDD, H3, HIDD, 0,0,0,0,0,0, 1, NOCVT);

    scatter_q<<<dim3(PQ, BATCH), 128>>>(tmap, qg, qscat, idx);
    gather_q<<<dim3(PQ, BATCH), 128>>>(qscat, idx, qq);
    add_bias2<<<BATCH * PQ, 256>>>(qq, HIDD, cbias, pbias, qqcb, qqpb);

    const float* kcp = qkv + 1024;
    const float* vp  = qkv + 2048;

    // content stream
    flash_content<<<dim3(SEQ / 64, NH, BATCH), 128, FL_SMEMF * sizeof(float)>>>(
        qkv, kp, cbias, pbias, segbias, segenc, segmat, cmask, catt);

    // query stream
    gemm128<true><<<dim3(8, 1, BATCH * NH), 256>>>(qqcb, kcp, csq,
        PQ, SEQ, DH, HIDD, H3, SEQ,  PH, DH, SH3, DH, (long)NH * PS, PS, NH, NOCVT);
    gemm128<true><<<dim3(16, 1, BATCH * NH), 256>>>(qqpb, kp, ppq,
        PQ, SEQ2, DH, HIDD, HIDD, SEQ2, PH, DH, S2H, DH, (long)NH * PS2, PS2, NH, NOCVT);
    softmax_kernel<<<dim3(PQ, NH, BATCH), 256>>>(
        csq, ppq, qq, segbias, segenc, segmat, qmask, idx, PQ, PH, HIDD);
    gemm_tf32<false><<<dim3(1, 1, BATCH * NH), 256>>>(csq, vp, qatt,
        PQ, DH, SEQ, SEQ, H3, HIDD, (long)NH * PS, PS, SH3, DH, PH, DH, NH, 0);

    // output projections (final out stays fp32)
    gemm128<false><<<dim3(8, 16, 1), 256>>>(catt, wo_c, out,
        2048, HIDD, HIDD, HIDD, HIDD, HIDD, 0,0,0,0,0,0, 1, NOCVT);
    gemm128<false><<<dim3(8, 2, 1), 256>>>(qatt, wo_c, out + (size_t)BATCH * SEQ * HIDD,
        256, HIDD, HIDD, HIDD, HIDD, HIDD, 0,0,0,0,0,0, 1, NOCVT);
}

// round 10
// speedup vs baseline: 1.2520x; 1.1553x over previous
#include <cuda_runtime.h>
#include <cstdint>
#include <cstddef>

#define BATCH 2
#define SEQ   1024
#define SEQ2  2048
#define PQ    128
#define HIDD  1024
#define NH    16
#define DH    64
#define H3    3072
#define NOCVT (1 << 30)

// ---------------- scratch ----------------
__device__ float g_qkv[BATCH * SEQ * H3];      // q (fp32) | kc (tf32) | v (tf32)
__device__ float g_wpack[HIDD * H3];           // tf32 bits
__device__ float g_kp[BATCH * SEQ2 * HIDD];    // tf32 bits
__device__ float g_qg[BATCH * PQ * HIDD];
__device__ float g_qscat[BATCH * SEQ * HIDD];
__device__ float g_qq[BATCH * PQ * HIDD];
__device__ float g_qqcb[BATCH * PQ * HIDD];
__device__ float g_qqpb[BATCH * PQ * HIDD];
__device__ float g_csq[(size_t)BATCH * NH * PQ * SEQ];
__device__ float g_ppq[(size_t)BATCH * NH * PQ * SEQ2];
__device__ float g_catt[BATCH * SEQ * HIDD];
__device__ float g_qatt[BATCH * PQ * HIDD];
__device__ float g_content_c[BATCH * SEQ * HIDD];
__device__ float g_pe_c[BATCH * SEQ2 * HIDD];
__device__ float g_query_c[BATCH * PQ * HIDD];
__device__ float g_wo_c[HIDD * HIDD];
__device__ float g_wkp_c[HIDD * HIDD];
__device__ int   g_idx[BATCH * PQ];
__device__ int   g_segmode[1];

// ---------------- probe ----------------
__global__ void probe_segmat(const uint32_t* __restrict__ p) {
    if (threadIdx.x == 0 && blockIdx.x == 0) {
        int mode = 1;
        for (int i = 0; i < 4096; i++) {
            uint32_t w = p[i];
            if (w == 0x3F800000u) { mode = 2; break; }
            if (w > 1u)           { mode = 0; break; }
        }
        g_segmode[0] = mode;
    }
}

__device__ __forceinline__ bool seg_at(const void* p, size_t i, int mode) {
    if (mode == 0) return ((const uint8_t*)p)[i] != 0;
    if (mode == 1) return ((const int*)p)[i] != 0;
    return ((const float*)p)[i] > 0.5f;
}

// ---------------- tf32 helpers ----------------
__device__ __forceinline__ uint32_t f2tf(float f) {
    uint32_t u;
    asm("cvt.rna.tf32.f32 %0, %1;" : "=r"(u) : "f"(f));
    return u;
}
__device__ __forceinline__ float f2tff(float f) { return __uint_as_float(f2tf(f)); }

__device__ __forceinline__ void mma_tf32(float* c, const uint32_t* a, const uint32_t* b) {
    asm volatile(
        "mma.sync.aligned.m16n8k8.row.col.f32.tf32.tf32.f32 "
        "{%0,%1,%2,%3}, {%4,%5,%6,%7}, {%8,%9}, {%0,%1,%2,%3};"
        : "+f"(c[0]), "+f"(c[1]), "+f"(c[2]), "+f"(c[3])
        : "r"(a[0]), "r"(a[1]), "r"(a[2]), "r"(a[3]), "r"(b[0]), "r"(b[1]));
}

__device__ __forceinline__ void cp16(uint32_t s, const float* g) {
    asm volatile("cp.async.ca.shared.global [%0], [%1], 16;" :: "r"(s), "l"(g));
}

// ---------------- fused prep: all input cvts + pack_w + zero(qscat) ----------------
#define N4_CONT  524288
#define N4_PE    1048576
#define N4_QRY   65536
#define N4_WO    262144
#define N4_WKP   262144
#define N4_PACK  262144
#define N4_ZERO  524288
#define PREP_BLOCKS ((N4_CONT+N4_PE+N4_QRY+N4_WO+N4_WKP+N4_PACK+N4_ZERO)/256)

__global__ void prep_all(
    const float* __restrict__ content, const float* __restrict__ pe,
    const float* __restrict__ query, const float* __restrict__ wo,
    const float* __restrict__ wkp, const float* __restrict__ wq,
    const float* __restrict__ wkc, const float* __restrict__ wv,
    float* __restrict__ content_c, float* __restrict__ pe_c,
    float* __restrict__ query_c, float* __restrict__ wo_c,
    float* __restrict__ wkp_c, float* __restrict__ wpack,
    float* __restrict__ qscat)
{
    long i = (long)blockIdx.x * 256 + threadIdx.x;
    auto cv4 = [](const float* s, float* d, long j) {
        float4 v = ((const float4*)s)[j];
        v.x = f2tff(v.x); v.y = f2tff(v.y); v.z = f2tff(v.z); v.w = f2tff(v.w);
        ((float4*)d)[j] = v;
    };
    if (i < N4_CONT) { cv4(content, content_c, i); return; }
    i -= N4_CONT;
    if (i < N4_PE)   { cv4(pe, pe_c, i); return; }
    i -= N4_PE;
    if (i < N4_QRY)  { cv4(query, query_c, i); return; }
    i -= N4_QRY;
    if (i < N4_WO)   { cv4(wo, wo_c, i); return; }
    i -= N4_WO;
    if (i < N4_WKP)  { cv4(wkp, wkp_c, i); return; }
    i -= N4_WKP;
    if (i < N4_PACK) {
        long e = i * 4;
        int r = (int)(e >> 10), c = (int)(e & 1023);
        float4 a = ((const float4*)wq)[i];
        float4 b = ((const float4*)wkc)[i];
        float4 v = ((const float4*)wv)[i];
        a.x = f2tff(a.x); a.y = f2tff(a.y); a.z = f2tff(a.z); a.w = f2tff(a.w);
        b.x = f2tff(b.x); b.y = f2tff(b.y); b.z = f2tff(b.z); b.w = f2tff(b.w);
        v.x = f2tff(v.x); v.y = f2tff(v.y); v.z = f2tff(v.z); v.w = f2tff(v.w);
        float* dst = wpack + (size_t)r * H3 + c;
        *(float4*)(dst)        = a;
        *(float4*)(dst + 1024) = b;
        *(float4*)(dst + 2048) = v;
        return;
    }
    i -= N4_PACK;
    ((float4*)qscat)[i] = make_float4(0.f, 0.f, 0.f, 0.f);
}

// ---------------- multi-problem tf32 GEMM 128x128 ----------------
#define AST  20
#define BSTT 20
#define B128 136

struct GD {
    const float* A; const float* B; float* C;
    int gx, gy;                 // tile grid (x = N/128, y = M/128)
    int lda, ldb, ldc;
    long aOut, aIn, bOut, bIn, cOut, cIn;
    int zInner;
    int KT;                     // K / 16
    int cvtCol;
};

template<bool TB>
__global__ __launch_bounds__(256) void gemm128m(GD d0, GD d1, GD d2, int n0, int n01)
{
    __shared__ float As[2][128 * AST];
    __shared__ float Bs[2][TB ? 128 * BSTT : 16 * B128];

    GD d;
    int r = blockIdx.x;
    if (r < n0)       { d = d0; }
    else if (r < n01) { d = d1; r -= n0; }
    else              { d = d2; r -= n01; }

    const int tiles = d.gx * d.gy;
    const int z  = r / tiles;
    const int rr = r % tiles;
    const int by = rr / d.gx, bx = rr % d.gx;
    const int zo = z / d.zInner, zi = z % d.zInner;

    const float* Ap = d.A + zo * d.aOut + zi * d.aIn;
    const float* Bp = d.B + zo * d.bOut + zi * d.bIn;
    float*       Cp = d.C + zo * d.cOut + zi * d.cIn;
    const int m0 = by * 128, n0px = bx * 128;
    const int lda = d.lda, ldb = d.ldb, ldc = d.ldc;

    const int tid = threadIdx.x;
    const int wid = tid >> 5, lane = tid & 31;
    const int wm = (wid & 3) * 32, wn = (wid >> 2) * 64;
    const int lr = lane >> 2, lc = lane & 3;

    uint32_t aSm[2], bSm[2];
    aSm[0] = (uint32_t)__cvta_generic_to_shared(&As[0][0]);
    aSm[1] = (uint32_t)__cvta_generic_to_shared(&As[1][0]);
    bSm[0] = (uint32_t)__cvta_generic_to_shared(&Bs[0][0]);
    bSm[1] = (uint32_t)__cvta_generic_to_shared(&Bs[1][0]);

    const int ar = tid >> 2, ac = (tid & 3) * 4;

    auto stage = [&](int kt) {
        const int k0 = kt * 16, buf = kt & 1;
        const float* ga = Ap + (size_t)(m0 + ar) * lda + k0 + ac;
        cp16(aSm[buf] + (ar * AST + ac) * 4, ga);
        cp16(aSm[buf] + ((ar + 64) * AST + ac) * 4, ga + (size_t)64 * lda);
        if (TB) {
            const int rw = tid >> 1, c = (tid & 1) * 8;
            const float* gb = Bp + (size_t)(n0px + rw) * ldb + k0 + c;
            cp16(bSm[buf] + (rw * BSTT + c) * 4, gb);
            cp16(bSm[buf] + (rw * BSTT + c + 4) * 4, gb + 4);
        } else {
            const int br = tid >> 4, bc = (tid & 15) * 4;
            const float* gb = Bp + (size_t)(k0 + br) * ldb + n0px + bc;
            cp16(bSm[buf] + (br * B128 + bc) * 4, gb);
            cp16(bSm[buf] + (br * B128 + bc + 64) * 4, gb + 64);
        }
    };

    float acc[2][8][4] = {};
    const int KT = d.KT;

    stage(0);
    asm volatile("cp.async.commit_group;");

    for (int kt = 0; kt < KT; kt++) {
        if (kt + 1 < KT) {
            stage(kt + 1);
            asm volatile("cp.async.commit_group;");
            asm volatile("cp.async.wait_group 1;");
        } else {
            asm volatile("cp.async.wait_group 0;");
        }
        __syncthreads();

        const float* as = As[kt & 1];
        const float* bs = Bs[kt & 1];
#pragma unroll
        for (int kk = 0; kk < 16; kk += 8) {
            uint32_t af[2][4], bf[8][2];
#pragma unroll
            for (int im = 0; im < 2; im++) {
                const int base = (wm + im * 16 + lr) * AST + kk + lc;
                af[im][0] = __float_as_uint(as[base]);
                af[im][1] = __float_as_uint(as[base + 8 * AST]);
                af[im][2] = __float_as_uint(as[base + 4]);
                af[im][3] = __float_as_uint(as[base + 8 * AST + 4]);
            }
#pragma unroll
            for (int jn = 0; jn < 8; jn++) {
                if (TB) {
                    const int bb = (wn + jn * 8 + lr) * BSTT + kk + lc;
                    bf[jn][0] = __float_as_uint(bs[bb]);
                    bf[jn][1] = __float_as_uint(bs[bb + 4]);
                } else {
                    const int bb = (kk + lc) * B128 + wn + jn * 8 + lr;
                    bf[jn][0] = __float_as_uint(bs[bb]);
                    bf[jn][1] = __float_as_uint(bs[bb + 4 * B128]);
                }
            }
#pragma unroll
            for (int im = 0; im < 2; im++)
#pragma unroll
                for (int jn = 0; jn < 8; jn++)
                    mma_tf32(acc[im][jn], af[im], bf[jn]);
        }
        __syncthreads();
    }

#pragma unroll
    for (int im = 0; im < 2; im++) {
#pragma unroll
        for (int jn = 0; jn < 8; jn++) {
            const int row = m0 + wm + im * 16 + lr;
            const int col = n0px + wn + jn * 8 + 2 * lc;
            float v0 = acc[im][jn][0], v1 = acc[im][jn][1];
            float v2 = acc[im][jn][2], v3 = acc[im][jn][3];
            if (col >= d.cvtCol) {
                v0 = f2tff(v0); v1 = f2tff(v1); v2 = f2tff(v2); v3 = f2tff(v3);
            }
            *(float2*)(Cp + (size_t)row * ldc + col) = make_float2(v0, v1);
            *(float2*)(Cp + (size_t)(row + 8) * ldc + col) = make_float2(v2, v3);
        }
    }
}

// ---------------- tf32 GEMM 128x64 (AV only) ----------------
#define BSTN 72

template<bool TB>
__global__ __launch_bounds__(256) void gemm_tf32(
    const float* __restrict__ A, const float* __restrict__ B, float* __restrict__ C,
    int M, int N, int K, int lda, int ldb, int ldc,
    long aOut, long aIn, long bOut, long bIn, long cOut, long cIn, int zInner, int cvtCol)
{
    __shared__ float As[2][128 * AST];
    __shared__ float Bs[2][1280];

    const int tid = threadIdx.x;
    const int zo = blockIdx.z / zInner, zi = blockIdx.z % zInner;
    const float* Ap = A + zo * aOut + zi * aIn;
    const float* Bp = B + zo * bOut + zi * bIn;
    float*       Cp = C + zo * cOut + zi * cIn;
    const int m0 = blockIdx.y * 128, n0 = blockIdx.x * 64;

    const int wid = tid >> 5, lane = tid & 31;
    const int wm = (wid & 3) * 32, wn = (wid >> 2) * 32;
    const int lr = lane >> 2, lc = lane & 3;

    uint32_t aSm[2], bSm[2];
    aSm[0] = (uint32_t)__cvta_generic_to_shared(&As[0][0]);
    aSm[1] = (uint32_t)__cvta_generic_to_shared(&As[1][0]);
    bSm[0] = (uint32_t)__cvta_generic_to_shared(&Bs[0][0]);
    bSm[1] = (uint32_t)__cvta_generic_to_shared(&Bs[1][0]);

    const int ar = tid >> 2, ac = (tid & 3) * 4;

    auto stage = [&](int kt) {
        const int k0 = kt * 16, buf = kt & 1;
        const float* ga = Ap + (size_t)(m0 + ar) * lda + k0 + ac;
        cp16(aSm[buf] + (ar * AST + ac) * 4, ga);
        cp16(aSm[buf] + ((ar + 64) * AST + ac) * 4, ga + (size_t)64 * lda);
        if (TB) {
            cp16(bSm[buf] + (ar * BSTT + ac) * 4,
                 Bp + (size_t)(n0 + ar) * ldb + k0 + ac);
        } else {
            const int br = tid >> 4, bc = (tid & 15) * 4;
            cp16(bSm[buf] + (br * BSTN + bc) * 4,
                 Bp + (size_t)(k0 + br) * ldb + n0 + bc);
        }
    };

    float acc[2][4][4] = {};

    stage(0);
    asm volatile("cp.async.commit_group;");
    const int KT = K >> 4;

    for (int kt = 0; kt < KT; kt++) {
        if (kt + 1 < KT) {
            stage(kt + 1);
            asm volatile("cp.async.commit_group;");
            asm volatile("cp.async.wait_group 1;");
        } else {
            asm volatile("cp.async.wait_group 0;");
        }
        __syncthreads();

        const float* as = As[kt & 1];
        const float* bs = Bs[kt & 1];
#pragma unroll
        for (int kk = 0; kk < 16; kk += 8) {
            uint32_t af[2][4], bf[4][2];
#pragma unroll
            for (int im = 0; im < 2; im++) {
                const int base = (wm + im * 16 + lr) * AST + kk + lc;
                af[im][0] = __float_as_uint(as[base]);
                af[im][1] = __float_as_uint(as[base + 8 * AST]);
                af[im][2] = __float_as_uint(as[base + 4]);
                af[im][3] = __float_as_uint(as[base + 8 * AST + 4]);
            }
#pragma unroll
            for (int jn = 0; jn < 4; jn++) {
                if (TB) {
                    const int bb = (wn + jn * 8 + lr) * BSTT + kk + lc;
                    bf[jn][0] = __float_as_uint(bs[bb]);
                    bf[jn][1] = __float_as_uint(bs[bb + 4]);
                } else {
                    const int bb = (kk + lc) * BSTN + wn + jn * 8 + lr;
                    bf[jn][0] = __float_as_uint(bs[bb]);
                    bf[jn][1] = __float_as_uint(bs[bb + 4 * BSTN]);
                }
            }
#pragma unroll
            for (int im = 0; im < 2; im++)
#pragma unroll
                for (int jn = 0; jn < 4; jn++)
                    mma_tf32(acc[im][jn], af[im], bf[jn]);
        }
        __syncthreads();
    }

#pragma unroll
    for (int im = 0; im < 2; im++) {
#pragma unroll
        for (int jn = 0; jn < 4; jn++) {
            const int row = m0 + wm + im * 16 + lr;
            const int col = n0 + wn + jn * 8 + 2 * lc;
            float v0 = acc[im][jn][0], v1 = acc[im][jn][1];
            float v2 = acc[im][jn][2], v3 = acc[im][jn][3];
            if (col >= cvtCol) {
                v0 = f2tff(v0); v1 = f2tff(v1); v2 = f2tff(v2); v3 = f2tff(v3);
            }
            *(float2*)(Cp + (size_t)row * ldc + col) = make_float2(v0, v1);
            *(float2*)(Cp + (size_t)(row + 8) * ldc + col) = make_float2(v2, v3);
        }
    }
}

// ---------------- flash-fused content attention (q64, 128 thr) ----------------
#define FST 68
#define T64 (64 * FST)
#define FL_SMEMF (5 * T64 + 128)

__device__ __forceinline__ void stage64f(float* dst, const float* src, long rstride, int tid) {
    uint32_t s = (uint32_t)__cvta_generic_to_shared(dst);
#pragma unroll
    for (int i = 0; i < 8; i++) {
        int id = tid + i * 128;
        int j = id >> 4, d4 = (id & 15) * 4;
        cp16(s + (uint32_t)(j * FST + d4) * 4, src + (size_t)j * rstride + d4);
    }
}

__global__ __launch_bounds__(128, 2) void flash_content(
    const float* __restrict__ qkv, const float* __restrict__ kp,
    const float* __restrict__ cb, const float* __restrict__ pb,
    const float* __restrict__ sb, const float* __restrict__ seg,
    const void* __restrict__ segmat, const float* __restrict__ mask,
    float* __restrict__ out)
{
    extern __shared__ float sm[];
    float* KCs  = sm;
    float* KPs  = sm + T64;
    float* Vs   = sm + 2 * T64;
    float* ring = sm + 3 * T64;
    float* s0s  = sm + 5 * T64;
    float* s1s  = s0s + 64;
    float* Ps   = KPs;

    const int b = blockIdx.z, h = blockIdx.y, qt = blockIdx.x, q0 = qt * 64;
    const int tid = threadIdx.x, w = tid >> 5, l = tid & 31;
    const int lr = l >> 2, lc = l & 3;
    const int qb = w * 16;
    const int mode = g_segmode[0];

    uint32_t aC[8][4], aP[8][4];
    {
        const float* r0 = qkv + ((size_t)(b * SEQ + q0 + qb + lr)) * H3 + h * DH;
        const float* r1 = r0 + (size_t)8 * H3;
#pragma unroll
        for (int s = 0; s < 8; s++) {
            const int d0 = 8 * s + lc, d1 = d0 + 4;
            const float c0v = cb[h * DH + d0], c1v = cb[h * DH + d1];
            const float p0v = pb[h * DH + d0], p1v = pb[h * DH + d1];
            float v00 = r0[d0], v01 = r0[d1], v10 = r1[d0], v11 = r1[d1];
            aC[s][0] = f2tf(v00 + c0v); aC[s][1] = f2tf(v10 + c0v);
            aC[s][2] = f2tf(v01 + c1v); aC[s][3] = f2tf(v11 + c1v);
            aP[s][0] = f2tf(v00 + p0v); aP[s][1] = f2tf(v10 + p0v);
            aP[s][2] = f2tf(v01 + p1v); aP[s][3] = f2tf(v11 + p1v);
        }
    }
    if (tid < 64) {
        const float* qr = qkv + ((size_t)(b * SEQ + q0 + tid)) * H3 + h * DH;
        float s0 = 0.f, s1 = 0.f;
        for (int d = 0; d < DH; d++) {
            float qs = qr[d] + sb[h * DH + d];
            s0 += qs * seg[h * DH + d];
            s1 += qs * seg[NH * DH + h * DH + d];
        }
        s0s[tid] = s0; s1s[tid] = s1;
    }

    float O[8][4] = {};
    float m_a = -1e30f, m_b = -1e30f, l_a = 0.f, l_b = 0.f;

    auto pp_tile = [&](int slot) {
        float* rg = ring + slot * T64;
#pragma unroll
        for (int jn = 0; jn < 8; jn++) {
            float c[4] = {0.f, 0.f, 0.f, 0.f};
            const float* bp = KPs + (jn * 8 + lr) * FST;
#pragma unroll
            for (int s = 0; s < 8; s++) {
                uint32_t bfr[2];
                bfr[0] = __float_as_uint(bp[8 * s + lc]);
                bfr[1] = __float_as_uint(bp[8 * s + lc + 4]);
                mma_tf32(c, aP[s], bfr);
            }
            float* r0 = rg + (qb + lr) * FST + jn * 8 + 2 * lc;
            *(float2*)r0 = make_float2(c[0], c[1]);
            *(float2*)(r0 + 8 * FST) = make_float2(c[2], c[3]);
        }
        __syncwarp();
    };

    {
        stage64f(KPs, kp + ((size_t)(b * SEQ2 + SEQ - q0 - 64)) * HIDD + h * DH, HIDD, tid);
        asm volatile("cp.async.commit_group;");
        asm volatile("cp.async.wait_group 0;");
        __syncthreads();
        pp_tile((15 - qt) & 1);
    }

    const int ra = qb + lr, rb = ra + 8;
    const size_t mbase_a = ((size_t)b * SEQ + q0 + ra) * SEQ;
    const size_t mbase_b = mbase_a + (size_t)8 * SEQ;
    const float s0a = s0s[ra], s1a = s1s[ra];
    const float s0b = s0s[rb], s1b = s1s[rb];

    for (int kt = 0; kt < 16; kt++) {
        const int k0 = kt * 64;
        const int Tb = 16 + kt - qt;
        __syncthreads();
        stage64f(KCs, qkv + ((size_t)(b * SEQ + k0)) * H3 + 1024 + h * DH, H3, tid);
        stage64f(Vs,  qkv + ((size_t)(b * SEQ + k0)) * H3 + 2048 + h * DH, H3, tid);
        stage64f(KPs, kp + ((size_t)b * SEQ2 + (size_t)64 * Tb) * HIDD + h * DH, HIDD, tid);
        asm volatile("cp.async.commit_group;");
        asm volatile("cp.async.wait_group 0;");
        __syncthreads();

        pp_tile(Tb & 1);
        const int slotA = (Tb - 1) & 1, slotB = Tb & 1;

        float cs[8][4];
#pragma unroll
        for (int jn = 0; jn < 8; jn++) {
            float c[4] = {0.f, 0.f, 0.f, 0.f};
            const float* bp = KCs + (jn * 8 + lr) * FST;
#pragma unroll
            for (int s = 0; s < 8; s++) {
                uint32_t bfr[2];
                bfr[0] = __float_as_uint(bp[8 * s + lc]);
                bfr[1] = __float_as_uint(bp[8 * s + lc + 4]);
                mma_tf32(c, aC[s], bfr);
            }
            cs[jn][0] = c[0]; cs[jn][1] = c[1]; cs[jn][2] = c[2]; cs[jn][3] = c[3];
        }

        float mxa = -1e30f, mxb = -1e30f;
#pragma unroll
        for (int jn = 0; jn < 8; jn++) {
            const int kkp = jn * 8 + 2 * lc;
            float2 mva = *(const float2*)(mask + mbase_a + k0 + kkp);
            float2 mvb = *(const float2*)(mask + mbase_b + k0 + kkp);
            float sa0 = seg_at(segmat, mbase_a + k0 + kkp, mode)     ? s1a : s0a;
            float sa1 = seg_at(segmat, mbase_a + k0 + kkp + 1, mode) ? s1a : s0a;
            float sb0 = seg_at(segmat, mbase_b + k0 + kkp, mode)     ? s1b : s0b;
            float sb1 = seg_at(segmat, mbase_b + k0 + kkp + 1, mode) ? s1b : s0b;
            const int wa = kkp - ra + 64, wb = kkp - rb + 64;
            float ppa0 = ring[(wa < 64 ? slotA : slotB) * T64 + ra * FST + (wa & 63)];
            float ppa1 = ring[(wa + 1 < 64 ? slotA : slotB) * T64 + ra * FST + ((wa + 1) & 63)];
            float ppb0 = ring[(wb < 64 ? slotA : slotB) * T64 + rb * FST + (wb & 63)];
            float ppb1 = ring[(wb + 1 < 64 ? slotA : slotB) * T64 + rb * FST + ((wb + 1) & 63)];
            cs[jn][0] = (cs[jn][0] + ppa0 + sa0) * 0.125f + mva.x * (-1e9f);
            cs[jn][1] = (cs[jn][1] + ppa1 + sa1) * 0.125f + mva.y * (-1e9f);
            cs[jn][2] = (cs[jn][2] + ppb0 + sb0) * 0.125f + mvb.x * (-1e9f);
            cs[jn][3] = (cs[jn][3] + ppb1 + sb1) * 0.125f + mvb.y * (-1e9f);
            mxa = fmaxf(mxa, fmaxf(cs[jn][0], cs[jn][1]));
            mxb = fmaxf(mxb, fmaxf(cs[jn][2], cs[jn][3]));
        }
        __syncthreads();

        mxa = fmaxf(mxa, __shfl_xor_sync(0xffffffffu, mxa, 1));
        mxa = fmaxf(mxa, __shfl_xor_sync(0xffffffffu, mxa, 2));
        mxb = fmaxf(mxb, __shfl_xor_sync(0xffffffffu, mxb, 1));
        mxb = fmaxf(mxb, __shfl_xor_sync(0xffffffffu, mxb, 2));

        const float mna = fmaxf(m_a, mxa), mnb = fmaxf(m_b, mxb);
        const float alA = __expf(m_a - mna), alB = __expf(m_b - mnb);
        m_a = mna; m_b = mnb;

        float sa = 0.f, sbm = 0.f;
#pragma unroll
        for (int jn = 0; jn < 8; jn++) {
            float p0 = __expf(cs[jn][0] - m_a), p1 = __expf(cs[jn][1] - m_a);
            float p2 = __expf(cs[jn][2] - m_b), p3 = __expf(cs[jn][3] - m_b);
            sa += p0 + p1; sbm += p2 + p3;
            *(float2*)(Ps + ra * FST + jn * 8 + 2 * lc) =
                make_float2(f2tff(p0), f2tff(p1));
            *(float2*)(Ps + rb * FST + jn * 8 + 2 * lc) =
                make_float2(f2tff(p2), f2tff(p3));
            O[jn][0] *= alA; O[jn][1] *= alA; O[jn][2] *= alB; O[jn][3] *= alB;
        }
        sa  += __shfl_xor_sync(0xffffffffu, sa, 1);
        sa  += __shfl_xor_sync(0xffffffffu, sa, 2);
        sbm += __shfl_xor_sync(0xffffffffu, sbm, 1);
        sbm += __shfl_xor_sync(0xffffffffu, sbm, 2);
        l_a = l_a * alA + sa;
        l_b = l_b * alB + sbm;
        __syncwarp();

        uint32_t ap[8][4];
#pragma unroll
        for (int s = 0; s < 8; s++) {
            ap[s][0] = __float_as_uint(Ps[ra * FST + 8 * s + lc]);
            ap[s][1] = __float_as_uint(Ps[rb * FST + 8 * s + lc]);
            ap[s][2] = __float_as_uint(Ps[ra * FST + 8 * s + lc + 4]);
            ap[s][3] = __float_as_uint(Ps[rb * FST + 8 * s + lc + 4]);
        }
#pragma unroll
        for (int jn = 0; jn < 8; jn++) {
#pragma unroll
            for (int s = 0; s < 8; s++) {
                uint32_t bfr[2];
                bfr[0] = __float_as_uint(Vs[(8 * s + lc) * FST + jn * 8 + lr]);
                bfr[1] = __float_as_uint(Vs[(8 * s + lc + 4) * FST + jn * 8 + lr]);
                mma_tf32(O[jn], ap[s], bfr);
            }
        }
        __syncwarp();
    }

    const float ia = 1.f / l_a, ib = 1.f / l_b;
    float* o0 = out + ((size_t)(b * SEQ + q0 + ra)) * HIDD + h * DH;
    float* o1 = o0 + (size_t)8 * HIDD;
#pragma unroll
    for (int jn = 0; jn < 8; jn++) {
        *(float2*)(o0 + jn * 8 + 2 * lc) =
            make_float2(f2tff(O[jn][0] * ia), f2tff(O[jn][1] * ia));
        *(float2*)(o1 + jn * 8 + 2 * lc) =
            make_float2(f2tff(O[jn][2] * ib), f2tff(O[jn][3] * ib));
    }
}

// ---------------- small kernels ----------------
__global__ void scatter_q(const float* __restrict__ tmap, const float* __restrict__ qg,
                          float* __restrict__ qscat, int* __restrict__ idx)
{
    const int b = blockIdx.y, p = blockIdx.x, t = threadIdx.x;
    __shared__ int sidx;
    const float* row = tmap + ((size_t)b * PQ + p) * SEQ;
    for (int s = t; s < SEQ; s += 128)
        if (row[s] > 0.5f) sidx = s;
    __syncthreads();
    const int si = sidx;
    if (t == 0) idx[b * PQ + p] = si;
    const float* src = qg + ((size_t)b * PQ + p) * HIDD;
    float* dst = qscat + ((size_t)b * SEQ + si) * HIDD;
    for (int i = t; i < HIDD; i += 128) atomicAdd(&dst[i], src[i]);
}

__global__ void gather_bias(const float* __restrict__ qscat, const int* __restrict__ idx,
                            const float* __restrict__ cb, const float* __restrict__ pb,
                            float* __restrict__ qq, float* __restrict__ ocb,
                            float* __restrict__ opb)
{
    const int b = blockIdx.y, p = blockIdx.x, t = threadIdx.x;
    const int si = idx[b * PQ + p];
    const float* src = qscat + ((size_t)b * SEQ + si) * HIDD;
    const size_t o = (size_t)(b * PQ + p) * HIDD;
    for (int i = t; i < HIDD; i += 128) {
        float v = src[i];
        qq[o + i]  = v;
        ocb[o + i] = f2tff(v + cb[i]);
        opb[o + i] = f2tff(v + pb[i]);
    }
}

// ---------------- query-stream softmax ----------------
__global__ __launch_bounds__(256) void softmax_kernel(
    float* __restrict__ cs, const float* __restrict__ pp,
    const float* __restrict__ qArr, const float* __restrict__ sb,
    const float* __restrict__ seg, const void* __restrict__ segmat,
    const float* __restrict__ mask, const int* __restrict__ qidx,
    int Mrows, long qBatchStride, int ldq)
{
    const int b = blockIdx.z, h = blockIdx.y, qo = blockIdx.x, t = threadIdx.x;
    const int qrow = qidx ? qidx[b * PQ + qo] : qo;
    const int z = b * NH + h;
    const int mode = g_segmode[0];

    float* csrow = cs + ((size_t)z * Mrows + qo) * SEQ;
    const float* pprow = pp + ((size_t)z * Mrows + qo) * SEQ2 + (SEQ - qrow);
    const float* mrow = mask + ((size_t)b * SEQ + qrow) * SEQ;
    const size_t segbase = ((size_t)b * SEQ + qrow) * SEQ;

    __shared__ float qsv[DH];
    __shared__ float s01[2];
    __shared__ float red[256];

    if (t < DH)
        qsv[t] = qArr[qBatchStride * b + (size_t)qo * ldq + h * DH + t] + sb[h * DH + t];
    __syncthreads();
    if (t < 64) {
        const int which = t >> 5, lx = t & 31;
        const float* sgp = seg + which * NH * DH + h * DH;
        float a = qsv[lx] * sgp[lx] + qsv[lx + 32] * sgp[lx + 32];
#pragma unroll
        for (int o = 16; o; o >>= 1) a += __shfl_xor_sync(0xffffffffu, a, o);
        if (lx == 0) s01[which] = a;
    }
    __syncthreads();
    const float s0 = s01[0], s1 = s01[1];

    float lg[4];
    float mx = -3.4e38f;
#pragma unroll
    for (int j = 0; j < 4; j++) {
        int k = t + j * 256;
        float sgv = seg_at(segmat, segbase + k, mode) ? s1 : s0;
        float v = (csrow[k] + pprow[k] + sgv) * 0.125f + mrow[k] * (-1e9f);
        lg[j] = v;
        mx = fmaxf(mx, v);
    }
    red[t] = mx; __syncthreads();
#pragma unroll
    for (int s2 = 128; s2; s2 >>= 1) {
        if (t < s2) red[t] = fmaxf(red[t], red[t + s2]);
        __syncthreads();
    }
    mx = red[0]; __syncthreads();

    float sum = 0.f;
#pragma unroll
    for (int j = 0; j < 4; j++) {
        float e = __expf(lg[j] - mx);
        lg[j] = e;
        sum += e;
    }
    red[t] = sum; __syncthreads();
#pragma unroll
    for (int s2 = 128; s2; s2 >>= 1) {
        if (t < s2) red[t] += red[t + s2];
        __syncthreads();
    }
    const float invZ = 1.f / red[0];
#pragma unroll
    for (int j = 0; j < 4; j++) csrow[t + j * 256] = f2tff(lg[j] * invZ);
}

// ---------------- launch (single stream, fused multi-GEMM) ----------------
extern "C" void kernel_launch(void* const* d_in, const int* in_sizes, int n_in,
                              void* d_out, int out_size)
{
    const float* content = (const float*)d_in[0];
    const float* query   = (const float*)d_in[1];
    const float* pe      = (const float*)d_in[2];
    const void*  segmat  = d_in[3];
    const float* segenc  = (const float*)d_in[4];
    const float* segbias = (const float*)d_in[5];
    const float* cmask   = (const float*)d_in[6];
    const float* qmask   = (const float*)d_in[7];
    const float* tmap    = (const float*)d_in[8];
    const float* cbias   = (const float*)d_in[9];
    const float* pbias   = (const float*)d_in[10];
    const float* wq      = (const float*)d_in[11];
    const float* wkc     = (const float*)d_in[12];
    const float* wv      = (const float*)d_in[13];
    const float* wkp     = (const float*)d_in[14];
    const float* wo      = (const float*)d_in[15];
    float* out = (float*)d_out;

    float *qkv, *wpack, *kp, *qg, *qscat, *qq, *qqcb, *qqpb;
    float *csq, *ppq, *catt, *qatt;
    float *content_c, *pe_c, *query_c, *wo_c, *wkp_c;
    int* idx;
    cudaGetSymbolAddress((void**)&qkv,   g_qkv);
    cudaGetSymbolAddress((void**)&wpack, g_wpack);
    cudaGetSymbolAddress((void**)&kp,    g_kp);
    cudaGetSymbolAddress((void**)&qg,    g_qg);
    cudaGetSymbolAddress((void**)&qscat, g_qscat);
    cudaGetSymbolAddress((void**)&qq,    g_qq);
    cudaGetSymbolAddress((void**)&qqcb,  g_qqcb);
    cudaGetSymbolAddress((void**)&qqpb,  g_qqpb);
    cudaGetSymbolAddress((void**)&csq,   g_csq);
    cudaGetSymbolAddress((void**)&ppq,   g_ppq);
    cudaGetSymbolAddress((void**)&catt,  g_catt);
    cudaGetSymbolAddress((void**)&qatt,  g_qatt);
    cudaGetSymbolAddress((void**)&content_c, g_content_c);
    cudaGetSymbolAddress((void**)&pe_c,  g_pe_c);
    cudaGetSymbolAddress((void**)&query_c, g_query_c);
    cudaGetSymbolAddress((void**)&wo_c,  g_wo_c);
    cudaGetSymbolAddress((void**)&wkp_c, g_wkp_c);
    cudaGetSymbolAddress((void**)&idx,   g_idx);

    static bool init_done = false;
    if (!init_done) {
        cudaFuncSetAttribute(flash_content, cudaFuncAttributeMaxDynamicSharedMemorySize,
                             FL_SMEMF * sizeof(float));
        init_done = true;
    }

    const long SH = (long)SEQ * HIDD, S2H = (long)SEQ2 * HIDD, PH = (long)PQ * HIDD;
    const long SH3 = (long)SEQ * H3;
    const long PS = (long)PQ * SEQ, PS2 = (long)PQ * SEQ2;

    probe_segmat<<<1, 32>>>((const uint32_t*)segmat);
    prep_all<<<PREP_BLOCKS, 256>>>(content, pe, query, wo, wkp, wq, wkc, wv,
                                   content_c, pe_c, query_c, wo_c, wkp_c, wpack, qscat);

    // fused projection launch: QKV (384) + kp (256) + query-proj (16)
    {
        GD dQKV = {content_c, wpack, qkv, 24, 16, HIDD, H3, H3,
                   0, 0, 0, 0, 0, 0, 1, 64, 1024};
        GD dKP  = {pe_c, wkp_c, kp, 8, 32, HIDD, HIDD, HIDD,
                   0, 0, 0, 0, 0, 0, 1, 64, 0};
        GD dQG  = {query_c, wpack, qg, 8, 2, HIDD, H3, HIDD,
                   0, 0, 0, 0, 0, 0, 1, 64, NOCVT};
        gemm128m<false><<<656, 256>>>(dQKV, dKP, dQG, 384, 640);
    }

    scatter_q<<<dim3(PQ, BATCH), 128>>>(tmap, qg, qscat, idx);
    gather_bias<<<dim3(PQ, BATCH), 128>>>(qscat, idx, cbias, pbias, qq, qqcb, qqpb);

    const float* kcp = qkv + 1024;
    const float* vp  = qkv + 2048;

    // fused query-stream score launch: csq (256) + ppq (512)
    {
        GD dCS = {qqcb, kcp, csq, 8, 1, HIDD, H3, SEQ,
                  PH, DH, SH3, DH, (long)NH * PS, PS, NH, 4, NOCVT};
        GD dPP = {qqpb, kp, ppq, 16, 1, HIDD, HIDD, SEQ2,
                  PH, DH, S2H, DH, (long)NH * PS2, PS2, NH, 4, NOCVT};
        GD dZ = {};
        gemm128m<true><<<768, 256>>>(dCS, dPP, dZ, 256, 768);
    }
    softmax_kernel<<<dim3(PQ, NH, BATCH), 256>>>(
        csq, ppq, qq, segbias, segenc, segmat, qmask, idx, PQ, PH, HIDD);
    gemm_tf32<false><<<dim3(1, 1, BATCH * NH), 256>>>(csq, vp, qatt,
        PQ, DH, SEQ, SEQ, H3, HIDD, (long)NH * PS, PS, SH3, DH, PH, DH, NH, 0);

    // content stream
    flash_content<<<dim3(SEQ / 64, NH, BATCH), 128, FL_SMEMF * sizeof(float)>>>(
        qkv, kp, cbias, pbias, segbias, segenc, segmat, cmask, catt);

    // fused output projections: catt (128) + qatt (16)
    {
        GD dCO = {catt, wo_c, out, 8, 16, HIDD, HIDD, HIDD,
                  0, 0, 0, 0, 0, 0, 1, 64, NOCVT};
        GD dQO = {qatt, wo_c, out + (size_t)BATCH * SEQ * HIDD, 8, 2, HIDD, HIDD, HIDD,
                  0, 0, 0, 0, 0, 0, 1, 64, NOCVT};
        GD dZ = {};
        gemm128m<false><<<144, 256>>>(dCO, dQO, dZ, 128, 144);
    }
}

// round 12
// speedup vs baseline: 1.6525x; 1.3199x over previous
#include <cuda_runtime.h>
#include <cuda_fp16.h>
#include <cstdint>
#include <cstddef>

#define BATCH 2
#define SEQ   1024
#define SEQ2  2048
#define PQ    128
#define HIDD  1024
#define NH    16
#define DH    64

// ---------------- scratch ----------------
__device__ float  g_q[BATCH * SEQ * HIDD];          // fp32 q projection
__device__ __half g_kc[BATCH * SEQ * HIDD];         // fp16 content keys
__device__ __half g_vT[BATCH * HIDD * SEQ];         // fp16 V transposed [b][d][s]
__device__ __half g_wpackT[3 * HIDD * HIDD];        // wq^T | wkc^T | wv^T (fp16)
__device__ __half g_wkpT[HIDD * HIDD];
__device__ __half g_woT[HIDD * HIDD];
__device__ __half g_kph[BATCH * SEQ2 * HIDD];
__device__ __half g_conth[BATCH * SEQ * HIDD];
__device__ __half g_peh[BATCH * SEQ2 * HIDD];
__device__ __half g_qryh[BATCH * PQ * HIDD];
__device__ float  g_qg[BATCH * PQ * HIDD];
__device__ float  g_qscat[BATCH * SEQ * HIDD];
__device__ float  g_qq[BATCH * PQ * HIDD];
__device__ __half g_qqcb[BATCH * PQ * HIDD];
__device__ __half g_qqpb[BATCH * PQ * HIDD];
__device__ float  g_csq[(size_t)BATCH * NH * PQ * SEQ];
__device__ float  g_ppq[(size_t)BATCH * NH * PQ * SEQ2];
__device__ __half g_csqh[(size_t)BATCH * NH * PQ * SEQ];
__device__ __half g_catt[BATCH * SEQ * HIDD];
__device__ __half g_qatt[BATCH * PQ * HIDD];
__device__ int    g_idx[BATCH * PQ];
__device__ int    g_segmode[1];

// ---------------- probe ----------------
__global__ void probe_segmat(const uint32_t* __restrict__ p) {
    if (threadIdx.x == 0 && blockIdx.x == 0) {
        int mode = 1;
        for (int i = 0; i < 4096; i++) {
            uint32_t w = p[i];
            if (w == 0x3F800000u) { mode = 2; break; }
            if (w > 1u)           { mode = 0; break; }
        }
        g_segmode[0] = mode;
    }
}

__device__ __forceinline__ bool seg_at(const void* p, size_t i, int mode) {
    if (mode == 0) return ((const uint8_t*)p)[i] != 0;
    if (mode == 1) return ((const int*)p)[i] != 0;
    return ((const float*)p)[i] > 0.5f;
}

// ---------------- fp16 helpers ----------------
__device__ __forceinline__ uint32_t pkh(float a, float b) {
    __half2 h = __floats2half2_rn(a, b);
    return *(uint32_t*)&h;
}

__device__ __forceinline__ void mma_f16(float* c, const uint32_t* a, const uint32_t* b) {
    asm volatile(
        "mma.sync.aligned.m16n8k16.row.col.f32.f16.f16.f32 "
        "{%0,%1,%2,%3}, {%4,%5,%6,%7}, {%8,%9}, {%0,%1,%2,%3};"
        : "+f"(c[0]), "+f"(c[1]), "+f"(c[2]), "+f"(c[3])
        : "r"(a[0]), "r"(a[1]), "r"(a[2]), "r"(a[3]), "r"(b[0]), "r"(b[1]));
}

__device__ __forceinline__ void cp16(uint32_t s, const void* g) {
    asm volatile("cp.async.ca.shared.global [%0], [%1], 16;" :: "r"(s), "l"(g));
}

// ---------------- prep: input f32->f16 + zero ----------------
#define N4_CONT  524288
#define N4_PE    1048576
#define N4_QRY   65536
#define N4_ZERO  524288
#define PREP_BLOCKS ((N4_CONT + N4_PE + N4_QRY + N4_ZERO) / 256)

__global__ void prep_all(
    const float* __restrict__ content, const float* __restrict__ pe,
    const float* __restrict__ query,
    __half* __restrict__ conth, __half* __restrict__ peh,
    __half* __restrict__ qryh, float* __restrict__ qscat)
{
    long i = (long)blockIdx.x * 256 + threadIdx.x;
    auto cv = [](const float* s, __half* d, long j) {
        float4 v = ((const float4*)s)[j];
        uint2 o;
        o.x = pkh(v.x, v.y);
        o.y = pkh(v.z, v.w);
        ((uint2*)d)[j] = o;
    };
    if (i < N4_CONT) { cv(content, conth, i); return; }
    i -= N4_CONT;
    if (i < N4_PE)   { cv(pe, peh, i); return; }
    i -= N4_PE;
    if (i < N4_QRY)  { cv(query, qryh, i); return; }
    i -= N4_QRY;
    ((float4*)qscat)[i] = make_float4(0.f, 0.f, 0.f, 0.f);
}

// ---------------- weight transpose + convert (5 matrices) ----------------
__global__ void transw(
    const float* __restrict__ wq, const float* __restrict__ wkc,
    const float* __restrict__ wv, const float* __restrict__ wkp,
    const float* __restrict__ wo,
    __half* __restrict__ wpackT, __half* __restrict__ wkpT, __half* __restrict__ woT)
{
    const float* src; __half* dst;
    switch (blockIdx.z) {
        case 0: src = wq;  dst = wpackT; break;
        case 1: src = wkc; dst = wpackT + 1024 * 1024; break;
        case 2: src = wv;  dst = wpackT + 2 * 1024 * 1024; break;
        case 3: src = wkp; dst = wkpT; break;
        default: src = wo; dst = woT; break;
    }
    __shared__ float t[32][33];
    const int tx = threadIdx.x, ty = threadIdx.y;
    const int x = blockIdx.x * 32 + tx;
#pragma unroll
    for (int i = 0; i < 4; i++) {
        int y = blockIdx.y * 32 + ty + i * 8;
        t[ty + i * 8][tx] = src[(size_t)y * 1024 + x];
    }
    __syncthreads();
    const int x2 = blockIdx.y * 32 + tx;
#pragma unroll
    for (int i = 0; i < 4; i++) {
        int y2 = blockIdx.x * 32 + ty + i * 8;
        dst[(size_t)y2 * 1024 + x2] = __float2half_rn(t[tx][ty + i * 8]);
    }
}

// ---------------- multi-problem fp16 TB GEMM 128x128 ----------------
// C[m,n] = sum_k A[m,k] * B[n,k].  A,B fp16 row-major. K-step 32, 2-stage.
#define ASH 40   // smem stride in halves (32 + 8)

struct GD {
    const __half* A; const __half* B;
    float* Cf; __half* Ch; __half* Cv;   // epi 0 / 1 / 2 targets
    int gx, gy;
    int lda, ldb, ldc;
    long aOut, aIn, bOut, bIn, cOut, cIn;
    int zInner, KT, epi;
};

__global__ __launch_bounds__(256) void gemm128h(GD d0, GD d1, GD d2, int n0, int n01)
{
    __shared__ __half As[2][128 * ASH];
    __shared__ __half Bs[2][128 * ASH];

    GD d;
    int r = blockIdx.x;
    if (r < n0)       { d = d0; }
    else if (r < n01) { d = d1; r -= n0; }
    else              { d = d2; r -= n01; }

    const int tiles = d.gx * d.gy;
    const int z  = r / tiles;
    const int rr = r % tiles;
    const int by = rr / d.gx, bx = rr % d.gx;
    const int zo = z / d.zInner, zi = z % d.zInner;

    const __half* Ap = d.A + zo * d.aOut + zi * d.aIn;
    const __half* Bp = d.B + zo * d.bOut + zi * d.bIn;
    const int m0 = by * 128, n0px = bx * 128;
    const int lda = d.lda, ldb = d.ldb;

    const int tid = threadIdx.x;
    const int wid = tid >> 5, lane = tid & 31;
    const int wm = (wid & 3) * 32, wn = (wid >> 2) * 64;
    const int lr = lane >> 2, lc = lane & 3;

    uint32_t aSm[2], bSm[2];
    aSm[0] = (uint32_t)__cvta_generic_to_shared(&As[0][0]);
    aSm[1] = (uint32_t)__cvta_generic_to_shared(&As[1][0]);
    bSm[0] = (uint32_t)__cvta_generic_to_shared(&Bs[0][0]);
    bSm[1] = (uint32_t)__cvta_generic_to_shared(&Bs[1][0]);

    auto stage = [&](int kt) {
        const int k0 = kt * 32, buf = kt & 1;
#pragma unroll
        for (int i = 0; i < 2; i++) {
            int id = tid + i * 256;
            int row = id >> 2, off = (id & 3) * 8;
            cp16(aSm[buf] + (uint32_t)(row * ASH + off) * 2,
                 Ap + (size_t)(m0 + row) * lda + k0 + off);
            cp16(bSm[buf] + (uint32_t)(row * ASH + off) * 2,
                 Bp + (size_t)(n0px + row) * ldb + k0 + off);
        }
    };

    float acc[2][8][4] = {};
    const int KT = d.KT;

    stage(0);
    asm volatile("cp.async.commit_group;");

    for (int kt = 0; kt < KT; kt++) {
        if (kt + 1 < KT) {
            stage(kt + 1);
            asm volatile("cp.async.commit_group;");
            asm volatile("cp.async.wait_group 1;");
        } else {
            asm volatile("cp.async.wait_group 0;");
        }
        __syncthreads();

        const __half* as = As[kt & 1];
        const __half* bs = Bs[kt & 1];
#pragma unroll
        for (int kk = 0; kk < 32; kk += 16) {
            uint32_t af[2][4], bf[8][2];
#pragma unroll
            for (int im = 0; im < 2; im++) {
                const int base = (wm + im * 16 + lr) * ASH + kk + 2 * lc;
                af[im][0] = *(const uint32_t*)(as + base);
                af[im][1] = *(const uint32_t*)(as + base + 8 * ASH);
                af[im][2] = *(const uint32_t*)(as + base + 8);
                af[im][3] = *(const uint32_t*)(as + base + 8 * ASH + 8);
            }
#pragma unroll
            for (int jn = 0; jn < 8; jn++) {
                const int bb = (wn + jn * 8 + lr) * ASH + kk + 2 * lc;
                bf[jn][0] = *(const uint32_t*)(bs + bb);
                bf[jn][1] = *(const uint32_t*)(bs + bb + 8);
            }
#pragma unroll
            for (int im = 0; im < 2; im++)
#pragma unroll
                for (int jn = 0; jn < 8; jn++)
                    mma_f16(acc[im][jn], af[im], bf[jn]);
        }
        __syncthreads();
    }

    // epilogue
#pragma unroll
    for (int im = 0; im < 2; im++) {
#pragma unroll
        for (int jn = 0; jn < 8; jn++) {
            const int row = m0 + wm + im * 16 + lr;
            const int col = n0px + wn + jn * 8 + 2 * lc;
            const float c0 = acc[im][jn][0], c1 = acc[im][jn][1];
            const float c2 = acc[im][jn][2], c3 = acc[im][jn][3];
            if (d.epi == 0) {
                float* Cp = d.Cf + zo * d.cOut + zi * d.cIn;
                *(float2*)(Cp + (size_t)row * d.ldc + col) = make_float2(c0, c1);
                *(float2*)(Cp + (size_t)(row + 8) * d.ldc + col) = make_float2(c2, c3);
            } else if (d.epi == 1) {
                __half* Cp = d.Ch + zo * d.cOut + zi * d.cIn;
                *(uint32_t*)(Cp + (size_t)row * d.ldc + col) = pkh(c0, c1);
                *(uint32_t*)(Cp + (size_t)(row + 8) * d.ldc + col) = pkh(c2, c3);
            } else {
                // QKV split: col<1024 -> q fp32; <2048 -> kc fp16; else -> vT fp16
                if (col < 1024) {
                    *(float2*)(d.Cf + (size_t)row * 1024 + col) = make_float2(c0, c1);
                    *(float2*)(d.Cf + (size_t)(row + 8) * 1024 + col) = make_float2(c2, c3);
                } else if (col < 2048) {
                    *(uint32_t*)(d.Ch + (size_t)row * 1024 + col - 1024) = pkh(c0, c1);
                    *(uint32_t*)(d.Ch + (size_t)(row + 8) * 1024 + col - 1024) = pkh(c2, c3);
                } else {
                    const int b = row >> 10, s = row & 1023, dd = col - 2048;
                    __half* v = d.Cv + (size_t)b * (1024 * 1024);
                    v[(size_t)dd * 1024 + s]           = __float2half_rn(c0);
                    v[(size_t)(dd + 1) * 1024 + s]     = __float2half_rn(c1);
                    v[(size_t)dd * 1024 + s + 8]       = __float2half_rn(c2);
                    v[(size_t)(dd + 1) * 1024 + s + 8] = __float2half_rn(c3);
                }
            }
        }
    }
}

// ---------------- fp16 TB GEMM M128 x N64 (AV) ----------------
__global__ __launch_bounds__(256) void gemm64h(
    const __half* __restrict__ A, const __half* __restrict__ B, __half* __restrict__ C,
    long aIn, long bOut, long bIn, long cOut, long cIn, int zInner,
    int lda, int ldb, int ldc, int KT)
{
    __shared__ __half As[2][128 * ASH];
    __shared__ __half Bs[2][64 * ASH];

    const int z = blockIdx.x;
    const int zo = z / zInner, zi = z % zInner;
    const __half* Ap = A + (size_t)z * aIn;
    const __half* Bp = B + zo * bOut + zi * bIn;
    __half* Cp = C + zo * cOut + zi * cIn;

    const int tid = threadIdx.x;
    const int wid = tid >> 5, lane = tid & 31;
    const int wm = (wid & 3) * 32, wn = (wid >> 2) * 32;
    const int lr = lane >> 2, lc = lane & 3;

    uint32_t aSm[2], bSm[2];
    aSm[0] = (uint32_t)__cvta_generic_to_shared(&As[0][0]);
    aSm[1] = (uint32_t)__cvta_generic_to_shared(&As[1][0]);
    bSm[0] = (uint32_t)__cvta_generic_to_shared(&Bs[0][0]);
    bSm[1] = (uint32_t)__cvta_generic_to_shared(&Bs[1][0]);

    auto stage = [&](int kt) {
        const int k0 = kt * 32, buf = kt & 1;
#pragma unroll
        for (int i = 0; i < 2; i++) {
            int id = tid + i * 256;
            int row = id >> 2, off = (id & 3) * 8;
            cp16(aSm[buf] + (uint32_t)(row * ASH + off) * 2,
                 Ap + (size_t)row * lda + k0 + off);
        }
        int row = tid >> 2, off = (tid & 3) * 8;
        if (row < 64)
            cp16(bSm[buf] + (uint32_t)(row * ASH + off) * 2,
                 Bp + (size_t)row * ldb + k0 + off);
    };

    float acc[2][4][4] = {};

    stage(0);
    asm volatile("cp.async.commit_group;");

    for (int kt = 0; kt < KT; kt++) {
        if (kt + 1 < KT) {
            stage(kt + 1);
            asm volatile("cp.async.commit_group;");
            asm volatile("cp.async.wait_group 1;");
        } else {
            asm volatile("cp.async.wait_group 0;");
        }
        __syncthreads();

        const __half* as = As[kt & 1];
        const __half* bs = Bs[kt & 1];
#pragma unroll
        for (int kk = 0; kk < 32; kk += 16) {
            uint32_t af[2][4], bf[4][2];
#pragma unroll
            for (int im = 0; im < 2; im++) {
                const int base = (wm + im * 16 + lr) * ASH + kk + 2 * lc;
                af[im][0] = *(const uint32_t*)(as + base);
                af[im][1] = *(const uint32_t*)(as + base + 8 * ASH);
                af[im][2] = *(const uint32_t*)(as + base + 8);
                af[im][3] = *(const uint32_t*)(as + base + 8 * ASH + 8);
            }
#pragma unroll
            for (int jn = 0; jn < 4; jn++) {
                const int bb = (wn + jn * 8 + lr) * ASH + kk + 2 * lc;
                bf[jn][0] = *(const uint32_t*)(bs + bb);
                bf[jn][1] = *(const uint32_t*)(bs + bb + 8);
            }
#pragma unroll
            for (int im = 0; im < 2; im++)
#pragma unroll
                for (int jn = 0; jn < 4; jn++)
                    mma_f16(acc[im][jn], af[im], bf[jn]);
        }
        __syncthreads();
    }

#pragma unroll
    for (int im = 0; im < 2; im++) {
#pragma unroll
        for (int jn = 0; jn < 4; jn++) {
            const int row = wm + im * 16 + lr;
            const int col = wn + jn * 8 + 2 * lc;
            *(uint32_t*)(Cp + (size_t)row * ldc + col) = pkh(acc[im][jn][0], acc[im][jn][1]);
            *(uint32_t*)(Cp + (size_t)(row + 8) * ldc + col) = pkh(acc[im][jn][2], acc[im][jn][3]);
        }
    }
}

// ---------------- flash-fused content attention (fp16 mma) ----------------
#define KST 72                          // half stride for KC/KP/V/P tiles
#define RSTF 68                         // float stride for PP ring
#define FL_SMEMF (3 * (64 * KST / 2) + 2 * 64 * RSTF + 128)

__device__ __forceinline__ void stage64h(__half* dst, const __half* src, long rstride, int tid) {
    uint32_t s = (uint32_t)__cvta_generic_to_shared(dst);
#pragma unroll
    for (int i = 0; i < 4; i++) {
        int id = tid + i * 128;
        int r = id >> 3, o = (id & 7) * 8;
        cp16(s + (uint32_t)(r * KST + o) * 2, src + (size_t)r * rstride + o);
    }
}

__global__ __launch_bounds__(128, 2) void flash_content(
    const float* __restrict__ q, const __half* __restrict__ kc,
    const __half* __restrict__ vT, const __half* __restrict__ kp,
    const float* __restrict__ cb, const float* __restrict__ pb,
    const float* __restrict__ sb, const float* __restrict__ seg,
    const void* __restrict__ segmat, const float* __restrict__ mask,
    __half* __restrict__ out)
{
    extern __shared__ float sm[];
    __half* KCs = (__half*)sm;                 // 64 x KST halves
    __half* KPs = (__half*)(sm + 2304);
    __half* VsT = (__half*)(sm + 4608);
    float*  ring = sm + 6912;                  // 2 x 64 x RSTF floats
    float*  s0s  = sm + 6912 + 2 * 64 * RSTF;
    float*  s1s  = s0s + 64;
    __half* Ps   = KPs;                        // alias

    const int b = blockIdx.z, h = blockIdx.y, qt = blockIdx.x, q0 = qt * 64;
    const int tid = threadIdx.x, w = tid >> 5, l = tid & 31;
    const int lr = l >> 2, lc = l & 3;
    const int qb = w * 16;
    const int mode = g_segmode[0];
    const int hD = h * DH;

    // Q fragments (+cb, +pb) as fp16 pairs
    uint32_t aC[4][4], aP[4][4];
    {
        const float* r0 = q + ((size_t)(b * SEQ + q0 + qb + lr)) * HIDD + hD;
        const float* r1 = r0 + (size_t)8 * HIDD;
#pragma unroll
        for (int s = 0; s < 4; s++) {
            const int d0 = 16 * s + 2 * lc;
            float2 q00 = *(const float2*)(r0 + d0);
            float2 q08 = *(const float2*)(r0 + d0 + 8);
            float2 q10 = *(const float2*)(r1 + d0);
            float2 q18 = *(const float2*)(r1 + d0 + 8);
            const float cb0 = cb[hD + d0], cb1 = cb[hD + d0 + 1];
            const float cb8 = cb[hD + d0 + 8], cb9 = cb[hD + d0 + 9];
            const float pb0 = pb[hD + d0], pb1 = pb[hD + d0 + 1];
            const float pb8 = pb[hD + d0 + 8], pb9 = pb[hD + d0 + 9];
            aC[s][0] = pkh(q00.x + cb0, q00.y + cb1);
            aC[s][1] = pkh(q10.x + cb0, q10.y + cb1);
            aC[s][2] = pkh(q08.x + cb8, q08.y + cb9);
            aC[s][3] = pkh(q18.x + cb8, q18.y + cb9);
            aP[s][0] = pkh(q00.x + pb0, q00.y + pb1);
            aP[s][1] = pkh(q10.x + pb0, q10.y + pb1);
            aP[s][2] = pkh(q08.x + pb8, q08.y + pb9);
            aP[s][3] = pkh(q18.x + pb8, q18.y + pb9);
        }
    }
    if (tid < 64) {
        const float* qr = q + ((size_t)(b * SEQ + q0 + tid)) * HIDD + hD;
        float s0 = 0.f, s1 = 0.f;
        for (int d = 0; d < DH; d++) {
            float qs = qr[d] + sb[hD + d];
            s0 += qs * seg[hD + d];
            s1 += qs * seg[NH * DH + hD + d];
        }
        s0s[tid] = s0; s1s[tid] = s1;
    }

    float O[8][4] = {};
    float m_a = -1e30f, m_b = -1e30f, l_a = 0.f, l_b = 0.f;

    auto pp_tile = [&](int slot) {
        float* rg = ring + slot * 64 * RSTF;
#pragma unroll
        for (int jn = 0; jn < 8; jn++) {
            float c[4] = {0.f, 0.f, 0.f, 0.f};
            const __half* bp = KPs + (jn * 8 + lr) * KST + 2 * lc;
#pragma unroll
            for (int s = 0; s < 4; s++) {
                uint32_t bfr[2];
                bfr[0] = *(const uint32_t*)(bp + 16 * s);
                bfr[1] = *(const uint32_t*)(bp + 16 * s + 8);
                mma_f16(c, aP[s], bfr);
            }
            float* r0 = rg + (qb + lr) * RSTF + jn * 8 + 2 * lc;
            *(float2*)r0 = make_float2(c[0], c[1]);
            *(float2*)(r0 + 8 * RSTF) = make_float2(c[2], c[3]);
        }
        __syncwarp();
    };

    {
        stage64h(KPs, kp + ((size_t)(b * SEQ2 + SEQ - q0 - 64)) * HIDD + hD, HIDD, tid);
        asm volatile("cp.async.commit_group;");
        asm volatile("cp.async.wait_group 0;");
        __syncthreads();
        pp_tile((15 - qt) & 1);
    }

    const int ra = qb + lr, rb = ra + 8;
    const size_t mbase_a = ((size_t)b * SEQ + q0 + ra) * SEQ;
    const size_t mbase_b = mbase_a + (size_t)8 * SEQ;
    const float s0a = s0s[ra], s1a = s1s[ra];
    const float s0b = s0s[rb], s1b = s1s[rb];

    for (int kt = 0; kt < 16; kt++) {
        const int k0 = kt * 64;
        const int Tb = 16 + kt - qt;
        __syncthreads();
        stage64h(KCs, kc + (size_t)(b * SEQ + k0) * HIDD + hD, HIDD, tid);
        stage64h(VsT, vT + ((size_t)b << 20) + (size_t)hD * SEQ + k0, SEQ, tid);
        stage64h(KPs, kp + ((size_t)b * SEQ2 + (size_t)64 * Tb) * HIDD + hD, HIDD, tid);
        asm volatile("cp.async.commit_group;");
        asm volatile("cp.async.wait_group 0;");
        __syncthreads();

        pp_tile(Tb & 1);
        const int slotA = (Tb - 1) & 1, slotB = Tb & 1;

        float cs[8][4];
#pragma unroll
        for (int jn = 0; jn < 8; jn++) {
            float c[4] = {0.f, 0.f, 0.f, 0.f};
            const __half* bp = KCs + (jn * 8 + lr) * KST + 2 * lc;
#pragma unroll
            for (int s = 0; s < 4; s++) {
                uint32_t bfr[2];
                bfr[0] = *(const uint32_t*)(bp + 16 * s);
                bfr[1] = *(const uint32_t*)(bp + 16 * s + 8);
                mma_f16(c, aC[s], bfr);
            }
            cs[jn][0] = c[0]; cs[jn][1] = c[1]; cs[jn][2] = c[2]; cs[jn][3] = c[3];
        }

        float mxa = -1e30f, mxb = -1e30f;
#pragma unroll
        for (int jn = 0; jn < 8; jn++) {
            const int kkp = jn * 8 + 2 * lc;
            float2 mva = *(const float2*)(mask + mbase_a + k0 + kkp);
            float2 mvb = *(const float2*)(mask + mbase_b + k0 + kkp);
            float sa0 = seg_at(segmat, mbase_a + k0 + kkp, mode)     ? s1a : s0a;
            float sa1 = seg_at(segmat, mbase_a + k0 + kkp + 1, mode) ? s1a : s0a;
            float sb0 = seg_at(segmat, mbase_b + k0 + kkp, mode)     ? s1b : s0b;
            float sb1 = seg_at(segmat, mbase_b + k0 + kkp + 1, mode) ? s1b : s0b;
            const int wa = kkp - ra + 64, wb = kkp - rb + 64;
            float ppa0 = ring[(wa < 64 ? slotA : slotB) * 64 * RSTF + ra * RSTF + (wa & 63)];
            float ppa1 = ring[(wa + 1 < 64 ? slotA : slotB) * 64 * RSTF + ra * RSTF + ((wa + 1) & 63)];
            float ppb0 = ring[(wb < 64 ? slotA : slotB) * 64 * RSTF + rb * RSTF + (wb & 63)];
            float ppb1 = ring[(wb + 1 < 64 ? slotA : slotB) * 64 * RSTF + rb * RSTF + ((wb + 1) & 63)];
            cs[jn][0] = (cs[jn][0] + ppa0 + sa0) * 0.125f + mva.x * (-1e9f);
            cs[jn][1] = (cs[jn][1] + ppa1 + sa1) * 0.125f + mva.y * (-1e9f);
            cs[jn][2] = (cs[jn][2] + ppb0 + sb0) * 0.125f + mvb.x * (-1e9f);
            cs[jn][3] = (cs[jn][3] + ppb1 + sb1) * 0.125f + mvb.y * (-1e9f);
            mxa = fmaxf(mxa, fmaxf(cs[jn][0], cs[jn][1]));
            mxb = fmaxf(mxb, fmaxf(cs[jn][2], cs[jn][3]));
        }
        __syncthreads();    // all warps done with KPs before Ps overwrite

        mxa = fmaxf(mxa, __shfl_xor_sync(0xffffffffu, mxa, 1));
        mxa = fmaxf(mxa, __shfl_xor_sync(0xffffffffu, mxa, 2));
        mxb = fmaxf(mxb, __shfl_xor_sync(0xffffffffu, mxb, 1));
        mxb = fmaxf(mxb, __shfl_xor_sync(0xffffffffu, mxb, 2));

        const float mna = fmaxf(m_a, mxa), mnb = fmaxf(m_b, mxb);
        const float alA = __expf(m_a - mna), alB = __expf(m_b - mnb);
        m_a = mna; m_b = mnb;

        float sa = 0.f, sbm = 0.f;
#pragma unroll
        for (int jn = 0; jn < 8; jn++) {
            float p0 = __expf(cs[jn][0] - m_a), p1 = __expf(cs[jn][1] - m_a);
            float p2 = __expf(cs[jn][2] - m_b), p3 = __expf(cs[jn][3] - m_b);
            sa += p0 + p1; sbm += p2 + p3;
            *(uint32_t*)(Ps + ra * KST + jn * 8 + 2 * lc) = pkh(p0, p1);
            *(uint32_t*)(Ps + rb * KST + jn * 8 + 2 * lc) = pkh(p2, p3);
            O[jn][0] *= alA; O[jn][1] *= alA; O[jn][2] *= alB; O[jn][3] *= alB;
        }
        sa  += __shfl_xor_sync(0xffffffffu, sa, 1);
        sa  += __shfl_xor_sync(0xffffffffu, sa, 2);
        sbm += __shfl_xor_sync(0xffffffffu, sbm, 1);
        sbm += __shfl_xor_sync(0xffffffffu, sbm, 2);
        l_a = l_a * alA + sa;
        l_b = l_b * alB + sbm;
        __syncwarp();

        uint32_t ap[4][4];
#pragma unroll
        for (int s = 0; s < 4; s++) {
            ap[s][0] = *(const uint32_t*)(Ps + ra * KST + 16 * s + 2 * lc);
            ap[s][1] = *(const uint32_t*)(Ps + rb * KST + 16 * s + 2 * lc);
            ap[s][2] = *(const uint32_t*)(Ps + ra * KST + 16 * s + 2 * lc + 8);
            ap[s][3] = *(const uint32_t*)(Ps + rb * KST + 16 * s + 2 * lc + 8);
        }
#pragma unroll
        for (int jn = 0; jn < 8; jn++) {
            const __half* vp = VsT + (jn * 8 + lr) * KST + 2 * lc;
#pragma unroll
            for (int s = 0; s < 4; s++) {
                uint32_t bfr[2];
                bfr[0] = *(const uint32_t*)(vp + 16 * s);
                bfr[1] = *(const uint32_t*)(vp + 16 * s + 8);
                mma_f16(O[jn], ap[s], bfr);
            }
        }
        __syncwarp();
    }

    const float ia = 1.f / l_a, ib = 1.f / l_b;
    __half* o0 = out + ((size_t)(b * SEQ + q0 + ra)) * HIDD + hD;
    __half* o1 = o0 + (size_t)8 * HIDD;
#pragma unroll
    for (int jn = 0; jn < 8; jn++) {
        *(uint32_t*)(o0 + jn * 8 + 2 * lc) = pkh(O[jn][0] * ia, O[jn][1] * ia);
        *(uint32_t*)(o1 + jn * 8 + 2 * lc) = pkh(O[jn][2] * ib, O[jn][3] * ib);
    }
}

// ---------------- small kernels ----------------
__global__ void scatter_q(const float* __restrict__ tmap, const float* __restrict__ qg,
                          float* __restrict__ qscat, int* __restrict__ idx)
{
    const int b = blockIdx.y, p = blockIdx.x, t = threadIdx.x;
    __shared__ int sidx;
    const float* row = tmap + ((size_t)b * PQ + p) * SEQ;
    for (int s = t; s < SEQ; s += 128)
        if (row[s] > 0.5f) sidx = s;
    __syncthreads();
    const int si = sidx;
    if (t == 0) idx[b * PQ + p] = si;
    const float* src = qg + ((size_t)b * PQ + p) * HIDD;
    float* dst = qscat + ((size_t)b * SEQ + si) * HIDD;
    for (int i = t; i < HIDD; i += 128) atomicAdd(&dst[i], src[i]);
}

__global__ void gather_bias(const float* __restrict__ qscat, const int* __restrict__ idx,
                            const float* __restrict__ cb, const float* __restrict__ pb,
                            float* __restrict__ qq, __half* __restrict__ ocb,
                            __half* __restrict__ opb)
{
    const int b = blockIdx.y, p = blockIdx.x, t = threadIdx.x;
    const int si = idx[b * PQ + p];
    const float* src = qscat + ((size_t)b * SEQ + si) * HIDD;
    const size_t o = (size_t)(b * PQ + p) * HIDD;
    for (int i = t; i < HIDD; i += 128) {
        float v = src[i];
        qq[o + i]  = v;
        ocb[o + i] = __float2half_rn(v + cb[i]);
        opb[o + i] = __float2half_rn(v + pb[i]);
    }
}

// ---------------- query-stream softmax (fp32 in, fp16 weights out) ----------------
__global__ __launch_bounds__(256) void softmax_kernel(
    const float* __restrict__ cs, const float* __restrict__ pp,
    __half* __restrict__ csh,
    const float* __restrict__ qArr, const float* __restrict__ sb,
    const float* __restrict__ seg, const void* __restrict__ segmat,
    const float* __restrict__ mask, const int* __restrict__ qidx)
{
    const int b = blockIdx.z, h = blockIdx.y, qo = blockIdx.x, t = threadIdx.x;
    const int qrow = qidx[b * PQ + qo];
    const int z = b * NH + h;
    const int mode = g_segmode[0];

    const float* csrow = cs + ((size_t)z * PQ + qo) * SEQ;
    __half* cw = csh + ((size_t)z * PQ + qo) * SEQ;
    const float* pprow = pp + ((size_t)z * PQ + qo) * SEQ2 + (SEQ - qrow);
    const float* mrow = mask + ((size_t)b * SEQ + qrow) * SEQ;
    const size_t segbase = ((size_t)b * SEQ + qrow) * SEQ;

    __shared__ float qsv[DH];
    __shared__ float s01[2];
    __shared__ float red[256];

    if (t < DH)
        qsv[t] = qArr[(size_t)(b * PQ + qo) * HIDD + h * DH + t] + sb[h * DH + t];
    __syncthreads();
    if (t < 64) {
        const int which = t >> 5, lx = t & 31;
        const float* sgp = seg + which * NH * DH + h * DH;
        float a = qsv[lx] * sgp[lx] + qsv[lx + 32] * sgp[lx + 32];
#pragma unroll
        for (int o = 16; o; o >>= 1) a += __shfl_xor_sync(0xffffffffu, a, o);
        if (lx == 0) s01[which] = a;
    }
    __syncthreads();
    const float s0 = s01[0], s1 = s01[1];

    float lg[4];
    float mx = -3.4e38f;
#pragma unroll
    for (int j = 0; j < 4; j++) {
        int k = t + j * 256;
        float sgv = seg_at(segmat, segbase + k, mode) ? s1 : s0;
        float v = (csrow[k] + pprow[k] + sgv) * 0.125f + mrow[k] * (-1e9f);
        lg[j] = v;
        mx = fmaxf(mx, v);
    }
    red[t] = mx; __syncthreads();
#pragma unroll
    for (int s2 = 128; s2; s2 >>= 1) {
        if (t < s2) red[t] = fmaxf(red[t], red[t + s2]);
        __syncthreads();
    }
    mx = red[0]; __syncthreads();

    float sum = 0.f;
#pragma unroll
    for (int j = 0; j < 4; j++) {
        float e = __expf(lg[j] - mx);
        lg[j] = e;
        sum += e;
    }
    red[t] = sum; __syncthreads();
#pragma unroll
    for (int s2 = 128; s2; s2 >>= 1) {
        if (t < s2) red[t] += red[t + s2];
        __syncthreads();
    }
    const float invZ = 1.f / red[0];
#pragma unroll
    for (int j = 0; j < 4; j++) cw[t + j * 256] = __float2half_rn(lg[j] * invZ);
}

// ---------------- launch ----------------
extern "C" void kernel_launch(void* const* d_in, const int* in_sizes, int n_in,
                              void* d_out, int out_size)
{
    const float* content = (const float*)d_in[0];
    const float* query   = (const float*)d_in[1];
    const float* pe      = (const float*)d_in[2];
    const void*  segmat  = d_in[3];
    const float* segenc  = (const float*)d_in[4];
    const float* segbias = (const float*)d_in[5];
    const float* cmask   = (const float*)d_in[6];
    const float* qmask   = (const float*)d_in[7];
    const float* tmap    = (const float*)d_in[8];
    const float* cbias   = (const float*)d_in[9];
    const float* pbias   = (const float*)d_in[10];
    const float* wq      = (const float*)d_in[11];
    const float* wkc     = (const float*)d_in[12];
    const float* wv      = (const float*)d_in[13];
    const float* wkp     = (const float*)d_in[14];
    const float* wo      = (const float*)d_in[15];
    float* out = (float*)d_out;

    float *q, *qg, *qscat, *qq, *csq, *ppq;
    __half *kc, *vT, *wpackT, *wkpT, *woT, *kph, *conth, *peh, *qryh;
    __half *qqcb, *qqpb, *csqh, *catt, *qatt;
    int* idx;
    cudaGetSymbolAddress((void**)&q,      g_q);
    cudaGetSymbolAddress((void**)&kc,     g_kc);
    cudaGetSymbolAddress((void**)&vT,     g_vT);
    cudaGetSymbolAddress((void**)&wpackT, g_wpackT);
    cudaGetSymbolAddress((void**)&wkpT,   g_wkpT);
    cudaGetSymbolAddress((void**)&woT,    g_woT);
    cudaGetSymbolAddress((void**)&kph,    g_kph);
    cudaGetSymbolAddress((void**)&conth,  g_conth);
    cudaGetSymbolAddress((void**)&peh,    g_peh);
    cudaGetSymbolAddress((void**)&qryh,   g_qryh);
    cudaGetSymbolAddress((void**)&qg,     g_qg);
    cudaGetSymbolAddress((void**)&qscat,  g_qscat);
    cudaGetSymbolAddress((void**)&qq,     g_qq);
    cudaGetSymbolAddress((void**)&qqcb,   g_qqcb);
    cudaGetSymbolAddress((void**)&qqpb,   g_qqpb);
    cudaGetSymbolAddress((void**)&csq,    g_csq);
    cudaGetSymbolAddress((void**)&ppq,    g_ppq);
    cudaGetSymbolAddress((void**)&csqh,   g_csqh);
    cudaGetSymbolAddress((void**)&catt,   g_catt);
    cudaGetSymbolAddress((void**)&qatt,   g_qatt);
    cudaGetSymbolAddress((void**)&idx,    g_idx);

    static bool init_done = false;
    if (!init_done) {
        cudaFuncSetAttribute(flash_content, cudaFuncAttributeMaxDynamicSharedMemorySize,
                             FL_SMEMF * sizeof(float));
        init_done = true;
    }

    const long PH = (long)PQ * HIDD;
    const long PS = (long)PQ * SEQ, PS2 = (long)PQ * SEQ2;

    probe_segmat<<<1, 32>>>((const uint32_t*)segmat);
    prep_all<<<PREP_BLOCKS, 256>>>(content, pe, query, conth, peh, qryh, qscat);
    transw<<<dim3(32, 32, 5), dim3(32, 8)>>>(wq, wkc, wv, wkp, wo, wpackT, wkpT, woT);

    // fused projections: QKV (384) + kp (256) + query-proj (16)
    {
        GD dQKV = {conth, wpackT, q, kc, vT, 24, 16, HIDD, HIDD, 0,
                   0, 0, 0, 0, 0, 0, 1, 32, 2};
        GD dKP  = {peh, wkpT, nullptr, kph, nullptr, 8, 32, HIDD, HIDD, HIDD,
                   0, 0, 0, 0, 0, 0, 1, 32, 1};
        GD dQG  = {qryh, wpackT, qg, nullptr, nullptr, 8, 2, HIDD, HIDD, HIDD,
                   0, 0, 0, 0, 0, 0, 1, 32, 0};
        gemm128h<<<656, 256>>>(dQKV, dKP, dQG, 384, 640);
    }

    scatter_q<<<dim3(PQ, BATCH), 128>>>(tmap, qg, qscat, idx);
    gather_bias<<<dim3(PQ, BATCH), 128>>>(qscat, idx, cbias, pbias, qq, qqcb, qqpb);

    // fused query-stream scores: csq (256) + ppq (512)
    {
        GD dCS = {qqcb, kc, csq, nullptr, nullptr, 8, 1, HIDD, HIDD, SEQ,
                  PH, 64, (long)SEQ * HIDD, 64, (long)NH * PS, PS, NH, 2, 0};
        GD dPP = {qqpb, kph, ppq, nullptr, nullptr, 16, 1, HIDD, HIDD, SEQ2,
                  PH, 64, (long)SEQ2 * HIDD, 64, (long)NH * PS2, PS2, NH, 2, 0};
        GD dZ = {};
        gemm128h<<<768, 256>>>(dCS, dPP, dZ, 256, 768);
    }
    softmax_kernel<<<dim3(PQ, NH, BATCH), 256>>>(
        csq, ppq, csqh, qq, segbias, segenc, segmat, qmask, idx);
    // AV: weights x vT  (32 blocks)
    gemm64h<<<BATCH * NH, 256>>>(csqh, vT, qatt,
        PS, (long)1024 * 1024, (long)64 * SEQ, PH, 64, NH,
        SEQ, SEQ, HIDD, 32);

    // content stream
    flash_content<<<dim3(SEQ / 64, NH, BATCH), 128, FL_SMEMF * sizeof(float)>>>(
        q, kc, vT, kph, cbias, pbias, segbias, segenc, segmat, cmask, catt);

    // fused output projections: catt (128) + qatt (16)
    {
        GD dCO = {catt, woT, out, nullptr, nullptr, 8, 16, HIDD, HIDD, HIDD,
                  0, 0, 0, 0, 0, 0, 1, 32, 0};
        GD dQO = {qatt, woT, out + (size_t)BATCH * SEQ * HIDD, nullptr, nullptr,
                  8, 2, HIDD, HIDD, HIDD, 0, 0, 0, 0, 0, 0, 1, 32, 0};
        GD dZ = {};
        gemm128h<<<144, 256>>>(dCO, dQO, dZ, 128, 144);
    }
}

// round 13
// speedup vs baseline: 1.6809x; 1.0172x over previous
#include <cuda_runtime.h>
#include <cuda_fp16.h>
#include <cstdint>
#include <cstddef>

#define BATCH 2
#define SEQ   1024
#define SEQ2  2048
#define PQ    128
#define HIDD  1024
#define NH    16
#define DH    64

// ---------------- scratch ----------------
__device__ float  g_q[BATCH * SEQ * HIDD];
__device__ __half g_kc[BATCH * SEQ * HIDD];
__device__ __half g_vT[BATCH * HIDD * SEQ];
__device__ __half g_wpackT[3 * HIDD * HIDD];
__device__ __half g_wkpT[HIDD * HIDD];
__device__ __half g_woT[HIDD * HIDD];
__device__ __half g_kph[BATCH * SEQ2 * HIDD];
__device__ __half g_conth[BATCH * SEQ * HIDD];
__device__ __half g_peh[BATCH * SEQ2 * HIDD];
__device__ __half g_qryh[BATCH * PQ * HIDD];
__device__ float  g_qg[BATCH * PQ * HIDD];
__device__ float  g_qscat[BATCH * SEQ * HIDD];
__device__ float  g_qq[BATCH * PQ * HIDD];
__device__ __half g_qqcb[BATCH * PQ * HIDD];
__device__ __half g_qqpb[BATCH * PQ * HIDD];
__device__ float  g_csq[(size_t)BATCH * NH * PQ * SEQ];
__device__ float  g_ppq[(size_t)BATCH * NH * PQ * SEQ2];
__device__ __half g_csqh[(size_t)BATCH * NH * PQ * SEQ];
__device__ __half g_catt[BATCH * SEQ * HIDD];
__device__ __half g_qatt[BATCH * PQ * HIDD];
__device__ int    g_idx[BATCH * PQ];
__device__ int    g_segmode[1];

// ---------------- probe ----------------
__global__ void probe_segmat(const uint32_t* __restrict__ p) {
    if (threadIdx.x == 0 && blockIdx.x == 0) {
        int mode = 1;
        for (int i = 0; i < 4096; i++) {
            uint32_t w = p[i];
            if (w == 0x3F800000u) { mode = 2; break; }
            if (w > 1u)           { mode = 0; break; }
        }
        g_segmode[0] = mode;
    }
}

__device__ __forceinline__ bool seg_at(const void* p, size_t i, int mode) {
    if (mode == 0) return ((const uint8_t*)p)[i] != 0;
    if (mode == 1) return ((const int*)p)[i] != 0;
    return ((const float*)p)[i] > 0.5f;
}

// ---------------- fp16 helpers ----------------
__device__ __forceinline__ uint32_t pkh(float a, float b) {
    __half2 h = __floats2half2_rn(a, b);
    return *(uint32_t*)&h;
}

__device__ __forceinline__ void mma_f16(float* c, const uint32_t* a, const uint32_t* b) {
    asm volatile(
        "mma.sync.aligned.m16n8k16.row.col.f32.f16.f16.f32 "
        "{%0,%1,%2,%3}, {%4,%5,%6,%7}, {%8,%9}, {%0,%1,%2,%3};"
        : "+f"(c[0]), "+f"(c[1]), "+f"(c[2]), "+f"(c[3])
        : "r"(a[0]), "r"(a[1]), "r"(a[2]), "r"(a[3]), "r"(b[0]), "r"(b[1]));
}

__device__ __forceinline__ void cp16(uint32_t s, const void* g) {
    asm volatile("cp.async.ca.shared.global [%0], [%1], 16;" :: "r"(s), "l"(g));
}

__device__ __forceinline__ void ldm4(uint32_t& r0, uint32_t& r1, uint32_t& r2, uint32_t& r3,
                                     uint32_t addr) {
    asm volatile("ldmatrix.sync.aligned.m8n8.x4.shared.b16 {%0,%1,%2,%3}, [%4];"
        : "=r"(r0), "=r"(r1), "=r"(r2), "=r"(r3) : "r"(addr));
}

// ---------------- prep: input f32->f16 + zero ----------------
#define N4_CONT  524288
#define N4_PE    1048576
#define N4_QRY   65536
#define N4_ZERO  524288
#define PREP_BLOCKS ((N4_CONT + N4_PE + N4_QRY + N4_ZERO) / 256)

__global__ void prep_all(
    const float* __restrict__ content, const float* __restrict__ pe,
    const float* __restrict__ query,
    __half* __restrict__ conth, __half* __restrict__ peh,
    __half* __restrict__ qryh, float* __restrict__ qscat)
{
    long i = (long)blockIdx.x * 256 + threadIdx.x;
    auto cv = [](const float* s, __half* d, long j) {
        float4 v = ((const float4*)s)[j];
        uint2 o;
        o.x = pkh(v.x, v.y);
        o.y = pkh(v.z, v.w);
        ((uint2*)d)[j] = o;
    };
    if (i < N4_CONT) { cv(content, conth, i); return; }
    i -= N4_CONT;
    if (i < N4_PE)   { cv(pe, peh, i); return; }
    i -= N4_PE;
    if (i < N4_QRY)  { cv(query, qryh, i); return; }
    i -= N4_QRY;
    ((float4*)qscat)[i] = make_float4(0.f, 0.f, 0.f, 0.f);
}

// ---------------- weight transpose + convert ----------------
__global__ void transw(
    const float* __restrict__ wq, const float* __restrict__ wkc,
    const float* __restrict__ wv, const float* __restrict__ wkp,
    const float* __restrict__ wo,
    __half* __restrict__ wpackT, __half* __restrict__ wkpT, __half* __restrict__ woT)
{
    const float* src; __half* dst;
    switch (blockIdx.z) {
        case 0: src = wq;  dst = wpackT; break;
        case 1: src = wkc; dst = wpackT + 1024 * 1024; break;
        case 2: src = wv;  dst = wpackT + 2 * 1024 * 1024; break;
        case 3: src = wkp; dst = wkpT; break;
        default: src = wo; dst = woT; break;
    }
    __shared__ float t[32][33];
    const int tx = threadIdx.x, ty = threadIdx.y;
    const int x = blockIdx.x * 32 + tx;
#pragma unroll
    for (int i = 0; i < 4; i++) {
        int y = blockIdx.y * 32 + ty + i * 8;
        t[ty + i * 8][tx] = src[(size_t)y * 1024 + x];
    }
    __syncthreads();
    const int x2 = blockIdx.y * 32 + tx;
#pragma unroll
    for (int i = 0; i < 4; i++) {
        int y2 = blockIdx.x * 32 + ty + i * 8;
        dst[(size_t)y2 * 1024 + x2] = __float2half_rn(t[tx][ty + i * 8]);
    }
}

// ---------------- multi-problem fp16 TB GEMM 128x128 ----------------
#define ASH 40

struct GD {
    const __half* A; const __half* B;
    float* Cf; __half* Ch; __half* Cv;
    int gx, gy;
    int lda, ldb, ldc;
    long aOut, aIn, bOut, bIn, cOut, cIn;
    int zInner, KT, epi;
};

__global__ __launch_bounds__(256) void gemm128h(GD d0, GD d1, GD d2, int n0, int n01)
{
    __shared__ __half As[2][128 * ASH];
    __shared__ __half Bs[2][128 * ASH];

    GD d;
    int r = blockIdx.x;
    if (r < n0)       { d = d0; }
    else if (r < n01) { d = d1; r -= n0; }
    else              { d = d2; r -= n01; }

    const int tiles = d.gx * d.gy;
    const int z  = r / tiles;
    const int rr = r % tiles;
    const int by = rr / d.gx, bx = rr % d.gx;
    const int zo = z / d.zInner, zi = z % d.zInner;

    const __half* Ap = d.A + zo * d.aOut + zi * d.aIn;
    const __half* Bp = d.B + zo * d.bOut + zi * d.bIn;
    const int m0 = by * 128, n0px = bx * 128;
    const int lda = d.lda, ldb = d.ldb;

    const int tid = threadIdx.x;
    const int wid = tid >> 5, lane = tid & 31;
    const int wm = (wid & 3) * 32, wn = (wid >> 2) * 64;
    const int lr = lane >> 2, lc = lane & 3;
    const int laneA = lane & 15;
    const int kA = (lane & 16) ? 8 : 0;
    const int laneB = (lane & 7) + ((lane & 16) ? 8 : 0);
    const int kB = (lane & 8) ? 8 : 0;

    uint32_t aSm[2], bSm[2];
    aSm[0] = (uint32_t)__cvta_generic_to_shared(&As[0][0]);
    aSm[1] = (uint32_t)__cvta_generic_to_shared(&As[1][0]);
    bSm[0] = (uint32_t)__cvta_generic_to_shared(&Bs[0][0]);
    bSm[1] = (uint32_t)__cvta_generic_to_shared(&Bs[1][0]);

    auto stage = [&](int kt) {
        const int k0 = kt * 32, buf = kt & 1;
#pragma unroll
        for (int i = 0; i < 2; i++) {
            int id = tid + i * 256;
            int row = id >> 2, off = (id & 3) * 8;
            cp16(aSm[buf] + (uint32_t)(row * ASH + off) * 2,
                 Ap + (size_t)(m0 + row) * lda + k0 + off);
            cp16(bSm[buf] + (uint32_t)(row * ASH + off) * 2,
                 Bp + (size_t)(n0px + row) * ldb + k0 + off);
        }
    };

    float acc[2][8][4] = {};
    const int KT = d.KT;

    stage(0);
    asm volatile("cp.async.commit_group;");

    for (int kt = 0; kt < KT; kt++) {
        if (kt + 1 < KT) {
            stage(kt + 1);
            asm volatile("cp.async.commit_group;");
            asm volatile("cp.async.wait_group 1;");
        } else {
            asm volatile("cp.async.wait_group 0;");
        }
        __syncthreads();

        const int buf = kt & 1;
#pragma unroll
        for (int kk = 0; kk < 32; kk += 16) {
            uint32_t af[2][4], bf[8][2];
#pragma unroll
            for (int im = 0; im < 2; im++)
                ldm4(af[im][0], af[im][1], af[im][2], af[im][3],
                     aSm[buf] + (uint32_t)(((wm + im * 16 + laneA) * ASH + kk + kA) * 2));
#pragma unroll
            for (int jp = 0; jp < 4; jp++)
                ldm4(bf[2 * jp][0], bf[2 * jp][1], bf[2 * jp + 1][0], bf[2 * jp + 1][1],
                     bSm[buf] + (uint32_t)(((wn + jp * 16 + laneB) * ASH + kk + kB) * 2));
#pragma unroll
            for (int im = 0; im < 2; im++)
#pragma unroll
                for (int jn = 0; jn < 8; jn++)
                    mma_f16(acc[im][jn], af[im], bf[jn]);
        }
        __syncthreads();
    }

#pragma unroll
    for (int im = 0; im < 2; im++) {
#pragma unroll
        for (int jn = 0; jn < 8; jn++) {
            const int row = m0 + wm + im * 16 + lr;
            const int col = n0px + wn + jn * 8 + 2 * lc;
            const float c0 = acc[im][jn][0], c1 = acc[im][jn][1];
            const float c2 = acc[im][jn][2], c3 = acc[im][jn][3];
            if (d.epi == 0) {
                float* Cp = d.Cf + zo * d.cOut + zi * d.cIn;
                *(float2*)(Cp + (size_t)row * d.ldc + col) = make_float2(c0, c1);
                *(float2*)(Cp + (size_t)(row + 8) * d.ldc + col) = make_float2(c2, c3);
            } else if (d.epi == 1) {
                __half* Cp = d.Ch + zo * d.cOut + zi * d.cIn;
                *(uint32_t*)(Cp + (size_t)row * d.ldc + col) = pkh(c0, c1);
                *(uint32_t*)(Cp + (size_t)(row + 8) * d.ldc + col) = pkh(c2, c3);
            } else {
                if (col < 1024) {
                    *(float2*)(d.Cf + (size_t)row * 1024 + col) = make_float2(c0, c1);
                    *(float2*)(d.Cf + (size_t)(row + 8) * 1024 + col) = make_float2(c2, c3);
                } else if (col < 2048) {
                    *(uint32_t*)(d.Ch + (size_t)row * 1024 + col - 1024) = pkh(c0, c1);
                    *(uint32_t*)(d.Ch + (size_t)(row + 8) * 1024 + col - 1024) = pkh(c2, c3);
                } else {
                    const int b = row >> 10, s = row & 1023, dd = col - 2048;
                    __half* v = d.Cv + (size_t)b * (1024 * 1024);
                    v[(size_t)dd * 1024 + s]           = __float2half_rn(c0);
                    v[(size_t)(dd + 1) * 1024 + s]     = __float2half_rn(c1);
                    v[(size_t)dd * 1024 + s + 8]       = __float2half_rn(c2);
                    v[(size_t)(dd + 1) * 1024 + s + 8] = __float2half_rn(c3);
                }
            }
        }
    }
}

// ---------------- fp16 TB GEMM M128 x N64 (AV) ----------------
__global__ __launch_bounds__(256) void gemm64h(
    const __half* __restrict__ A, const __half* __restrict__ B, __half* __restrict__ C,
    long aIn, long bOut, long bIn, long cOut, long cIn, int zInner,
    int lda, int ldb, int ldc, int KT)
{
    __shared__ __half As[2][128 * ASH];
    __shared__ __half Bs[2][64 * ASH];

    const int z = blockIdx.x;
    const int zo = z / zInner, zi = z % zInner;
    const __half* Ap = A + (size_t)z * aIn;
    const __half* Bp = B + zo * bOut + zi * bIn;
    __half* Cp = C + zo * cOut + zi * cIn;

    const int tid = threadIdx.x;
    const int wid = tid >> 5, lane = tid & 31;
    const int wm = (wid & 3) * 32, wn = (wid >> 2) * 32;
    const int lr = lane >> 2, lc = lane & 3;
    const int laneA = lane & 15;
    const int kA = (lane & 16) ? 8 : 0;
    const int laneB = (lane & 7) + ((lane & 16) ? 8 : 0);
    const int kB = (lane & 8) ? 8 : 0;

    uint32_t aSm[2], bSm[2];
    aSm[0] = (uint32_t)__cvta_generic_to_shared(&As[0][0]);
    aSm[1] = (uint32_t)__cvta_generic_to_shared(&As[1][0]);
    bSm[0] = (uint32_t)__cvta_generic_to_shared(&Bs[0][0]);
    bSm[1] = (uint32_t)__cvta_generic_to_shared(&Bs[1][0]);

    auto stage = [&](int kt) {
        const int k0 = kt * 32, buf = kt & 1;
#pragma unroll
        for (int i = 0; i < 2; i++) {
            int id = tid + i * 256;
            int row = id >> 2, off = (id & 3) * 8;
            cp16(aSm[buf] + (uint32_t)(row * ASH + off) * 2,
                 Ap + (size_t)row * lda + k0 + off);
        }
        int row = tid >> 2, off = (tid & 3) * 8;
        if (row < 64)
            cp16(bSm[buf] + (uint32_t)(row * ASH + off) * 2,
                 Bp + (size_t)row * ldb + k0 + off);
    };

    float acc[2][4][4] = {};

    stage(0);
    asm volatile("cp.async.commit_group;");

    for (int kt = 0; kt < KT; kt++) {
        if (kt + 1 < KT) {
            stage(kt + 1);
            asm volatile("cp.async.commit_group;");
            asm volatile("cp.async.wait_group 1;");
        } else {
            asm volatile("cp.async.wait_group 0;");
        }
        __syncthreads();

        const int buf = kt & 1;
#pragma unroll
        for (int kk = 0; kk < 32; kk += 16) {
            uint32_t af[2][4], bf[4][2];
#pragma unroll
            for (int im = 0; im < 2; im++)
                ldm4(af[im][0], af[im][1], af[im][2], af[im][3],
                     aSm[buf] + (uint32_t)(((wm + im * 16 + laneA) * ASH + kk + kA) * 2));
#pragma unroll
            for (int jp = 0; jp < 2; jp++)
                ldm4(bf[2 * jp][0], bf[2 * jp][1], bf[2 * jp + 1][0], bf[2 * jp + 1][1],
                     bSm[buf] + (uint32_t)(((wn + jp * 16 + laneB) * ASH + kk + kB) * 2));
#pragma unroll
            for (int im = 0; im < 2; im++)
#pragma unroll
                for (int jn = 0; jn < 4; jn++)
                    mma_f16(acc[im][jn], af[im], bf[jn]);
        }
        __syncthreads();
    }

#pragma unroll
    for (int im = 0; im < 2; im++) {
#pragma unroll
        for (int jn = 0; jn < 4; jn++) {
            const int row = wm + im * 16 + lr;
            const int col = wn + jn * 8 + 2 * lc;
            *(uint32_t*)(Cp + (size_t)row * ldc + col) = pkh(acc[im][jn][0], acc[im][jn][1]);
            *(uint32_t*)(Cp + (size_t)(row + 8) * ldc + col) = pkh(acc[im][jn][2], acc[im][jn][3]);
        }
    }
}

// ---------------- flash-fused content attention (fp16 mma + ldmatrix) ----------------
#define KST 72
#define RSTF 68
#define FL_SMEMF (3 * (64 * KST / 2) + 2 * 64 * RSTF + 128)

__device__ __forceinline__ void stage64h(__half* dst, const __half* src, long rstride, int tid) {
    uint32_t s = (uint32_t)__cvta_generic_to_shared(dst);
#pragma unroll
    for (int i = 0; i < 4; i++) {
        int id = tid + i * 128;
        int r = id >> 3, o = (id & 7) * 8;
        cp16(s + (uint32_t)(r * KST + o) * 2, src + (size_t)r * rstride + o);
    }
}

__global__ __launch_bounds__(128, 2) void flash_content(
    const float* __restrict__ q, const __half* __restrict__ kc,
    const __half* __restrict__ vT, const __half* __restrict__ kp,
    const float* __restrict__ cb, const float* __restrict__ pb,
    const float* __restrict__ sb, const float* __restrict__ seg,
    const void* __restrict__ segmat, const float* __restrict__ mask,
    __half* __restrict__ out)
{
    extern __shared__ float sm[];
    __half* KCs = (__half*)sm;
    __half* KPs = (__half*)(sm + 2304);
    __half* VsT = (__half*)(sm + 4608);
    float*  ring = sm + 6912;
    float*  s0s  = sm + 6912 + 2 * 64 * RSTF;
    float*  s1s  = s0s + 64;
    __half* Ps   = KPs;

    const uint32_t smB = (uint32_t)__cvta_generic_to_shared(sm);
    const uint32_t KCsA = smB, KPsA = smB + 9216, VsA = smB + 18432, PsA = KPsA;

    const int b = blockIdx.z, h = blockIdx.y, qt = blockIdx.x, q0 = qt * 64;
    const int tid = threadIdx.x, w = tid >> 5, l = tid & 31;
    const int lr = l >> 2, lc = l & 3;
    const int qb = w * 16;
    const int mode = g_segmode[0];
    const int hD = h * DH;
    const int laneA = l & 15;
    const int kA = (l & 16) ? 8 : 0;
    const int laneB = (l & 7) + ((l & 16) ? 8 : 0);
    const int kB = (l & 8) ? 8 : 0;

    uint32_t aC[4][4], aP[4][4];
    {
        const float* r0 = q + ((size_t)(b * SEQ + q0 + qb + lr)) * HIDD + hD;
        const float* r1 = r0 + (size_t)8 * HIDD;
#pragma unroll
        for (int s = 0; s < 4; s++) {
            const int d0 = 16 * s + 2 * lc;
            float2 q00 = *(const float2*)(r0 + d0);
            float2 q08 = *(const float2*)(r0 + d0 + 8);
            float2 q10 = *(const float2*)(r1 + d0);
            float2 q18 = *(const float2*)(r1 + d0 + 8);
            const float cb0 = cb[hD + d0], cb1 = cb[hD + d0 + 1];
            const float cb8 = cb[hD + d0 + 8], cb9 = cb[hD + d0 + 9];
            const float pb0 = pb[hD + d0], pb1 = pb[hD + d0 + 1];
            const float pb8 = pb[hD + d0 + 8], pb9 = pb[hD + d0 + 9];
            aC[s][0] = pkh(q00.x + cb0, q00.y + cb1);
            aC[s][1] = pkh(q10.x + cb0, q10.y + cb1);
            aC[s][2] = pkh(q08.x + cb8, q08.y + cb9);
            aC[s][3] = pkh(q18.x + cb8, q18.y + cb9);
            aP[s][0] = pkh(q00.x + pb0, q00.y + pb1);
            aP[s][1] = pkh(q10.x + pb0, q10.y + pb1);
            aP[s][2] = pkh(q08.x + pb8, q08.y + pb9);
            aP[s][3] = pkh(q18.x + pb8, q18.y + pb9);
        }
    }
    if (tid < 64) {
        const float* qr = q + ((size_t)(b * SEQ + q0 + tid)) * HIDD + hD;
        float s0 = 0.f, s1 = 0.f;
        for (int d = 0; d < DH; d++) {
            float qs = qr[d] + sb[hD + d];
            s0 += qs * seg[hD + d];
            s1 += qs * seg[NH * DH + hD + d];
        }
        s0s[tid] = s0; s1s[tid] = s1;
    }

    float O[8][4] = {};
    float m_a = -1e30f, m_b = -1e30f, l_a = 0.f, l_b = 0.f;

    auto pp_tile = [&](int slot) {
        float* rg = ring + slot * 64 * RSTF;
#pragma unroll
        for (int jp = 0; jp < 4; jp++) {
            float c0[4] = {0.f, 0.f, 0.f, 0.f}, c1[4] = {0.f, 0.f, 0.f, 0.f};
#pragma unroll
            for (int s = 0; s < 4; s++) {
                uint32_t t0, t1, t2, t3;
                ldm4(t0, t1, t2, t3,
                     KPsA + (uint32_t)(((jp * 16 + laneB) * KST + 16 * s + kB) * 2));
                uint32_t b0[2] = {t0, t1}, b1[2] = {t2, t3};
                mma_f16(c0, aP[s], b0);
                mma_f16(c1, aP[s], b1);
            }
            float* r0 = rg + (qb + lr) * RSTF + jp * 16 + 2 * lc;
            *(float2*)r0 = make_float2(c0[0], c0[1]);
            *(float2*)(r0 + 8 * RSTF) = make_float2(c0[2], c0[3]);
            *(float2*)(r0 + 8) = make_float2(c1[0], c1[1]);
            *(float2*)(r0 + 8 * RSTF + 8) = make_float2(c1[2], c1[3]);
        }
        __syncwarp();
    };

    {
        stage64h(KPs, kp + ((size_t)(b * SEQ2 + SEQ - q0 - 64)) * HIDD + hD, HIDD, tid);
        asm volatile("cp.async.commit_group;");
        asm volatile("cp.async.wait_group 0;");
        __syncthreads();
        pp_tile((15 - qt) & 1);
    }

    const int ra = qb + lr, rb = ra + 8;
    const size_t mbase_a = ((size_t)b * SEQ + q0 + ra) * SEQ;
    const size_t mbase_b = mbase_a + (size_t)8 * SEQ;
    const float s0a = s0s[ra], s1a = s1s[ra];
    const float s0b = s0s[rb], s1b = s1s[rb];

    for (int kt = 0; kt < 16; kt++) {
        const int k0 = kt * 64;
        const int Tb = 16 + kt - qt;
        __syncthreads();
        stage64h(KCs, kc + (size_t)(b * SEQ + k0) * HIDD + hD, HIDD, tid);
        stage64h(VsT, vT + ((size_t)b << 20) + (size_t)hD * SEQ + k0, SEQ, tid);
        stage64h(KPs, kp + ((size_t)b * SEQ2 + (size_t)64 * Tb) * HIDD + hD, HIDD, tid);
        asm volatile("cp.async.commit_group;");
        asm volatile("cp.async.wait_group 0;");
        __syncthreads();

        pp_tile(Tb & 1);
        const int slotA = (Tb - 1) & 1, slotB = Tb & 1;

        float cs[8][4];
#pragma unroll
        for (int jp = 0; jp < 4; jp++) {
            float c0[4] = {0.f, 0.f, 0.f, 0.f}, c1[4] = {0.f, 0.f, 0.f, 0.f};
#pragma unroll
            for (int s = 0; s < 4; s++) {
                uint32_t t0, t1, t2, t3;
                ldm4(t0, t1, t2, t3,
                     KCsA + (uint32_t)(((jp * 16 + laneB) * KST + 16 * s + kB) * 2));
                uint32_t b0[2] = {t0, t1}, b1[2] = {t2, t3};
                mma_f16(c0, aC[s], b0);
                mma_f16(c1, aC[s], b1);
            }
#pragma unroll
            for (int e = 0; e < 4; e++) {
                cs[2 * jp][e] = c0[e];
                cs[2 * jp + 1][e] = c1[e];
            }
        }

        float mxa = -1e30f, mxb = -1e30f;
#pragma unroll
        for (int jn = 0; jn < 8; jn++) {
            const int kkp = jn * 8 + 2 * lc;
            float2 mva = *(const float2*)(mask + mbase_a + k0 + kkp);
            float2 mvb = *(const float2*)(mask + mbase_b + k0 + kkp);
            float sa0 = seg_at(segmat, mbase_a + k0 + kkp, mode)     ? s1a : s0a;
            float sa1 = seg_at(segmat, mbase_a + k0 + kkp + 1, mode) ? s1a : s0a;
            float sb0 = seg_at(segmat, mbase_b + k0 + kkp, mode)     ? s1b : s0b;
            float sb1 = seg_at(segmat, mbase_b + k0 + kkp + 1, mode) ? s1b : s0b;
            const int wa = kkp - ra + 64, wb = kkp - rb + 64;
            float ppa0 = ring[(wa < 64 ? slotA : slotB) * 64 * RSTF + ra * RSTF + (wa & 63)];
            float ppa1 = ring[(wa + 1 < 64 ? slotA : slotB) * 64 * RSTF + ra * RSTF + ((wa + 1) & 63)];
            float ppb0 = ring[(wb < 64 ? slotA : slotB) * 64 * RSTF + rb * RSTF + (wb & 63)];
            float ppb1 = ring[(wb + 1 < 64 ? slotA : slotB) * 64 * RSTF + rb * RSTF + ((wb + 1) & 63)];
            cs[jn][0] = (cs[jn][0] + ppa0 + sa0) * 0.125f + mva.x * (-1e9f);
            cs[jn][1] = (cs[jn][1] + ppa1 + sa1) * 0.125f + mva.y * (-1e9f);
            cs[jn][2] = (cs[jn][2] + ppb0 + sb0) * 0.125f + mvb.x * (-1e9f);
            cs[jn][3] = (cs[jn][3] + ppb1 + sb1) * 0.125f + mvb.y * (-1e9f);
            mxa = fmaxf(mxa, fmaxf(cs[jn][0], cs[jn][1]));
            mxb = fmaxf(mxb, fmaxf(cs[jn][2], cs[jn][3]));
        }
        __syncthreads();

        mxa = fmaxf(mxa, __shfl_xor_sync(0xffffffffu, mxa, 1));
        mxa = fmaxf(mxa, __shfl_xor_sync(0xffffffffu, mxa, 2));
        mxb = fmaxf(mxb, __shfl_xor_sync(0xffffffffu, mxb, 1));
        mxb = fmaxf(mxb, __shfl_xor_sync(0xffffffffu, mxb, 2));

        const float mna = fmaxf(m_a, mxa), mnb = fmaxf(m_b, mxb);
        const float alA = __expf(m_a - mna), alB = __expf(m_b - mnb);
        m_a = mna; m_b = mnb;

        float sa = 0.f, sbm = 0.f;
#pragma unroll
        for (int jn = 0; jn < 8; jn++) {
            float p0 = __expf(cs[jn][0] - m_a), p1 = __expf(cs[jn][1] - m_a);
            float p2 = __expf(cs[jn][2] - m_b), p3 = __expf(cs[jn][3] - m_b);
            sa += p0 + p1; sbm += p2 + p3;
            *(uint32_t*)(Ps + ra * KST + jn * 8 + 2 * lc) = pkh(p0, p1);
            *(uint32_t*)(Ps + rb * KST + jn * 8 + 2 * lc) = pkh(p2, p3);
            O[jn][0] *= alA; O[jn][1] *= alA; O[jn][2] *= alB; O[jn][3] *= alB;
        }
        sa  += __shfl_xor_sync(0xffffffffu, sa, 1);
        sa  += __shfl_xor_sync(0xffffffffu, sa, 2);
        sbm += __shfl_xor_sync(0xffffffffu, sbm, 1);
        sbm += __shfl_xor_sync(0xffffffffu, sbm, 2);
        l_a = l_a * alA + sa;
        l_b = l_b * alB + sbm;
        __syncwarp();

        uint32_t ap[4][4];
#pragma unroll
        for (int s = 0; s < 4; s++)
            ldm4(ap[s][0], ap[s][1], ap[s][2], ap[s][3],
                 PsA + (uint32_t)(((qb + laneA) * KST + 16 * s + kA) * 2));
#pragma unroll
        for (int jp = 0; jp < 4; jp++) {
#pragma unroll
            for (int s = 0; s < 4; s++) {
                uint32_t t0, t1, t2, t3;
                ldm4(t0, t1, t2, t3,
                     VsA + (uint32_t)(((jp * 16 + laneB) * KST + 16 * s + kB) * 2));
                uint32_t b0[2] = {t0, t1}, b1[2] = {t2, t3};
                mma_f16(O[2 * jp], ap[s], b0);
                mma_f16(O[2 * jp + 1], ap[s], b1);
            }
        }
        __syncwarp();
    }

    const float ia = 1.f / l_a, ib = 1.f / l_b;
    __half* o0 = out + ((size_t)(b * SEQ + q0 + ra)) * HIDD + hD;
    __half* o1 = o0 + (size_t)8 * HIDD;
#pragma unroll
    for (int jn = 0; jn < 8; jn++) {
        *(uint32_t*)(o0 + jn * 8 + 2 * lc) = pkh(O[jn][0] * ia, O[jn][1] * ia);
        *(uint32_t*)(o1 + jn * 8 + 2 * lc) = pkh(O[jn][2] * ib, O[jn][3] * ib);
    }
}

// ---------------- small kernels ----------------
__global__ void scatter_q(const float* __restrict__ tmap, const float* __restrict__ qg,
                          float* __restrict__ qscat, int* __restrict__ idx)
{
    const int b = blockIdx.y, p = blockIdx.x, t = threadIdx.x;
    __shared__ int sidx;
    const float* row = tmap + ((size_t)b * PQ + p) * SEQ;
    for (int s = t; s < SEQ; s += 128)
        if (row[s] > 0.5f) sidx = s;
    __syncthreads();
    const int si = sidx;
    if (t == 0) idx[b * PQ + p] = si;
    const float* src = qg + ((size_t)b * PQ + p) * HIDD;
    float* dst = qscat + ((size_t)b * SEQ + si) * HIDD;
    for (int i = t; i < HIDD; i += 128) atomicAdd(&dst[i], src[i]);
}

__global__ void gather_bias(const float* __restrict__ qscat, const int* __restrict__ idx,
                            const float* __restrict__ cb, const float* __restrict__ pb,
                            float* __restrict__ qq, __half* __restrict__ ocb,
                            __half* __restrict__ opb)
{
    const int b = blockIdx.y, p = blockIdx.x, t = threadIdx.x;
    const int si = idx[b * PQ + p];
    const float* src = qscat + ((size_t)b * SEQ + si) * HIDD;
    const size_t o = (size_t)(b * PQ + p) * HIDD;
    for (int i = t; i < HIDD; i += 128) {
        float v = src[i];
        qq[o + i]  = v;
        ocb[o + i] = __float2half_rn(v + cb[i]);
        opb[o + i] = __float2half_rn(v + pb[i]);
    }
}

// ---------------- query-stream softmax ----------------
__global__ __launch_bounds__(256) void softmax_kernel(
    const float* __restrict__ cs, const float* __restrict__ pp,
    __half* __restrict__ csh,
    const float* __restrict__ qArr, const float* __restrict__ sb,
    const float* __restrict__ seg, const void* __restrict__ segmat,
    const float* __restrict__ mask, const int* __restrict__ qidx)
{
    const int b = blockIdx.z, h = blockIdx.y, qo = blockIdx.x, t = threadIdx.x;
    const int qrow = qidx[b * PQ + qo];
    const int z = b * NH + h;
    const int mode = g_segmode[0];

    const float* csrow = cs + ((size_t)z * PQ + qo) * SEQ;
    __half* cw = csh + ((size_t)z * PQ + qo) * SEQ;
    const float* pprow = pp + ((size_t)z * PQ + qo) * SEQ2 + (SEQ - qrow);
    const float* mrow = mask + ((size_t)b * SEQ + qrow) * SEQ;
    const size_t segbase = ((size_t)b * SEQ + qrow) * SEQ;

    __shared__ float qsv[DH];
    __shared__ float s01[2];
    __shared__ float red[256];

    if (t < DH)
        qsv[t] = qArr[(size_t)(b * PQ + qo) * HIDD + h * DH + t] + sb[h * DH + t];
    __syncthreads();
    if (t < 64) {
        const int which = t >> 5, lx = t & 31;
        const float* sgp = seg + which * NH * DH + h * DH;
        float a = qsv[lx] * sgp[lx] + qsv[lx + 32] * sgp[lx + 32];
#pragma unroll
        for (int o = 16; o; o >>= 1) a += __shfl_xor_sync(0xffffffffu, a, o);
        if (lx == 0) s01[which] = a;
    }
    __syncthreads();
    const float s0 = s01[0], s1 = s01[1];

    float lg[4];
    float mx = -3.4e38f;
#pragma unroll
    for (int j = 0; j < 4; j++) {
        int k = t + j * 256;
        float sgv = seg_at(segmat, segbase + k, mode) ? s1 : s0;
        float v = (csrow[k] + pprow[k] + sgv) * 0.125f + mrow[k] * (-1e9f);
        lg[j] = v;
        mx = fmaxf(mx, v);
    }
    red[t] = mx; __syncthreads();
#pragma unroll
    for (int s2 = 128; s2; s2 >>= 1) {
        if (t < s2) red[t] = fmaxf(red[t], red[t + s2]);
        __syncthreads();
    }
    mx = red[0]; __syncthreads();

    float sum = 0.f;
#pragma unroll
    for (int j = 0; j < 4; j++) {
        float e = __expf(lg[j] - mx);
        lg[j] = e;
        sum += e;
    }
    red[t] = sum; __syncthreads();
#pragma unroll
    for (int s2 = 128; s2; s2 >>= 1) {
        if (t < s2) red[t] += red[t + s2];
        __syncthreads();
    }
    const float invZ = 1.f / red[0];
#pragma unroll
    for (int j = 0; j < 4; j++) cw[t + j * 256] = __float2half_rn(lg[j] * invZ);
}

// ---------------- launch ----------------
extern "C" void kernel_launch(void* const* d_in, const int* in_sizes, int n_in,
                              void* d_out, int out_size)
{
    const float* content = (const float*)d_in[0];
    const float* query   = (const float*)d_in[1];
    const float* pe      = (const float*)d_in[2];
    const void*  segmat  = d_in[3];
    const float* segenc  = (const float*)d_in[4];
    const float* segbias = (const float*)d_in[5];
    const float* cmask   = (const float*)d_in[6];
    const float* qmask   = (const float*)d_in[7];
    const float* tmap    = (const float*)d_in[8];
    const float* cbias   = (const float*)d_in[9];
    const float* pbias   = (const float*)d_in[10];
    const float* wq      = (const float*)d_in[11];
    const float* wkc     = (const float*)d_in[12];
    const float* wv      = (const float*)d_in[13];
    const float* wkp     = (const float*)d_in[14];
    const float* wo      = (const float*)d_in[15];
    float* out = (float*)d_out;

    float *q, *qg, *qscat, *qq, *csq, *ppq;
    __half *kc, *vT, *wpackT, *wkpT, *woT, *kph, *conth, *peh, *qryh;
    __half *qqcb, *qqpb, *csqh, *catt, *qatt;
    int* idx;
    cudaGetSymbolAddress((void**)&q,      g_q);
    cudaGetSymbolAddress((void**)&kc,     g_kc);
    cudaGetSymbolAddress((void**)&vT,     g_vT);
    cudaGetSymbolAddress((void**)&wpackT, g_wpackT);
    cudaGetSymbolAddress((void**)&wkpT,   g_wkpT);
    cudaGetSymbolAddress((void**)&woT,    g_woT);
    cudaGetSymbolAddress((void**)&kph,    g_kph);
    cudaGetSymbolAddress((void**)&conth,  g_conth);
    cudaGetSymbolAddress((void**)&peh,    g_peh);
    cudaGetSymbolAddress((void**)&qryh,   g_qryh);
    cudaGetSymbolAddress((void**)&qg,     g_qg);
    cudaGetSymbolAddress((void**)&qscat,  g_qscat);
    cudaGetSymbolAddress((void**)&qq,     g_qq);
    cudaGetSymbolAddress((void**)&qqcb,   g_qqcb);
    cudaGetSymbolAddress((void**)&qqpb,   g_qqpb);
    cudaGetSymbolAddress((void**)&csq,    g_csq);
    cudaGetSymbolAddress((void**)&ppq,    g_ppq);
    cudaGetSymbolAddress((void**)&csqh,   g_csqh);
    cudaGetSymbolAddress((void**)&catt,   g_catt);
    cudaGetSymbolAddress((void**)&qatt,   g_qatt);
    cudaGetSymbolAddress((void**)&idx,    g_idx);

    static bool init_done = false;
    if (!init_done) {
        cudaFuncSetAttribute(flash_content, cudaFuncAttributeMaxDynamicSharedMemorySize,
                             FL_SMEMF * sizeof(float));
        init_done = true;
    }

    const long PH = (long)PQ * HIDD;
    const long PS = (long)PQ * SEQ, PS2 = (long)PQ * SEQ2;

    probe_segmat<<<1, 32>>>((const uint32_t*)segmat);
    prep_all<<<PREP_BLOCKS, 256>>>(content, pe, query, conth, peh, qryh, qscat);
    transw<<<dim3(32, 32, 5), dim3(32, 8)>>>(wq, wkc, wv, wkp, wo, wpackT, wkpT, woT);

    // fused projections: QKV (384) + kp (256) + query-proj (16)
    {
        GD dQKV = {conth, wpackT, q, kc, vT, 24, 16, HIDD, HIDD, 0,
                   0, 0, 0, 0, 0, 0, 1, 32, 2};
        GD dKP  = {peh, wkpT, nullptr, kph, nullptr, 8, 32, HIDD, HIDD, HIDD,
                   0, 0, 0, 0, 0, 0, 1, 32, 1};
        GD dQG  = {qryh, wpackT, qg, nullptr, nullptr, 8, 2, HIDD, HIDD, HIDD,
                   0, 0, 0, 0, 0, 0, 1, 32, 0};
        gemm128h<<<656, 256>>>(dQKV, dKP, dQG, 384, 640);
    }

    scatter_q<<<dim3(PQ, BATCH), 128>>>(tmap, qg, qscat, idx);
    gather_bias<<<dim3(PQ, BATCH), 128>>>(qscat, idx, cbias, pbias, qq, qqcb, qqpb);

    // fused query-stream scores: csq (256) + ppq (512)
    {
        GD dCS = {qqcb, kc, csq, nullptr, nullptr, 8, 1, HIDD, HIDD, SEQ,
                  PH, 64, (long)SEQ * HIDD, 64, (long)NH * PS, PS, NH, 2, 0};
        GD dPP = {qqpb, kph, ppq, nullptr, nullptr, 16, 1, HIDD, HIDD, SEQ2,
                  PH, 64, (long)SEQ2 * HIDD, 64, (long)NH * PS2, PS2, NH, 2, 0};
        GD dZ = {};
        gemm128h<<<768, 256>>>(dCS, dPP, dZ, 256, 768);
    }
    softmax_kernel<<<dim3(PQ, NH, BATCH), 256>>>(
        csq, ppq, csqh, qq, segbias, segenc, segmat, qmask, idx);
    gemm64h<<<BATCH * NH, 256>>>(csqh, vT, qatt,
        PS, (long)1024 * 1024, (long)64 * SEQ, PH, 64, NH,
        SEQ, SEQ, HIDD, 32);

    // content stream
    flash_content<<<dim3(SEQ / 64, NH, BATCH), 128, FL_SMEMF * sizeof(float)>>>(
        q, kc, vT, kph, cbias, pbias, segbias, segenc, segmat, cmask, catt);

    // fused output projections: catt (128) + qatt (16)
    {
        GD dCO = {catt, woT, out, nullptr, nullptr, 8, 16, HIDD, HIDD, HIDD,
                  0, 0, 0, 0, 0, 0, 1, 32, 0};
        GD dQO = {qatt, woT, out + (size_t)BATCH * SEQ * HIDD, nullptr, nullptr,
                  8, 2, HIDD, HIDD, HIDD, 0, 0, 0, 0, 0, 0, 1, 32, 0};
        GD dZ = {};
        gemm128h<<<144, 256>>>(dCO, dQO, dZ, 128, 144);
    }
}